// round 1
// baseline (speedup 1.0000x reference)
#include <cuda_runtime.h>
#include <math.h>

#define NN   50000
#define HID  128
#define HEADS 4
#define RR   8
#define EE   640000
#define EE2  200000
#define NCLS 8

// ---------------- scratch (device globals; allocation-free) ----------------
__device__ float g_xw[NN * RR * HID];        // 204.8 MB: per-(node,rel) transformed feats
__device__ float g_aq[NN * RR * HEADS];
__device__ float g_ak[NN * RR * HEADS];
__device__ float g_wq[RR * HID * HEADS];
__device__ float g_wk[RR * HID * HEADS];
__device__ float g_alpha[EE * HEADS];        // logits, then exp()
__device__ float g_amax[NN * HEADS];
__device__ float g_den[NN * HEADS];
__device__ float g_agg[NN * HID];            // pre-LN aggregation
__device__ float g_h1[NN * HID];
__device__ float g_hsum[NN * HID];
__device__ float g_z[EE2 * HID];             // decode hidden

// ---------------- helpers ----------------
__device__ __forceinline__ void atomicMaxF(float* addr, float val) {
    int* ia = (int*)addr;
    int old = *ia;
    while (__int_as_float(old) < val) {
        int assumed = old;
        old = atomicCAS(ia, assumed, __float_as_int(val));
        if (old == assumed) break;
    }
}

// ---------------- Wq = W @ q, Wk = W @ k  (tiny) ----------------
__global__ void k_wqk(const float* __restrict__ W, const float* __restrict__ q,
                      const float* __restrict__ k) {
    int id = blockIdx.x * blockDim.x + threadIdx.x;
    if (id >= RR * HID * HEADS) return;
    int h = id % HEADS;
    int i = (id / HEADS) % HID;
    int r = id / (HEADS * HID);
    const float* wrow = W + (r * HID + i) * HID;
    float aq = 0.f, ak = 0.f;
#pragma unroll 4
    for (int o = 0; o < HID; o++) {
        float w = wrow[o];
        aq += w * q[o * HEADS + h];
        ak += w * k[o * HEADS + h];
    }
    g_wq[id] = aq;
    g_wk[id] = ak;
}

// ---------------- init per-layer accumulators ----------------
__global__ void k_init() {
    int i = blockIdx.x * blockDim.x + threadIdx.x;
    if (i < NN * HID) g_agg[i] = 0.f;
    if (i < NN * HEADS) {
        g_den[i] = 0.f;
        g_amax[i] = __int_as_float((int)0xff800000); // -inf
    }
}

// ---------------- xw GEMM: [NN,128] x [128,128] per relation ----------------
// 64x128 tile, K chunks of 32. 256 threads, 4x8 register tile.
__global__ void k_gemm_xw(const float* __restrict__ xin, const float* __restrict__ W,
                          int use_h1) {
    __shared__ float As[32][65];    // [kk][row], pad 65 -> conflict-free
    __shared__ float Bs[32][128];
    const int r = blockIdx.y;
    const int row0 = blockIdx.x * 64;
    const float* A = use_h1 ? g_h1 : xin;
    const float* B = W + r * HID * HID;
    const int t = threadIdx.x;
    const int tx = t & 15, ty = t >> 4;

    float acc[4][8];
#pragma unroll
    for (int i = 0; i < 4; i++)
#pragma unroll
        for (int j = 0; j < 8; j++) acc[i][j] = 0.f;

    for (int k0 = 0; k0 < 128; k0 += 32) {
        for (int l = t; l < 64 * 32; l += 256) {
            int row = l >> 5, kk = l & 31;
            int gr = row0 + row;
            As[kk][row] = (gr < NN) ? A[gr * 128 + k0 + kk] : 0.f;
        }
        for (int l = t; l < 32 * 128; l += 256) {
            int kk = l >> 7, c = l & 127;
            Bs[kk][c] = B[(k0 + kk) * 128 + c];
        }
        __syncthreads();
#pragma unroll
        for (int kk = 0; kk < 32; kk++) {
            float a[4], b[8];
#pragma unroll
            for (int i = 0; i < 4; i++) a[i] = As[kk][ty * 4 + i];
            float4 b0 = *(const float4*)&Bs[kk][tx * 8];
            float4 b1 = *(const float4*)&Bs[kk][tx * 8 + 4];
            b[0] = b0.x; b[1] = b0.y; b[2] = b0.z; b[3] = b0.w;
            b[4] = b1.x; b[5] = b1.y; b[6] = b1.z; b[7] = b1.w;
#pragma unroll
            for (int i = 0; i < 4; i++)
#pragma unroll
                for (int j = 0; j < 8; j++) acc[i][j] += a[i] * b[j];
        }
        __syncthreads();
    }
#pragma unroll
    for (int i = 0; i < 4; i++) {
        int gr = row0 + ty * 4 + i;
        if (gr >= NN) continue;
        float* dst = g_xw + (gr * RR + r) * HID + tx * 8;
        float4 s0 = make_float4(acc[i][0], acc[i][1], acc[i][2], acc[i][3]);
        float4 s1 = make_float4(acc[i][4], acc[i][5], acc[i][6], acc[i][7]);
        *(float4*)dst = s0;
        *(float4*)(dst + 4) = s1;
    }
}

// ---------------- aq/ak = x @ Wq / x @ Wk ----------------
__global__ void k_aqk(const float* __restrict__ xin, int use_h1) {
    __shared__ float sq[RR * HID * HEADS];  // 16 KB
    __shared__ float sk[RR * HID * HEADS];  // 16 KB
    for (int l = threadIdx.x; l < RR * HID * HEADS; l += blockDim.x) {
        sq[l] = g_wq[l];
        sk[l] = g_wk[l];
    }
    __syncthreads();
    int gid = blockIdx.x * blockDim.x + threadIdx.x;
    int n = gid >> 3, r = gid & 7;
    if (n >= NN) return;
    const float* A = use_h1 ? g_h1 : xin;
    const float* row = A + n * 128;
    const float* wq = sq + r * HID * HEADS;
    const float* wk = sk + r * HID * HEADS;
    float aq0 = 0, aq1 = 0, aq2 = 0, aq3 = 0;
    float ak0 = 0, ak1 = 0, ak2 = 0, ak3 = 0;
#pragma unroll 4
    for (int i = 0; i < 128; i++) {
        float v = row[i];
        aq0 += v * wq[i * 4 + 0]; aq1 += v * wq[i * 4 + 1];
        aq2 += v * wq[i * 4 + 2]; aq3 += v * wq[i * 4 + 3];
        ak0 += v * wk[i * 4 + 0]; ak1 += v * wk[i * 4 + 1];
        ak2 += v * wk[i * 4 + 2]; ak3 += v * wk[i * 4 + 3];
    }
    int base = (n * RR + r) * HEADS;
    g_aq[base + 0] = aq0; g_aq[base + 1] = aq1; g_aq[base + 2] = aq2; g_aq[base + 3] = aq3;
    g_ak[base + 0] = ak0; g_ak[base + 1] = ak1; g_ak[base + 2] = ak2; g_ak[base + 3] = ak3;
}

// ---------------- per-edge logits + segment max ----------------
__global__ void k_edge_alpha(const int* __restrict__ ei, const int* __restrict__ et) {
    int e = blockIdx.x * blockDim.x + threadIdx.x;
    if (e >= EE) return;
    int src = ei[e], dst = ei[EE + e], r = et[e];
    const float* aq = g_aq + (dst * RR + r) * HEADS;
    const float* ak = g_ak + (src * RR + r) * HEADS;
#pragma unroll
    for (int h = 0; h < HEADS; h++) {
        float a = aq[h] + ak[h];
        a = a > 0.f ? a : 0.2f * a;          // leaky_relu(0.2)
        g_alpha[e * HEADS + h] = a;
        atomicMaxF(&g_amax[dst * HEADS + h], a);
    }
}

// ---------------- exp + segment sum ----------------
__global__ void k_edge_exp(const int* __restrict__ ei) {
    int e = blockIdx.x * blockDim.x + threadIdx.x;
    if (e >= EE) return;
    int dst = ei[EE + e];
#pragma unroll
    for (int h = 0; h < HEADS; h++) {
        float ex = expf(g_alpha[e * HEADS + h] - g_amax[dst * HEADS + h]);
        g_alpha[e * HEADS + h] = ex;
        atomicAdd(&g_den[dst * HEADS + h], ex);
    }
}

// ---------------- weighted message scatter (warp per edge) ----------------
__global__ void k_edge_scatter(const int* __restrict__ ei, const int* __restrict__ et) {
    int gw = (blockIdx.x * blockDim.x + threadIdx.x) >> 5;
    if (gw >= EE) return;
    int lane = threadIdx.x & 31;
    int e = gw;
    int src = ei[e], dst = ei[EE + e], r = et[e];
    int h = lane >> 3;                                   // 4 floats per lane, same head
    float attn = g_alpha[e * HEADS + h] / (g_den[dst * HEADS + h] + 1e-16f);
    float4 xj = *(const float4*)(g_xw + (src * RR + r) * HID + lane * 4);
    float* o = g_agg + dst * HID + lane * 4;
    atomicAdd(o + 0, xj.x * attn);
    atomicAdd(o + 1, xj.y * attn);
    atomicAdd(o + 2, xj.z * attn);
    atomicAdd(o + 3, xj.w * attn);
}

// ---------------- bias + relu + layernorm (warp per node) ----------------
__global__ void k_ln(const float* __restrict__ bias, const float* __restrict__ gam,
                     const float* __restrict__ bet, int layer) {
    int nid = blockIdx.x * 8 + (threadIdx.x >> 5);
    if (nid >= NN) return;
    int lane = threadIdx.x & 31;
    float4 v = *(const float4*)(g_agg + nid * HID + lane * 4);
    float4 bb = *(const float4*)(bias + lane * 4);
    v.x = fmaxf(v.x + bb.x, 0.f);
    v.y = fmaxf(v.y + bb.y, 0.f);
    v.z = fmaxf(v.z + bb.z, 0.f);
    v.w = fmaxf(v.w + bb.w, 0.f);
    float s = v.x + v.y + v.z + v.w;
#pragma unroll
    for (int o = 16; o >= 1; o >>= 1) s += __shfl_xor_sync(0xffffffffu, s, o);
    float mean = s * (1.f / 128.f);
    float dx = v.x - mean, dy = v.y - mean, dz = v.z - mean, dw = v.w - mean;
    float ss = dx * dx + dy * dy + dz * dz + dw * dw;
#pragma unroll
    for (int o = 16; o >= 1; o >>= 1) ss += __shfl_xor_sync(0xffffffffu, ss, o);
    float rs = rsqrtf(ss * (1.f / 128.f) + 1e-5f);
    float4 g4 = *(const float4*)(gam + lane * 4);
    float4 b4 = *(const float4*)(bet + lane * 4);
    float4 y;
    y.x = dx * rs * g4.x + b4.x;
    y.y = dy * rs * g4.y + b4.y;
    y.z = dz * rs * g4.z + b4.z;
    y.w = dw * rs * g4.w + b4.w;
    if (layer == 1) {
        *(float4*)(g_h1 + nid * HID + lane * 4) = y;
    } else {
        float4 h1 = *(const float4*)(g_h1 + nid * HID + lane * 4);
        y.x += h1.x; y.y += h1.y; y.z += h1.z; y.w += h1.w;
        *(float4*)(g_hsum + nid * HID + lane * 4) = y;
    }
}

// ---------------- decode GEMM 1: gathered [E2,256] x [256,128] + GELU ----------------
__global__ void k_decode1(const int* __restrict__ edges, const float* __restrict__ mw1,
                          const float* __restrict__ mb1) {
    __shared__ float As[32][65];
    __shared__ float Bs[32][128];
    __shared__ int sidx[64][2];
    const int t = threadIdx.x;
    const int row0 = blockIdx.x * 64;
    if (t < 64) {
        int2 p = ((const int2*)edges)[row0 + t];
        sidx[t][0] = p.x;
        sidx[t][1] = p.y;
    }
    __syncthreads();
    const int tx = t & 15, ty = t >> 4;
    float acc[4][8];
#pragma unroll
    for (int i = 0; i < 4; i++)
#pragma unroll
        for (int j = 0; j < 8; j++) acc[i][j] = 0.f;

    for (int k0 = 0; k0 < 256; k0 += 32) {
        const int half = (k0 >= 128) ? 1 : 0;
        const int colbase = k0 - half * 128;
        for (int l = t; l < 64 * 32; l += 256) {
            int row = l >> 5, kk = l & 31;
            int node = sidx[row][half];
            As[kk][row] = g_hsum[node * HID + colbase + kk];
        }
        for (int l = t; l < 32 * 128; l += 256) {
            int kk = l >> 7, c = l & 127;
            Bs[kk][c] = mw1[(k0 + kk) * 128 + c];
        }
        __syncthreads();
#pragma unroll
        for (int kk = 0; kk < 32; kk++) {
            float a[4], b[8];
#pragma unroll
            for (int i = 0; i < 4; i++) a[i] = As[kk][ty * 4 + i];
            float4 b0 = *(const float4*)&Bs[kk][tx * 8];
            float4 b1 = *(const float4*)&Bs[kk][tx * 8 + 4];
            b[0] = b0.x; b[1] = b0.y; b[2] = b0.z; b[3] = b0.w;
            b[4] = b1.x; b[5] = b1.y; b[6] = b1.z; b[7] = b1.w;
#pragma unroll
            for (int i = 0; i < 4; i++)
#pragma unroll
                for (int j = 0; j < 8; j++) acc[i][j] += a[i] * b[j];
        }
        __syncthreads();
    }
#pragma unroll
    for (int i = 0; i < 4; i++) {
        int p = row0 + ty * 4 + i;
#pragma unroll
        for (int j = 0; j < 8; j++) {
            int c = tx * 8 + j;
            float v = acc[i][j] + mb1[c];
            v = 0.5f * v * (1.f + erff(v * 0.70710678118654752f));  // exact GELU
            g_z[p * HID + c] = v;
        }
    }
}

// ---------------- decode GEMM 2: [E2,128] x [128,8] (warp per pair) ----------------
__global__ void k_decode2(const float* __restrict__ mw2, const float* __restrict__ mb2,
                          float* __restrict__ out) {
    __shared__ float sw[HID * NCLS];
    __shared__ float sb[NCLS];
    const int t = threadIdx.x;
    for (int l = t; l < HID * NCLS; l += 256) sw[l] = mw2[l];
    if (t < NCLS) sb[t] = mb2[t];
    __syncthreads();
    int p = blockIdx.x * 8 + (t >> 5);
    int lane = t & 31;
    float4 z = *(const float4*)(g_z + p * HID + lane * 4);
    const float* w = sw + lane * 4 * NCLS;
    float acc[NCLS];
#pragma unroll
    for (int c = 0; c < NCLS; c++)
        acc[c] = z.x * w[c] + z.y * w[NCLS + c] + z.z * w[2 * NCLS + c] + z.w * w[3 * NCLS + c];
#pragma unroll
    for (int o = 16; o >= 1; o >>= 1)
#pragma unroll
        for (int c = 0; c < NCLS; c++) acc[c] += __shfl_xor_sync(0xffffffffu, acc[c], o);
    if (lane < NCLS) out[p * NCLS + lane] = acc[lane] + sb[lane];
}

// ---------------- launch ----------------
extern "C" void kernel_launch(void* const* d_in, const int* in_sizes, int n_in,
                              void* d_out, int out_size) {
    const float* x     = (const float*)d_in[0];
    const int*   ei    = (const int*)d_in[1];
    const int*   et    = (const int*)d_in[2];
    const int*   edges = (const int*)d_in[3];
    const float* w1 = (const float*)d_in[4];
    const float* q1 = (const float*)d_in[5];
    const float* k1 = (const float*)d_in[6];
    const float* b1 = (const float*)d_in[7];
    const float* w2 = (const float*)d_in[8];
    const float* q2 = (const float*)d_in[9];
    const float* k2 = (const float*)d_in[10];
    const float* b2 = (const float*)d_in[11];
    const float* ln1g = (const float*)d_in[12];
    const float* ln1b = (const float*)d_in[13];
    const float* ln2g = (const float*)d_in[14];
    const float* ln2b = (const float*)d_in[15];
    const float* mw1 = (const float*)d_in[16];
    const float* mb1 = (const float*)d_in[17];
    const float* mw2 = (const float*)d_in[18];
    const float* mb2 = (const float*)d_in[19];
    float* out = (float*)d_out;

    const int gInit = (NN * HID + 255) / 256;
    const dim3 gXW((NN + 63) / 64, RR);
    const int gAQK = (NN * RR + 255) / 256;
    const int gE = (EE + 255) / 256;
    const int gScat = (EE * 32 + 255) / 256;
    const int gLN = NN / 8;

    // ---- layer 1 ----
    k_wqk<<<(RR * HID * HEADS + 255) / 256, 256>>>(w1, q1, k1);
    k_init<<<gInit, 256>>>();
    k_gemm_xw<<<gXW, 256>>>(x, w1, 0);
    k_aqk<<<gAQK, 256>>>(x, 0);
    k_edge_alpha<<<gE, 256>>>(ei, et);
    k_edge_exp<<<gE, 256>>>(ei);
    k_edge_scatter<<<gScat, 256>>>(ei, et);
    k_ln<<<gLN, 256>>>(b1, ln1g, ln1b, 1);

    // ---- layer 2 ----
    k_wqk<<<(RR * HID * HEADS + 255) / 256, 256>>>(w2, q2, k2);
    k_init<<<gInit, 256>>>();
    k_gemm_xw<<<gXW, 256>>>(x, w2, 1);
    k_aqk<<<gAQK, 256>>>(x, 1);
    k_edge_alpha<<<gE, 256>>>(ei, et);
    k_edge_exp<<<gE, 256>>>(ei);
    k_edge_scatter<<<gScat, 256>>>(ei, et);
    k_ln<<<gLN, 256>>>(b2, ln2g, ln2b, 2);

    // ---- decode ----
    k_decode1<<<EE2 / 64, 256>>>(edges, mw1, mb1);
    k_decode2<<<EE2 / 8, 256>>>(mw2, mb2, out);
}

// round 2
// speedup vs baseline: 1.9329x; 1.9329x over previous
#include <cuda_runtime.h>
#include <math.h>

#define NN   50000
#define HID  128
#define RR   8
#define EE   640000
#define EE2  200000
#define NCLS 8

// ---------------- scratch (device globals; allocation-free) ----------------
__device__ float g_xw[NN * RR * HID];      // per-(node,rel) transformed feats
__device__ float g_aq[NN * RR * 4];
__device__ float g_ak[NN * RR * 4];
__device__ float g_h1[NN * HID];
__device__ float g_hsum[NN * HID];
__device__ float g_z[EE2 * HID];
__device__ int   g_deg[NN];
__device__ int   g_rowptr[NN + 1];
__device__ int   g_cursor[NN];
__device__ int   g_csr[EE];                // packed src*8 + rel per in-edge

// ---------------- CSR build ----------------
__global__ void k_zero() {
    int i = blockIdx.x * blockDim.x + threadIdx.x;
    if (i < NN) g_deg[i] = 0;
}

__global__ void k_hist(const int* __restrict__ ei) {
    int e = blockIdx.x * blockDim.x + threadIdx.x;
    if (e < EE) atomicAdd(&g_deg[ei[EE + e]], 1);
}

__global__ void k_scan() {
    __shared__ int sp[1024];
    const int t = threadIdx.x;
    const int chunk = (NN + 1023) / 1024;
    int start = t * chunk;
    int end = min(start + chunk, NN);
    int s = 0;
    for (int i = start; i < end; i++) s += g_deg[i];
    sp[t] = s;
    __syncthreads();
    for (int off = 1; off < 1024; off <<= 1) {
        int v = (t >= off) ? sp[t - off] : 0;
        __syncthreads();
        sp[t] += v;
        __syncthreads();
    }
    int run = (t == 0) ? 0 : sp[t - 1];
    for (int i = start; i < end; i++) {
        g_rowptr[i] = run;
        g_cursor[i] = run;
        run += g_deg[i];
    }
    if (t == 1023) g_rowptr[NN] = run;
}

__global__ void k_fill(const int* __restrict__ ei, const int* __restrict__ et) {
    int e = blockIdx.x * blockDim.x + threadIdx.x;
    if (e >= EE) return;
    int dst = ei[EE + e];
    int pos = atomicAdd(&g_cursor[dst], 1);
    g_csr[pos] = ei[e] * 8 + et[e];
}

// ---------------- fused GEMM: xw = A @ W[r], plus aq/ak epilogue ----------------
// 128x128 tile, K chunks of 16, 256 threads, 8x8 register tile.
__global__ void __launch_bounds__(256, 2)
k_gemm_fused(const float* __restrict__ xin, const float* __restrict__ W,
             const float* __restrict__ qm, const float* __restrict__ km,
             int use_h1) {
    __shared__ float As[16][132];   // [kk][row], row-dim padded
    __shared__ float Bs[16][128];   // [kk][col]
    __shared__ float sq[128][4];
    __shared__ float sk[128][4];
    const int r = blockIdx.y;
    const int row0 = blockIdx.x * 128;
    const float* A = use_h1 ? g_h1 : xin;
    const float* B = W + r * HID * HID;
    const int t = threadIdx.x;
    const int tx = t & 15, ty = t >> 4;

    if (t < 128) {
        *(float4*)&sq[t][0] = *(const float4*)&qm[t * 4];
        *(float4*)&sk[t][0] = *(const float4*)&km[t * 4];
    }

    float acc[8][8];
#pragma unroll
    for (int i = 0; i < 8; i++)
#pragma unroll
        for (int j = 0; j < 8; j++) acc[i][j] = 0.f;

    const int lrow = t >> 1;
    const int lkk = (t & 1) * 8;
    const int gr_l = row0 + lrow;
    const int bkk = (t * 8) >> 7;
    const int bcol = (t * 8) & 127;

    for (int k0 = 0; k0 < 128; k0 += 16) {
        float4 v0, v1;
        if (gr_l < NN) {
            v0 = *(const float4*)&A[gr_l * 128 + k0 + lkk];
            v1 = *(const float4*)&A[gr_l * 128 + k0 + lkk + 4];
        } else {
            v0 = make_float4(0.f, 0.f, 0.f, 0.f);
            v1 = v0;
        }
        float4 b0 = *(const float4*)&B[(k0 + bkk) * 128 + bcol];
        float4 b1 = *(const float4*)&B[(k0 + bkk) * 128 + bcol + 4];
        __syncthreads();
        As[lkk + 0][lrow] = v0.x; As[lkk + 1][lrow] = v0.y;
        As[lkk + 2][lrow] = v0.z; As[lkk + 3][lrow] = v0.w;
        As[lkk + 4][lrow] = v1.x; As[lkk + 5][lrow] = v1.y;
        As[lkk + 6][lrow] = v1.z; As[lkk + 7][lrow] = v1.w;
        *(float4*)&Bs[bkk][bcol] = b0;
        *(float4*)&Bs[bkk][bcol + 4] = b1;
        __syncthreads();
#pragma unroll
        for (int kk = 0; kk < 16; kk++) {
            float4 a0 = *(const float4*)&As[kk][ty * 8];
            float4 a1 = *(const float4*)&As[kk][ty * 8 + 4];
            float4 c0 = *(const float4*)&Bs[kk][tx * 8];
            float4 c1 = *(const float4*)&Bs[kk][tx * 8 + 4];
            float av[8] = {a0.x, a0.y, a0.z, a0.w, a1.x, a1.y, a1.z, a1.w};
            float bv[8] = {c0.x, c0.y, c0.z, c0.w, c1.x, c1.y, c1.z, c1.w};
#pragma unroll
            for (int i = 0; i < 8; i++)
#pragma unroll
                for (int j = 0; j < 8; j++) acc[i][j] += av[i] * bv[j];
        }
    }

    // store xw
#pragma unroll
    for (int i = 0; i < 8; i++) {
        int gr = row0 + ty * 8 + i;
        if (gr < NN) {
            float* dst = g_xw + (gr * 8 + r) * 128 + tx * 8;
            *(float4*)dst = make_float4(acc[i][0], acc[i][1], acc[i][2], acc[i][3]);
            *(float4*)(dst + 4) = make_float4(acc[i][4], acc[i][5], acc[i][6], acc[i][7]);
        }
    }

    // aq/ak epilogue: partial dot over this thread's 8 cols, butterfly over tx
#pragma unroll
    for (int half = 0; half < 2; half++) {
        float pq[4][4], pk[4][4];
#pragma unroll
        for (int i = 0; i < 4; i++)
#pragma unroll
            for (int h = 0; h < 4; h++) { pq[i][h] = 0.f; pk[i][h] = 0.f; }
#pragma unroll
        for (int j = 0; j < 8; j++) {
            int col = tx * 8 + j;
            float q0 = sq[col][0], q1 = sq[col][1], q2 = sq[col][2], q3 = sq[col][3];
            float s0 = sk[col][0], s1 = sk[col][1], s2 = sk[col][2], s3 = sk[col][3];
#pragma unroll
            for (int i = 0; i < 4; i++) {
                float a = acc[half * 4 + i][j];
                pq[i][0] += a * q0; pq[i][1] += a * q1; pq[i][2] += a * q2; pq[i][3] += a * q3;
                pk[i][0] += a * s0; pk[i][1] += a * s1; pk[i][2] += a * s2; pk[i][3] += a * s3;
            }
        }
#pragma unroll
        for (int off = 1; off < 16; off <<= 1) {
#pragma unroll
            for (int i = 0; i < 4; i++)
#pragma unroll
                for (int h = 0; h < 4; h++) {
                    pq[i][h] += __shfl_xor_sync(0xffffffffu, pq[i][h], off);
                    pk[i][h] += __shfl_xor_sync(0xffffffffu, pk[i][h], off);
                }
        }
        if (tx == 0) {
#pragma unroll
            for (int i = 0; i < 4; i++) {
                int gr = row0 + ty * 8 + half * 4 + i;
                if (gr < NN) {
                    *(float4*)&g_aq[(gr * 8 + r) * 4] =
                        make_float4(pq[i][0], pq[i][1], pq[i][2], pq[i][3]);
                    *(float4*)&g_ak[(gr * 8 + r) * 4] =
                        make_float4(pk[i][0], pk[i][1], pk[i][2], pk[i][3]);
                }
            }
        }
    }
}

// ---------------- fused per-node softmax + aggregate + bias + relu + LN ----------------
// warp per dst node; lane owns 4 cols; head = lane>>3.
__global__ void k_agg_ln(const float* __restrict__ bias, const float* __restrict__ gam,
                         const float* __restrict__ bet, int layer) {
    int nid = blockIdx.x * 8 + (threadIdx.x >> 5);
    if (nid >= NN) return;
    int lane = threadIdx.x & 31;
    int h = lane >> 3;
    int j0 = g_rowptr[nid], j1 = g_rowptr[nid + 1];
    float4 num = make_float4(0.f, 0.f, 0.f, 0.f);
    float den = 0.f;
    const int aqbase = nid * 32 + h;
    for (int j = j0; j < j1; j++) {
        int p = g_csr[j];                 // src*8 + r
        int r = p & 7;
        float a = g_aq[aqbase + r * 4] + g_ak[p * 4 + h];
        a = a > 0.f ? a : 0.2f * a;       // leaky_relu(0.2)
        float ex = expf(a);               // max-shift dropped (logits bounded)
        den += ex;
        float4 xj = *(const float4*)&g_xw[p * 128 + lane * 4];
        num.x += ex * xj.x; num.y += ex * xj.y;
        num.z += ex * xj.z; num.w += ex * xj.w;
    }
    float inv = 1.f / (den + 1e-16f);
    float4 bb = *(const float4*)&bias[lane * 4];
    float4 v;
    v.x = fmaxf(num.x * inv + bb.x, 0.f);
    v.y = fmaxf(num.y * inv + bb.y, 0.f);
    v.z = fmaxf(num.z * inv + bb.z, 0.f);
    v.w = fmaxf(num.w * inv + bb.w, 0.f);
    float s = v.x + v.y + v.z + v.w;
#pragma unroll
    for (int o = 16; o >= 1; o >>= 1) s += __shfl_xor_sync(0xffffffffu, s, o);
    float mean = s * (1.f / 128.f);
    float dx = v.x - mean, dy = v.y - mean, dz = v.z - mean, dw = v.w - mean;
    float ss = dx * dx + dy * dy + dz * dz + dw * dw;
#pragma unroll
    for (int o = 16; o >= 1; o >>= 1) ss += __shfl_xor_sync(0xffffffffu, ss, o);
    float rs = rsqrtf(ss * (1.f / 128.f) + 1e-5f);
    float4 g4 = *(const float4*)&gam[lane * 4];
    float4 b4 = *(const float4*)&bet[lane * 4];
    float4 y;
    y.x = dx * rs * g4.x + b4.x;
    y.y = dy * rs * g4.y + b4.y;
    y.z = dz * rs * g4.z + b4.z;
    y.w = dw * rs * g4.w + b4.w;
    if (layer == 1) {
        *(float4*)&g_h1[nid * HID + lane * 4] = y;
    } else {
        float4 h1 = *(const float4*)&g_h1[nid * HID + lane * 4];
        y.x += h1.x; y.y += h1.y; y.z += h1.z; y.w += h1.w;
        *(float4*)&g_hsum[nid * HID + lane * 4] = y;
    }
}

// ---------------- decode GEMM 1: gathered [E2,256] x [256,128] + GELU ----------------
__global__ void __launch_bounds__(256, 2)
k_decode1(const int* __restrict__ edges, const float* __restrict__ mw1,
          const float* __restrict__ mb1) {
    __shared__ float As[16][132];
    __shared__ float Bs[16][128];
    __shared__ int sidx[128][2];
    const int t = threadIdx.x;
    const int row0 = blockIdx.x * 128;
    if (t < 128) {
        int p = row0 + t;
        int2 pr = (p < EE2) ? ((const int2*)edges)[p] : make_int2(0, 0);
        sidx[t][0] = pr.x;
        sidx[t][1] = pr.y;
    }
    const int tx = t & 15, ty = t >> 4;
    float acc[8][8];
#pragma unroll
    for (int i = 0; i < 8; i++)
#pragma unroll
        for (int j = 0; j < 8; j++) acc[i][j] = 0.f;

    const int lrow = t >> 1;
    const int lkk = (t & 1) * 8;
    const int bkk = (t * 8) >> 7;
    const int bcol = (t * 8) & 127;
    __syncthreads();
    const int node0 = sidx[lrow][0];
    const int node1 = sidx[lrow][1];

    for (int k0 = 0; k0 < 256; k0 += 16) {
        int node = (k0 < 128) ? node0 : node1;
        int colbase = (k0 & 127) + lkk;
        float4 v0 = *(const float4*)&g_hsum[node * 128 + colbase];
        float4 v1 = *(const float4*)&g_hsum[node * 128 + colbase + 4];
        float4 b0 = *(const float4*)&mw1[(k0 + bkk) * 128 + bcol];
        float4 b1 = *(const float4*)&mw1[(k0 + bkk) * 128 + bcol + 4];
        __syncthreads();
        As[lkk + 0][lrow] = v0.x; As[lkk + 1][lrow] = v0.y;
        As[lkk + 2][lrow] = v0.z; As[lkk + 3][lrow] = v0.w;
        As[lkk + 4][lrow] = v1.x; As[lkk + 5][lrow] = v1.y;
        As[lkk + 6][lrow] = v1.z; As[lkk + 7][lrow] = v1.w;
        *(float4*)&Bs[bkk][bcol] = b0;
        *(float4*)&Bs[bkk][bcol + 4] = b1;
        __syncthreads();
#pragma unroll
        for (int kk = 0; kk < 16; kk++) {
            float4 a0 = *(const float4*)&As[kk][ty * 8];
            float4 a1 = *(const float4*)&As[kk][ty * 8 + 4];
            float4 c0 = *(const float4*)&Bs[kk][tx * 8];
            float4 c1 = *(const float4*)&Bs[kk][tx * 8 + 4];
            float av[8] = {a0.x, a0.y, a0.z, a0.w, a1.x, a1.y, a1.z, a1.w};
            float bv[8] = {c0.x, c0.y, c0.z, c0.w, c1.x, c1.y, c1.z, c1.w};
#pragma unroll
            for (int i = 0; i < 8; i++)
#pragma unroll
                for (int j = 0; j < 8; j++) acc[i][j] += av[i] * bv[j];
        }
    }

    float4 bb0 = *(const float4*)&mb1[tx * 8];
    float4 bb1 = *(const float4*)&mb1[tx * 8 + 4];
    float bb[8] = {bb0.x, bb0.y, bb0.z, bb0.w, bb1.x, bb1.y, bb1.z, bb1.w};
#pragma unroll
    for (int i = 0; i < 8; i++) {
        int p = row0 + ty * 8 + i;
        if (p >= EE2) continue;
        float o[8];
#pragma unroll
        for (int j = 0; j < 8; j++) {
            float v = acc[i][j] + bb[j];
            o[j] = 0.5f * v * (1.f + erff(v * 0.70710678118654752f));
        }
        float* dst = g_z + p * 128 + tx * 8;
        *(float4*)dst = make_float4(o[0], o[1], o[2], o[3]);
        *(float4*)(dst + 4) = make_float4(o[4], o[5], o[6], o[7]);
    }
}

// ---------------- decode GEMM 2: [E2,128] x [128,8] (warp per pair) ----------------
__global__ void k_decode2(const float* __restrict__ mw2, const float* __restrict__ mb2,
                          float* __restrict__ out) {
    __shared__ float sw[HID * NCLS];
    __shared__ float sb[NCLS];
    const int t = threadIdx.x;
    for (int l = t; l < HID * NCLS; l += 256) sw[l] = mw2[l];
    if (t < NCLS) sb[t] = mb2[t];
    __syncthreads();
    int p = blockIdx.x * 8 + (t >> 5);
    int lane = t & 31;
    float4 z = *(const float4*)&g_z[p * HID + lane * 4];
    const float* w = sw + lane * 4 * NCLS;
    float acc[NCLS];
#pragma unroll
    for (int c = 0; c < NCLS; c++)
        acc[c] = z.x * w[c] + z.y * w[NCLS + c] + z.z * w[2 * NCLS + c] + z.w * w[3 * NCLS + c];
#pragma unroll
    for (int o = 16; o >= 1; o >>= 1)
#pragma unroll
        for (int c = 0; c < NCLS; c++) acc[c] += __shfl_xor_sync(0xffffffffu, acc[c], o);
    if (lane < NCLS) out[p * NCLS + lane] = acc[lane] + sb[lane];
}

// ---------------- launch ----------------
extern "C" void kernel_launch(void* const* d_in, const int* in_sizes, int n_in,
                              void* d_out, int out_size) {
    const float* x     = (const float*)d_in[0];
    const int*   ei    = (const int*)d_in[1];
    const int*   et    = (const int*)d_in[2];
    const int*   edges = (const int*)d_in[3];
    const float* w1 = (const float*)d_in[4];
    const float* q1 = (const float*)d_in[5];
    const float* k1 = (const float*)d_in[6];
    const float* b1 = (const float*)d_in[7];
    const float* w2 = (const float*)d_in[8];
    const float* q2 = (const float*)d_in[9];
    const float* k2 = (const float*)d_in[10];
    const float* b2 = (const float*)d_in[11];
    const float* ln1g = (const float*)d_in[12];
    const float* ln1b = (const float*)d_in[13];
    const float* ln2g = (const float*)d_in[14];
    const float* ln2b = (const float*)d_in[15];
    const float* mw1 = (const float*)d_in[16];
    const float* mb1 = (const float*)d_in[17];
    const float* mw2 = (const float*)d_in[18];
    const float* mb2 = (const float*)d_in[19];
    float* out = (float*)d_out;

    // ---- CSR by destination (built once, reused by both layers) ----
    k_zero<<<(NN + 255) / 256, 256>>>();
    k_hist<<<(EE + 255) / 256, 256>>>(ei);
    k_scan<<<1, 1024>>>();
    k_fill<<<(EE + 255) / 256, 256>>>(ei, et);

    const dim3 gXW((NN + 127) / 128, RR);
    const int gAgg = (NN + 7) / 8;

    // ---- layer 1 ----
    k_gemm_fused<<<gXW, 256>>>(x, w1, q1, k1, 0);
    k_agg_ln<<<gAgg, 256>>>(b1, ln1g, ln1b, 1);

    // ---- layer 2 ----
    k_gemm_fused<<<gXW, 256>>>(x, w2, q2, k2, 1);
    k_agg_ln<<<gAgg, 256>>>(b2, ln2g, ln2b, 2);

    // ---- decode ----
    k_decode1<<<(EE2 + 127) / 128, 256>>>(edges, mw1, mb1);
    k_decode2<<<EE2 / 8, 256>>>(mw2, mb2, out);
}

// round 3
// speedup vs baseline: 2.2896x; 1.1845x over previous
#include <cuda_runtime.h>
#include <math.h>
#include <stdint.h>

#define NN   50000
#define HID  128
#define RR   8
#define EE   640000
#define EE2  200000
#define NCLS 8

// ---------------- scratch (device globals; allocation-free) ----------------
__device__ float g_xw[NN * RR * HID];
__device__ float g_aq[NN * RR * 4];
__device__ float g_ak[NN * RR * 4];
__device__ float g_h1[NN * HID];
__device__ float g_hsum[NN * HID];
__device__ float g_z[EE2 * HID];
__device__ int   g_deg[NN];
__device__ int   g_rowptr[NN + 1];
__device__ int   g_cursor[NN];
__device__ int   g_csr[EE];                // packed src*8 + rel per in-edge

// ---------------- mma helpers ----------------
__device__ __forceinline__ uint32_t f2tf(float f) {
    uint32_t u;
    asm("cvt.rna.tf32.f32 %0, %1;" : "=r"(u) : "f"(f));
    return u;
}
__device__ __forceinline__ void tf_split(float f, uint32_t& hi, uint32_t& lo) {
    hi = f2tf(f);
    lo = f2tf(f - __uint_as_float(hi));
}
__device__ __forceinline__ void mma_tf32(float4& d, const uint32_t* a, const uint32_t* b) {
    asm volatile(
        "mma.sync.aligned.m16n8k8.row.col.f32.tf32.tf32.f32 "
        "{%0,%1,%2,%3}, {%4,%5,%6,%7}, {%8,%9}, {%0,%1,%2,%3};"
        : "+f"(d.x), "+f"(d.y), "+f"(d.z), "+f"(d.w)
        : "r"(a[0]), "r"(a[1]), "r"(a[2]), "r"(a[3]), "r"(b[0]), "r"(b[1]));
}

// ---------------- CSR build ----------------
__global__ void k_zero() {
    int i = blockIdx.x * blockDim.x + threadIdx.x;
    if (i < NN) g_deg[i] = 0;
}
__global__ void k_hist(const int* __restrict__ ei) {
    int e = blockIdx.x * blockDim.x + threadIdx.x;
    if (e < EE) atomicAdd(&g_deg[ei[EE + e]], 1);
}
__global__ void k_scan() {
    __shared__ int sp[1024];
    const int t = threadIdx.x;
    const int chunk = (NN + 1023) / 1024;
    int start = t * chunk;
    int end = min(start + chunk, NN);
    int s = 0;
    for (int i = start; i < end; i++) s += g_deg[i];
    sp[t] = s;
    __syncthreads();
    for (int off = 1; off < 1024; off <<= 1) {
        int v = (t >= off) ? sp[t - off] : 0;
        __syncthreads();
        sp[t] += v;
        __syncthreads();
    }
    int run = (t == 0) ? 0 : sp[t - 1];
    for (int i = start; i < end; i++) {
        g_rowptr[i] = run;
        g_cursor[i] = run;
        run += g_deg[i];
    }
    if (t == 1023) g_rowptr[NN] = run;
}
__global__ void k_fill(const int* __restrict__ ei, const int* __restrict__ et) {
    int e = blockIdx.x * blockDim.x + threadIdx.x;
    if (e >= EE) return;
    int dst = ei[EE + e];
    int pos = atomicAdd(&g_cursor[dst], 1);
    g_csr[pos] = ei[e] * 8 + et[e];
}

// ---------------- fused tf32x3 GEMM: xw = A @ W[r], plus aq/ak epilogue ----------------
// 128x128 tile, 8 warps (4m x 2n), warp tile m32 x n64, mma m16n8k8 tf32.
__global__ void __launch_bounds__(256)
k_gemm_fused(const float* __restrict__ xin, const float* __restrict__ W,
             const float* __restrict__ qm, const float* __restrict__ km,
             int use_h1) {
    __shared__ float As[128][20];     // [row][k-chunk], conflict-free for frag loads
    __shared__ float Bs[16][136];     // [k][col], conflict-free
    __shared__ float sq[128][4], sk[128][4];
    __shared__ float s_aq[128][4], s_ak[128][4];

    const int r = blockIdx.y;
    const int row0 = blockIdx.x * 128;
    const float* A = use_h1 ? g_h1 : xin;
    const float* B = W + r * HID * HID;
    const int t = threadIdx.x;
    const int lane = t & 31, wid = t >> 5;
    const int wm = wid & 3, wn = wid >> 2;
    const int g = lane >> 2, tg = lane & 3;

    if (t < 128) {
        *(float4*)sq[t] = *(const float4*)&qm[t * 4];
        *(float4*)sk[t] = *(const float4*)&km[t * 4];
        *(float4*)s_aq[t] = make_float4(0.f, 0.f, 0.f, 0.f);
        *(float4*)s_ak[t] = make_float4(0.f, 0.f, 0.f, 0.f);
    }

    float4 acc[2][8];
#pragma unroll
    for (int i = 0; i < 2; i++)
#pragma unroll
        for (int j = 0; j < 8; j++) acc[i][j] = make_float4(0.f, 0.f, 0.f, 0.f);

    const int lrow = t >> 1;
    const int lkk = (t & 1) * 8;
    const int gr_l = row0 + lrow;
    const int bkk = t >> 4;
    const int bcol = (t & 15) * 8;

    for (int k0 = 0; k0 < 128; k0 += 16) {
        float4 v0, v1;
        if (gr_l < NN) {
            v0 = *(const float4*)&A[gr_l * 128 + k0 + lkk];
            v1 = *(const float4*)&A[gr_l * 128 + k0 + lkk + 4];
        } else {
            v0 = make_float4(0.f, 0.f, 0.f, 0.f);
            v1 = v0;
        }
        float4 b0 = *(const float4*)&B[(k0 + bkk) * 128 + bcol];
        float4 b1 = *(const float4*)&B[(k0 + bkk) * 128 + bcol + 4];
        __syncthreads();
        *(float4*)&As[lrow][lkk] = v0;
        *(float4*)&As[lrow][lkk + 4] = v1;
        *(float4*)&Bs[bkk][bcol] = b0;
        *(float4*)&Bs[bkk][bcol + 4] = b1;
        __syncthreads();
#pragma unroll
        for (int ks = 0; ks < 16; ks += 8) {
            uint32_t ahi[2][4], alo[2][4];
#pragma unroll
            for (int i = 0; i < 2; i++) {
                int m0 = wm * 32 + i * 16;
                tf_split(As[m0 + g][ks + tg],         ahi[i][0], alo[i][0]);
                tf_split(As[m0 + g + 8][ks + tg],     ahi[i][1], alo[i][1]);
                tf_split(As[m0 + g][ks + tg + 4],     ahi[i][2], alo[i][2]);
                tf_split(As[m0 + g + 8][ks + tg + 4], ahi[i][3], alo[i][3]);
            }
            uint32_t bhi[8][2], blo[8][2];
#pragma unroll
            for (int j = 0; j < 8; j++) {
                int n0 = wn * 64 + j * 8;
                tf_split(Bs[ks + tg][n0 + g],     bhi[j][0], blo[j][0]);
                tf_split(Bs[ks + tg + 4][n0 + g], bhi[j][1], blo[j][1]);
            }
#pragma unroll
            for (int i = 0; i < 2; i++)
#pragma unroll
                for (int j = 0; j < 8; j++) {
                    mma_tf32(acc[i][j], ahi[i], blo[j]);
                    mma_tf32(acc[i][j], alo[i], bhi[j]);
                    mma_tf32(acc[i][j], ahi[i], bhi[j]);
                }
        }
    }

    // ---- store xw ----
#pragma unroll
    for (int i = 0; i < 2; i++)
#pragma unroll
        for (int half = 0; half < 2; half++) {
            int gr = row0 + wm * 32 + i * 16 + half * 8 + g;
            if (gr < NN) {
                float* dst = &g_xw[(gr * 8 + r) * 128 + wn * 64 + 2 * tg];
#pragma unroll
                for (int j = 0; j < 8; j++) {
                    float2 v = half ? make_float2(acc[i][j].z, acc[i][j].w)
                                    : make_float2(acc[i][j].x, acc[i][j].y);
                    *(float2*)(dst + j * 8) = v;
                }
            }
        }

    // ---- aq/ak epilogue ----
    float pq[4][4], pk[4][4];
#pragma unroll
    for (int rr = 0; rr < 4; rr++)
#pragma unroll
        for (int h = 0; h < 4; h++) { pq[rr][h] = 0.f; pk[rr][h] = 0.f; }
#pragma unroll
    for (int j = 0; j < 8; j++) {
        int col = wn * 64 + j * 8 + 2 * tg;
        float4 q0 = *(const float4*)sq[col];
        float4 q1 = *(const float4*)sq[col + 1];
        float4 s0 = *(const float4*)sk[col];
        float4 s1 = *(const float4*)sk[col + 1];
#pragma unroll
        for (int i = 0; i < 2; i++)
#pragma unroll
            for (int half = 0; half < 2; half++) {
                float cA = half ? acc[i][j].z : acc[i][j].x;
                float cB = half ? acc[i][j].w : acc[i][j].y;
                int rr = i * 2 + half;
                pq[rr][0] += cA * q0.x + cB * q1.x;
                pq[rr][1] += cA * q0.y + cB * q1.y;
                pq[rr][2] += cA * q0.z + cB * q1.z;
                pq[rr][3] += cA * q0.w + cB * q1.w;
                pk[rr][0] += cA * s0.x + cB * s1.x;
                pk[rr][1] += cA * s0.y + cB * s1.y;
                pk[rr][2] += cA * s0.z + cB * s1.z;
                pk[rr][3] += cA * s0.w + cB * s1.w;
            }
    }
#pragma unroll
    for (int off = 1; off < 4; off <<= 1)
#pragma unroll
        for (int rr = 0; rr < 4; rr++)
#pragma unroll
            for (int h = 0; h < 4; h++) {
                pq[rr][h] += __shfl_xor_sync(0xffffffffu, pq[rr][h], off);
                pk[rr][h] += __shfl_xor_sync(0xffffffffu, pk[rr][h], off);
            }
    if (tg == 0) {
#pragma unroll
        for (int rr = 0; rr < 4; rr++) {
            int row = wm * 32 + (rr >> 1) * 16 + (rr & 1) * 8 + g;
#pragma unroll
            for (int h = 0; h < 4; h++) {
                atomicAdd(&s_aq[row][h], pq[rr][h]);
                atomicAdd(&s_ak[row][h], pk[rr][h]);
            }
        }
    }
    __syncthreads();
    if (t < 128) {
        int gr = row0 + t;
        if (gr < NN) {
            *(float4*)&g_aq[(gr * 8 + r) * 4] = *(const float4*)s_aq[t];
            *(float4*)&g_ak[(gr * 8 + r) * 4] = *(const float4*)s_ak[t];
        }
    }
}

// ---------------- fused per-node softmax + aggregate + bias + relu + LN ----------------
__global__ void k_agg_ln(const float* __restrict__ bias, const float* __restrict__ gam,
                         const float* __restrict__ bet, int layer) {
    int nid = blockIdx.x * 8 + (threadIdx.x >> 5);
    if (nid >= NN) return;
    int lane = threadIdx.x & 31;
    int h = lane >> 3;
    int j0 = g_rowptr[nid], j1 = g_rowptr[nid + 1];
    float4 num = make_float4(0.f, 0.f, 0.f, 0.f);
    float den = 0.f;
    const int aqbase = nid * 32 + h;
    for (int j = j0; j < j1; j++) {
        int p = g_csr[j];
        int r = p & 7;
        float a = g_aq[aqbase + r * 4] + g_ak[p * 4 + h];
        a = a > 0.f ? a : 0.2f * a;
        float ex = expf(a);
        den += ex;
        float4 xj = *(const float4*)&g_xw[p * 128 + lane * 4];
        num.x += ex * xj.x; num.y += ex * xj.y;
        num.z += ex * xj.z; num.w += ex * xj.w;
    }
    float inv = 1.f / (den + 1e-16f);
    float4 bb = *(const float4*)&bias[lane * 4];
    float4 v;
    v.x = fmaxf(num.x * inv + bb.x, 0.f);
    v.y = fmaxf(num.y * inv + bb.y, 0.f);
    v.z = fmaxf(num.z * inv + bb.z, 0.f);
    v.w = fmaxf(num.w * inv + bb.w, 0.f);
    float s = v.x + v.y + v.z + v.w;
#pragma unroll
    for (int o = 16; o >= 1; o >>= 1) s += __shfl_xor_sync(0xffffffffu, s, o);
    float mean = s * (1.f / 128.f);
    float dx = v.x - mean, dy = v.y - mean, dz = v.z - mean, dw = v.w - mean;
    float ss = dx * dx + dy * dy + dz * dz + dw * dw;
#pragma unroll
    for (int o = 16; o >= 1; o >>= 1) ss += __shfl_xor_sync(0xffffffffu, ss, o);
    float rs = rsqrtf(ss * (1.f / 128.f) + 1e-5f);
    float4 g4 = *(const float4*)&gam[lane * 4];
    float4 b4 = *(const float4*)&bet[lane * 4];
    float4 y;
    y.x = dx * rs * g4.x + b4.x;
    y.y = dy * rs * g4.y + b4.y;
    y.z = dz * rs * g4.z + b4.z;
    y.w = dw * rs * g4.w + b4.w;
    if (layer == 1) {
        *(float4*)&g_h1[nid * HID + lane * 4] = y;
    } else {
        float4 h1 = *(const float4*)&g_h1[nid * HID + lane * 4];
        y.x += h1.x; y.y += h1.y; y.z += h1.z; y.w += h1.w;
        *(float4*)&g_hsum[nid * HID + lane * 4] = y;
    }
}

// ---------------- decode GEMM 1 (tf32x3): gathered [E2,256] x [256,128] + GELU ----------------
__global__ void __launch_bounds__(256)
k_decode1(const int* __restrict__ edges, const float* __restrict__ mw1,
          const float* __restrict__ mb1) {
    __shared__ float As[128][20];
    __shared__ float Bs[16][136];
    __shared__ int sidx[128][2];
    __shared__ float sb[128];

    const int t = threadIdx.x;
    const int row0 = blockIdx.x * 128;
    const int lane = t & 31, wid = t >> 5;
    const int wm = wid & 3, wn = wid >> 2;
    const int g = lane >> 2, tg = lane & 3;

    if (t < 128) {
        int p = row0 + t;
        int2 pr = (p < EE2) ? ((const int2*)edges)[p] : make_int2(0, 0);
        sidx[t][0] = pr.x;
        sidx[t][1] = pr.y;
        sb[t] = mb1[t];
    }

    float4 acc[2][8];
#pragma unroll
    for (int i = 0; i < 2; i++)
#pragma unroll
        for (int j = 0; j < 8; j++) acc[i][j] = make_float4(0.f, 0.f, 0.f, 0.f);

    const int lrow = t >> 1;
    const int lkk = (t & 1) * 8;
    const int bkk = t >> 4;
    const int bcol = (t & 15) * 8;
    __syncthreads();
    const int node0 = sidx[lrow][0];
    const int node1 = sidx[lrow][1];

    for (int k0 = 0; k0 < 256; k0 += 16) {
        int node = (k0 < 128) ? node0 : node1;
        int colbase = (k0 & 127) + lkk;
        float4 v0 = *(const float4*)&g_hsum[node * 128 + colbase];
        float4 v1 = *(const float4*)&g_hsum[node * 128 + colbase + 4];
        float4 b0 = *(const float4*)&mw1[(k0 + bkk) * 128 + bcol];
        float4 b1 = *(const float4*)&mw1[(k0 + bkk) * 128 + bcol + 4];
        __syncthreads();
        *(float4*)&As[lrow][lkk] = v0;
        *(float4*)&As[lrow][lkk + 4] = v1;
        *(float4*)&Bs[bkk][bcol] = b0;
        *(float4*)&Bs[bkk][bcol + 4] = b1;
        __syncthreads();
#pragma unroll
        for (int ks = 0; ks < 16; ks += 8) {
            uint32_t ahi[2][4], alo[2][4];
#pragma unroll
            for (int i = 0; i < 2; i++) {
                int m0 = wm * 32 + i * 16;
                tf_split(As[m0 + g][ks + tg],         ahi[i][0], alo[i][0]);
                tf_split(As[m0 + g + 8][ks + tg],     ahi[i][1], alo[i][1]);
                tf_split(As[m0 + g][ks + tg + 4],     ahi[i][2], alo[i][2]);
                tf_split(As[m0 + g + 8][ks + tg + 4], ahi[i][3], alo[i][3]);
            }
            uint32_t bhi[8][2], blo[8][2];
#pragma unroll
            for (int j = 0; j < 8; j++) {
                int n0 = wn * 64 + j * 8;
                tf_split(Bs[ks + tg][n0 + g],     bhi[j][0], blo[j][0]);
                tf_split(Bs[ks + tg + 4][n0 + g], bhi[j][1], blo[j][1]);
            }
#pragma unroll
            for (int i = 0; i < 2; i++)
#pragma unroll
                for (int j = 0; j < 8; j++) {
                    mma_tf32(acc[i][j], ahi[i], blo[j]);
                    mma_tf32(acc[i][j], alo[i], bhi[j]);
                    mma_tf32(acc[i][j], ahi[i], bhi[j]);
                }
        }
    }

#pragma unroll
    for (int i = 0; i < 2; i++)
#pragma unroll
        for (int half = 0; half < 2; half++) {
            int p = row0 + wm * 32 + i * 16 + half * 8 + g;
            if (p >= EE2) continue;
            float* dst = &g_z[p * 128 + wn * 64 + 2 * tg];
#pragma unroll
            for (int j = 0; j < 8; j++) {
                int col = wn * 64 + j * 8 + 2 * tg;
                float vA = (half ? acc[i][j].z : acc[i][j].x) + sb[col];
                float vB = (half ? acc[i][j].w : acc[i][j].y) + sb[col + 1];
                vA = 0.5f * vA * (1.f + erff(vA * 0.70710678118654752f));
                vB = 0.5f * vB * (1.f + erff(vB * 0.70710678118654752f));
                *(float2*)(dst + j * 8) = make_float2(vA, vB);
            }
        }
}

// ---------------- decode GEMM 2: [E2,128] x [128,8] (warp per pair) ----------------
__global__ void k_decode2(const float* __restrict__ mw2, const float* __restrict__ mb2,
                          float* __restrict__ out) {
    __shared__ float sw[HID * NCLS];
    __shared__ float sb[NCLS];
    const int t = threadIdx.x;
    for (int l = t; l < HID * NCLS; l += 256) sw[l] = mw2[l];
    if (t < NCLS) sb[t] = mb2[t];
    __syncthreads();
    int p = blockIdx.x * 8 + (t >> 5);
    int lane = t & 31;
    float4 z = *(const float4*)&g_z[p * HID + lane * 4];
    const float* w = sw + lane * 4 * NCLS;
    float acc[NCLS];
#pragma unroll
    for (int c = 0; c < NCLS; c++)
        acc[c] = z.x * w[c] + z.y * w[NCLS + c] + z.z * w[2 * NCLS + c] + z.w * w[3 * NCLS + c];
#pragma unroll
    for (int o = 16; o >= 1; o >>= 1)
#pragma unroll
        for (int c = 0; c < NCLS; c++) acc[c] += __shfl_xor_sync(0xffffffffu, acc[c], o);
    if (lane < NCLS) out[p * NCLS + lane] = acc[lane] + sb[lane];
}

// ---------------- launch ----------------
extern "C" void kernel_launch(void* const* d_in, const int* in_sizes, int n_in,
                              void* d_out, int out_size) {
    const float* x     = (const float*)d_in[0];
    const int*   ei    = (const int*)d_in[1];
    const int*   et    = (const int*)d_in[2];
    const int*   edges = (const int*)d_in[3];
    const float* w1 = (const float*)d_in[4];
    const float* q1 = (const float*)d_in[5];
    const float* k1 = (const float*)d_in[6];
    const float* b1 = (const float*)d_in[7];
    const float* w2 = (const float*)d_in[8];
    const float* q2 = (const float*)d_in[9];
    const float* k2 = (const float*)d_in[10];
    const float* b2 = (const float*)d_in[11];
    const float* ln1g = (const float*)d_in[12];
    const float* ln1b = (const float*)d_in[13];
    const float* ln2g = (const float*)d_in[14];
    const float* ln2b = (const float*)d_in[15];
    const float* mw1 = (const float*)d_in[16];
    const float* mb1 = (const float*)d_in[17];
    const float* mw2 = (const float*)d_in[18];
    const float* mb2 = (const float*)d_in[19];
    float* out = (float*)d_out;

    k_zero<<<(NN + 255) / 256, 256>>>();
    k_hist<<<(EE + 255) / 256, 256>>>(ei);
    k_scan<<<1, 1024>>>();
    k_fill<<<(EE + 255) / 256, 256>>>(ei, et);

    const dim3 gXW((NN + 127) / 128, RR);
    const int gAgg = (NN + 7) / 8;

    k_gemm_fused<<<gXW, 256>>>(x, w1, q1, k1, 0);
    k_agg_ln<<<gAgg, 256>>>(b1, ln1g, ln1b, 1);

    k_gemm_fused<<<gXW, 256>>>(x, w2, q2, k2, 1);
    k_agg_ln<<<gAgg, 256>>>(b2, ln2g, ln2b, 2);

    k_decode1<<<(EE2 + 127) / 128, 256>>>(edges, mw1, mb1);
    k_decode2<<<EE2 / 8, 256>>>(mw2, mb2, out);
}

// round 4
// speedup vs baseline: 2.7977x; 1.2219x over previous
#include <cuda_runtime.h>
#include <cuda_bf16.h>
#include <math.h>
#include <stdint.h>

#define NN   50000
#define HID  128
#define RR   8
#define EE   640000
#define EE2  200000
#define NCLS 8

// ---------------- scratch (device globals; allocation-free) ----------------
__device__ float g_xw[NN * RR * HID];
__device__ float g_aq[NN * RR * 4];
__device__ float g_ak[NN * RR * 4];
__device__ float g_h1[NN * HID];
__device__ float g_z[EE2 * HID];
__device__ __nv_bfloat16 g_xhi[NN * HID],  g_xlo[NN * HID];    // layer1 A planes
__device__ __nv_bfloat16 g_h1hi[NN * HID], g_h1lo[NN * HID];   // layer2 A planes
__device__ __nv_bfloat16 g_hshi[NN * HID], g_hslo[NN * HID];   // decode A planes
__device__ __nv_bfloat16 g_wthi[RR * HID * HID], g_wtlo[RR * HID * HID]; // [r][n][k]
__device__ __nv_bfloat16 g_m1thi[HID * 2 * HID], g_m1tlo[HID * 2 * HID]; // [n][k=256]
__device__ int g_deg[NN], g_rowptr[NN + 1], g_cursor[NN], g_csr[EE];

// ---------------- helpers ----------------
__device__ __forceinline__ void bsplit(float v, __nv_bfloat16& hi, __nv_bfloat16& lo) {
    hi = __float2bfloat16(v);
    lo = __float2bfloat16(v - __bfloat162float(hi));
}
__device__ __forceinline__ void mma_bf16(float4& d, const uint32_t* a, const uint32_t* b) {
    asm volatile(
        "mma.sync.aligned.m16n8k16.row.col.f32.bf16.bf16.f32 "
        "{%0,%1,%2,%3}, {%4,%5,%6,%7}, {%8,%9}, {%0,%1,%2,%3};"
        : "+f"(d.x), "+f"(d.y), "+f"(d.z), "+f"(d.w)
        : "r"(a[0]), "r"(a[1]), "r"(a[2]), "r"(a[3]), "r"(b[0]), "r"(b[1]));
}
#define U32AT(arr, r_, c_) (*(const uint32_t*)&(arr)[r_][c_])

// ---------------- CSR build ----------------
__global__ void k_zero() {
    int i = blockIdx.x * blockDim.x + threadIdx.x;
    if (i < NN) g_deg[i] = 0;
}
__global__ void k_hist(const int* __restrict__ ei) {
    int e = blockIdx.x * blockDim.x + threadIdx.x;
    if (e < EE) atomicAdd(&g_deg[ei[EE + e]], 1);
}
__global__ void k_scan() {
    __shared__ int sp[1024];
    const int t = threadIdx.x;
    const int chunk = (NN + 1023) / 1024;
    int start = t * chunk, end = min(start + chunk, NN);
    int s = 0;
    for (int i = start; i < end; i++) s += g_deg[i];
    sp[t] = s;
    __syncthreads();
    for (int off = 1; off < 1024; off <<= 1) {
        int v = (t >= off) ? sp[t - off] : 0;
        __syncthreads();
        sp[t] += v;
        __syncthreads();
    }
    int run = (t == 0) ? 0 : sp[t - 1];
    for (int i = start; i < end; i++) {
        g_rowptr[i] = run;
        g_cursor[i] = run;
        run += g_deg[i];
    }
    if (t == 1023) g_rowptr[NN] = run;
}
__global__ void k_fill(const int* __restrict__ ei, const int* __restrict__ et) {
    int e = blockIdx.x * blockDim.x + threadIdx.x;
    if (e >= EE) return;
    int dst = ei[EE + e];
    int pos = atomicAdd(&g_cursor[dst], 1);
    g_csr[pos] = ei[e] * 8 + et[e];
}

// ---------------- split prep kernels ----------------
__global__ void k_split_x(const float* __restrict__ x) {
    int i = blockIdx.x * blockDim.x + threadIdx.x;
    if (i * 4 >= NN * HID) return;
    float4 v = *(const float4*)&x[i * 4];
    union { __nv_bfloat16 b[4]; uint2 u; } ph, pl;
    bsplit(v.x, ph.b[0], pl.b[0]); bsplit(v.y, ph.b[1], pl.b[1]);
    bsplit(v.z, ph.b[2], pl.b[2]); bsplit(v.w, ph.b[3], pl.b[3]);
    *(uint2*)&g_xhi[i * 4] = ph.u;
    *(uint2*)&g_xlo[i * 4] = pl.u;
}
__global__ void k_split_w(const float* __restrict__ W) {  // W[r][k][n] -> planes [r][n][k]
    int id = blockIdx.x * blockDim.x + threadIdx.x;
    if (id >= RR * HID * HID) return;
    int k = id & 127, n = (id >> 7) & 127, r = id >> 14;
    float v = W[r * 16384 + k * 128 + n];
    bsplit(v, g_wthi[id], g_wtlo[id]);
}
__global__ void k_split_m1(const float* __restrict__ mw1) {  // mw1[k=256][n=128] -> [n][k]
    int id = blockIdx.x * blockDim.x + threadIdx.x;
    if (id >= HID * 2 * HID) return;
    int k = id & 255, n = id >> 8;
    float v = mw1[k * 128 + n];
    bsplit(v, g_m1thi[id], g_m1tlo[id]);
}

// ---------------- fused bf16x3 GEMM: xw = A @ W[r], plus aq/ak epilogue ----------------
// 128x128 tile, 8 warps (4m x 2n), warp tile m32 x n64, mma m16n8k16 bf16.
__global__ void __launch_bounds__(256)
k_gemm_fused(const float* __restrict__ qm, const float* __restrict__ km, int use_h1) {
    __shared__ __nv_bfloat16 Ah[128][40], Al[128][40], Bh[128][40], Bl[128][40];
    __shared__ float sq[128][4], sk[128][4], s_aq[128][4], s_ak[128][4];

    const int r = blockIdx.y;
    const int row0 = blockIdx.x * 128;
    const __nv_bfloat16* Ahi = use_h1 ? g_h1hi : g_xhi;
    const __nv_bfloat16* Alo = use_h1 ? g_h1lo : g_xlo;
    const __nv_bfloat16* Bhi = g_wthi + r * HID * HID;
    const __nv_bfloat16* Blo = g_wtlo + r * HID * HID;
    const int t = threadIdx.x;
    const int lane = t & 31, wid = t >> 5;
    const int wm = wid & 3, wn = wid >> 2;
    const int g = lane >> 2, tg = lane & 3;

    if (t < 128) {
        *(float4*)sq[t] = *(const float4*)&qm[t * 4];
        *(float4*)sk[t] = *(const float4*)&km[t * 4];
        *(float4*)s_aq[t] = make_float4(0.f, 0.f, 0.f, 0.f);
        *(float4*)s_ak[t] = make_float4(0.f, 0.f, 0.f, 0.f);
    }

    float4 acc[2][8];
#pragma unroll
    for (int i = 0; i < 2; i++)
#pragma unroll
        for (int j = 0; j < 8; j++) acc[i][j] = make_float4(0.f, 0.f, 0.f, 0.f);

    const int lr = t >> 1;
    const int lc = (t & 1) * 16;
    const int garow = row0 + lr;
    const bool arow_ok = garow < NN;

    for (int k0 = 0; k0 < 128; k0 += 32) {
        uint4 ah0 = {0,0,0,0}, ah1 = {0,0,0,0}, al0 = {0,0,0,0}, al1 = {0,0,0,0};
        if (arow_ok) {
            ah0 = *(const uint4*)&Ahi[garow * 128 + k0 + lc];
            ah1 = *(const uint4*)&Ahi[garow * 128 + k0 + lc + 8];
            al0 = *(const uint4*)&Alo[garow * 128 + k0 + lc];
            al1 = *(const uint4*)&Alo[garow * 128 + k0 + lc + 8];
        }
        uint4 bh0 = *(const uint4*)&Bhi[lr * 128 + k0 + lc];
        uint4 bh1 = *(const uint4*)&Bhi[lr * 128 + k0 + lc + 8];
        uint4 bl0 = *(const uint4*)&Blo[lr * 128 + k0 + lc];
        uint4 bl1 = *(const uint4*)&Blo[lr * 128 + k0 + lc + 8];
        __syncthreads();
        *(uint4*)&Ah[lr][lc] = ah0; *(uint4*)&Ah[lr][lc + 8] = ah1;
        *(uint4*)&Al[lr][lc] = al0; *(uint4*)&Al[lr][lc + 8] = al1;
        *(uint4*)&Bh[lr][lc] = bh0; *(uint4*)&Bh[lr][lc + 8] = bh1;
        *(uint4*)&Bl[lr][lc] = bl0; *(uint4*)&Bl[lr][lc + 8] = bl1;
        __syncthreads();
#pragma unroll
        for (int ks = 0; ks < 32; ks += 16) {
            uint32_t ahh[2][4], all[2][4];
#pragma unroll
            for (int i = 0; i < 2; i++) {
                int m0 = wm * 32 + i * 16;
                ahh[i][0] = U32AT(Ah, m0 + g,     ks + 2 * tg);
                ahh[i][1] = U32AT(Ah, m0 + g + 8, ks + 2 * tg);
                ahh[i][2] = U32AT(Ah, m0 + g,     ks + 8 + 2 * tg);
                ahh[i][3] = U32AT(Ah, m0 + g + 8, ks + 8 + 2 * tg);
                all[i][0] = U32AT(Al, m0 + g,     ks + 2 * tg);
                all[i][1] = U32AT(Al, m0 + g + 8, ks + 2 * tg);
                all[i][2] = U32AT(Al, m0 + g,     ks + 8 + 2 * tg);
                all[i][3] = U32AT(Al, m0 + g + 8, ks + 8 + 2 * tg);
            }
            uint32_t bhh[8][2], bll[8][2];
#pragma unroll
            for (int j = 0; j < 8; j++) {
                int n = wn * 64 + j * 8 + g;
                bhh[j][0] = U32AT(Bh, n, ks + 2 * tg);
                bhh[j][1] = U32AT(Bh, n, ks + 8 + 2 * tg);
                bll[j][0] = U32AT(Bl, n, ks + 2 * tg);
                bll[j][1] = U32AT(Bl, n, ks + 8 + 2 * tg);
            }
#pragma unroll
            for (int i = 0; i < 2; i++)
#pragma unroll
                for (int j = 0; j < 8; j++) {
                    mma_bf16(acc[i][j], ahh[i], bll[j]);
                    mma_bf16(acc[i][j], all[i], bhh[j]);
                    mma_bf16(acc[i][j], ahh[i], bhh[j]);
                }
        }
    }

    // ---- store xw ----
#pragma unroll
    for (int i = 0; i < 2; i++)
#pragma unroll
        for (int half = 0; half < 2; half++) {
            int gr = row0 + wm * 32 + i * 16 + half * 8 + g;
            if (gr < NN) {
                float* dst = &g_xw[(gr * 8 + r) * 128 + wn * 64 + 2 * tg];
#pragma unroll
                for (int j = 0; j < 8; j++) {
                    float2 v = half ? make_float2(acc[i][j].z, acc[i][j].w)
                                    : make_float2(acc[i][j].x, acc[i][j].y);
                    *(float2*)(dst + j * 8) = v;
                }
            }
        }

    // ---- aq/ak epilogue ----
    float pq[4][4], pk[4][4];
#pragma unroll
    for (int rr = 0; rr < 4; rr++)
#pragma unroll
        for (int h = 0; h < 4; h++) { pq[rr][h] = 0.f; pk[rr][h] = 0.f; }
#pragma unroll
    for (int j = 0; j < 8; j++) {
        int col = wn * 64 + j * 8 + 2 * tg;
        float4 q0 = *(const float4*)sq[col];
        float4 q1 = *(const float4*)sq[col + 1];
        float4 s0 = *(const float4*)sk[col];
        float4 s1 = *(const float4*)sk[col + 1];
#pragma unroll
        for (int i = 0; i < 2; i++)
#pragma unroll
            for (int half = 0; half < 2; half++) {
                float cA = half ? acc[i][j].z : acc[i][j].x;
                float cB = half ? acc[i][j].w : acc[i][j].y;
                int rr = i * 2 + half;
                pq[rr][0] += cA * q0.x + cB * q1.x;
                pq[rr][1] += cA * q0.y + cB * q1.y;
                pq[rr][2] += cA * q0.z + cB * q1.z;
                pq[rr][3] += cA * q0.w + cB * q1.w;
                pk[rr][0] += cA * s0.x + cB * s1.x;
                pk[rr][1] += cA * s0.y + cB * s1.y;
                pk[rr][2] += cA * s0.z + cB * s1.z;
                pk[rr][3] += cA * s0.w + cB * s1.w;
            }
    }
#pragma unroll
    for (int off = 1; off < 4; off <<= 1)
#pragma unroll
        for (int rr = 0; rr < 4; rr++)
#pragma unroll
            for (int h = 0; h < 4; h++) {
                pq[rr][h] += __shfl_xor_sync(0xffffffffu, pq[rr][h], off);
                pk[rr][h] += __shfl_xor_sync(0xffffffffu, pk[rr][h], off);
            }
    if (tg == 0) {
#pragma unroll
        for (int rr = 0; rr < 4; rr++) {
            int row = wm * 32 + (rr >> 1) * 16 + (rr & 1) * 8 + g;
#pragma unroll
            for (int h = 0; h < 4; h++) {
                atomicAdd(&s_aq[row][h], pq[rr][h]);
                atomicAdd(&s_ak[row][h], pk[rr][h]);
            }
        }
    }
    __syncthreads();
    if (t < 128) {
        int gr = row0 + t;
        if (gr < NN) {
            *(float4*)&g_aq[(gr * 8 + r) * 4] = *(const float4*)s_aq[t];
            *(float4*)&g_ak[(gr * 8 + r) * 4] = *(const float4*)s_ak[t];
        }
    }
}

// ---------------- fused per-node softmax + aggregate + bias + relu + LN ----------------
// warp per node; chunked csr with shfl broadcast for MLP.
__global__ void k_agg_ln(const float* __restrict__ bias, const float* __restrict__ gam,
                         const float* __restrict__ bet, int layer) {
    int nid = blockIdx.x * 8 + (threadIdx.x >> 5);
    if (nid >= NN) return;
    int lane = threadIdx.x & 31;
    int h = lane >> 3;
    int e8 = lane & 7;
    int j0 = g_rowptr[nid], j1 = g_rowptr[nid + 1];
    float4 num = make_float4(0.f, 0.f, 0.f, 0.f);
    float den = 0.f;
    for (int base = j0; base < j1; base += 8) {
        int idx = base + e8;
        int p = 0;
        float ex = 0.f;
        if (idx < j1) {
            p = g_csr[idx];
            int rr = p & 7;
            float a = g_aq[nid * 32 + rr * 4 + h] + g_ak[p * 4 + h];
            a = a > 0.f ? a : 0.2f * a;
            ex = __expf(a);
        }
        den += ex;
        int cnt = min(8, j1 - base);
        for (int e = 0; e < cnt; e++) {
            float exe = __shfl_sync(0xffffffffu, ex, (lane & 24) + e);
            int pe = __shfl_sync(0xffffffffu, p, e);
            float4 xj = *(const float4*)&g_xw[pe * 128 + lane * 4];
            num.x += exe * xj.x; num.y += exe * xj.y;
            num.z += exe * xj.z; num.w += exe * xj.w;
        }
    }
    den += __shfl_xor_sync(0xffffffffu, den, 1);
    den += __shfl_xor_sync(0xffffffffu, den, 2);
    den += __shfl_xor_sync(0xffffffffu, den, 4);
    float inv = 1.f / (den + 1e-16f);
    float4 bb = *(const float4*)&bias[lane * 4];
    float4 v;
    v.x = fmaxf(num.x * inv + bb.x, 0.f);
    v.y = fmaxf(num.y * inv + bb.y, 0.f);
    v.z = fmaxf(num.z * inv + bb.z, 0.f);
    v.w = fmaxf(num.w * inv + bb.w, 0.f);
    float s = v.x + v.y + v.z + v.w;
#pragma unroll
    for (int o = 16; o >= 1; o >>= 1) s += __shfl_xor_sync(0xffffffffu, s, o);
    float mean = s * (1.f / 128.f);
    float dx = v.x - mean, dy = v.y - mean, dz = v.z - mean, dw = v.w - mean;
    float ss = dx * dx + dy * dy + dz * dz + dw * dw;
#pragma unroll
    for (int o = 16; o >= 1; o >>= 1) ss += __shfl_xor_sync(0xffffffffu, ss, o);
    float rs = rsqrtf(ss * (1.f / 128.f) + 1e-5f);
    float4 g4 = *(const float4*)&gam[lane * 4];
    float4 b4 = *(const float4*)&bet[lane * 4];
    float4 y;
    y.x = dx * rs * g4.x + b4.x;
    y.y = dy * rs * g4.y + b4.y;
    y.z = dz * rs * g4.z + b4.z;
    y.w = dw * rs * g4.w + b4.w;
    union { __nv_bfloat16 b[4]; uint2 u; } ph, pl;
    if (layer == 1) {
        *(float4*)&g_h1[nid * HID + lane * 4] = y;
        bsplit(y.x, ph.b[0], pl.b[0]); bsplit(y.y, ph.b[1], pl.b[1]);
        bsplit(y.z, ph.b[2], pl.b[2]); bsplit(y.w, ph.b[3], pl.b[3]);
        *(uint2*)&g_h1hi[nid * HID + lane * 4] = ph.u;
        *(uint2*)&g_h1lo[nid * HID + lane * 4] = pl.u;
    } else {
        float4 h1 = *(const float4*)&g_h1[nid * HID + lane * 4];
        y.x += h1.x; y.y += h1.y; y.z += h1.z; y.w += h1.w;
        bsplit(y.x, ph.b[0], pl.b[0]); bsplit(y.y, ph.b[1], pl.b[1]);
        bsplit(y.z, ph.b[2], pl.b[2]); bsplit(y.w, ph.b[3], pl.b[3]);
        *(uint2*)&g_hshi[nid * HID + lane * 4] = ph.u;
        *(uint2*)&g_hslo[nid * HID + lane * 4] = pl.u;
    }
}

// ---------------- decode GEMM 1 (bf16x3): gathered [E2,256] x [256,128] + GELU ----------------
__global__ void __launch_bounds__(256)
k_decode1(const int* __restrict__ edges, const float* __restrict__ mb1) {
    __shared__ __nv_bfloat16 Ah[128][40], Al[128][40], Bh[128][40], Bl[128][40];
    __shared__ int sidx[128][2];
    __shared__ float sb[128];

    const int t = threadIdx.x;
    const int row0 = blockIdx.x * 128;
    const int lane = t & 31, wid = t >> 5;
    const int wm = wid & 3, wn = wid >> 2;
    const int g = lane >> 2, tg = lane & 3;

    if (t < 128) {
        int p = row0 + t;
        int2 pr = (p < EE2) ? ((const int2*)edges)[p] : make_int2(0, 0);
        sidx[t][0] = pr.x;
        sidx[t][1] = pr.y;
        sb[t] = mb1[t];
    }

    float4 acc[2][8];
#pragma unroll
    for (int i = 0; i < 2; i++)
#pragma unroll
        for (int j = 0; j < 8; j++) acc[i][j] = make_float4(0.f, 0.f, 0.f, 0.f);

    const int lr = t >> 1;
    const int lc = (t & 1) * 16;
    __syncthreads();
    const int node0 = sidx[lr][0];
    const int node1 = sidx[lr][1];

    for (int c = 0; c < 8; c++) {
        int node = (c < 4) ? node0 : node1;
        int colbase = (c & 3) * 32 + lc;
        uint4 ah0 = *(const uint4*)&g_hshi[node * 128 + colbase];
        uint4 ah1 = *(const uint4*)&g_hshi[node * 128 + colbase + 8];
        uint4 al0 = *(const uint4*)&g_hslo[node * 128 + colbase];
        uint4 al1 = *(const uint4*)&g_hslo[node * 128 + colbase + 8];
        uint4 bh0 = *(const uint4*)&g_m1thi[lr * 256 + c * 32 + lc];
        uint4 bh1 = *(const uint4*)&g_m1thi[lr * 256 + c * 32 + lc + 8];
        uint4 bl0 = *(const uint4*)&g_m1tlo[lr * 256 + c * 32 + lc];
        uint4 bl1 = *(const uint4*)&g_m1tlo[lr * 256 + c * 32 + lc + 8];
        __syncthreads();
        *(uint4*)&Ah[lr][lc] = ah0; *(uint4*)&Ah[lr][lc + 8] = ah1;
        *(uint4*)&Al[lr][lc] = al0; *(uint4*)&Al[lr][lc + 8] = al1;
        *(uint4*)&Bh[lr][lc] = bh0; *(uint4*)&Bh[lr][lc + 8] = bh1;
        *(uint4*)&Bl[lr][lc] = bl0; *(uint4*)&Bl[lr][lc + 8] = bl1;
        __syncthreads();
#pragma unroll
        for (int ks = 0; ks < 32; ks += 16) {
            uint32_t ahh[2][4], all[2][4];
#pragma unroll
            for (int i = 0; i < 2; i++) {
                int m0 = wm * 32 + i * 16;
                ahh[i][0] = U32AT(Ah, m0 + g,     ks + 2 * tg);
                ahh[i][1] = U32AT(Ah, m0 + g + 8, ks + 2 * tg);
                ahh[i][2] = U32AT(Ah, m0 + g,     ks + 8 + 2 * tg);
                ahh[i][3] = U32AT(Ah, m0 + g + 8, ks + 8 + 2 * tg);
                all[i][0] = U32AT(Al, m0 + g,     ks + 2 * tg);
                all[i][1] = U32AT(Al, m0 + g + 8, ks + 2 * tg);
                all[i][2] = U32AT(Al, m0 + g,     ks + 8 + 2 * tg);
                all[i][3] = U32AT(Al, m0 + g + 8, ks + 8 + 2 * tg);
            }
            uint32_t bhh[8][2], bll[8][2];
#pragma unroll
            for (int j = 0; j < 8; j++) {
                int n = wn * 64 + j * 8 + g;
                bhh[j][0] = U32AT(Bh, n, ks + 2 * tg);
                bhh[j][1] = U32AT(Bh, n, ks + 8 + 2 * tg);
                bll[j][0] = U32AT(Bl, n, ks + 2 * tg);
                bll[j][1] = U32AT(Bl, n, ks + 8 + 2 * tg);
            }
#pragma unroll
            for (int i = 0; i < 2; i++)
#pragma unroll
                for (int j = 0; j < 8; j++) {
                    mma_bf16(acc[i][j], ahh[i], bll[j]);
                    mma_bf16(acc[i][j], all[i], bhh[j]);
                    mma_bf16(acc[i][j], ahh[i], bhh[j]);
                }
        }
    }

#pragma unroll
    for (int i = 0; i < 2; i++)
#pragma unroll
        for (int half = 0; half < 2; half++) {
            int p = row0 + wm * 32 + i * 16 + half * 8 + g;
            if (p >= EE2) continue;
            float* dst = &g_z[p * 128 + wn * 64 + 2 * tg];
#pragma unroll
            for (int j = 0; j < 8; j++) {
                int col = wn * 64 + j * 8 + 2 * tg;
                float vA = (half ? acc[i][j].z : acc[i][j].x) + sb[col];
                float vB = (half ? acc[i][j].w : acc[i][j].y) + sb[col + 1];
                vA = 0.5f * vA * (1.f + erff(vA * 0.70710678118654752f));
                vB = 0.5f * vB * (1.f + erff(vB * 0.70710678118654752f));
                *(float2*)(dst + j * 8) = make_float2(vA, vB);
            }
        }
}

// ---------------- decode GEMM 2: [E2,128] x [128,8] (warp per pair) ----------------
__global__ void k_decode2(const float* __restrict__ mw2, const float* __restrict__ mb2,
                          float* __restrict__ out) {
    __shared__ float sw[HID * NCLS];
    __shared__ float sb[NCLS];
    const int t = threadIdx.x;
    for (int l = t; l < HID * NCLS; l += 256) sw[l] = mw2[l];
    if (t < NCLS) sb[t] = mb2[t];
    __syncthreads();
    int p = blockIdx.x * 8 + (t >> 5);
    int lane = t & 31;
    float4 z = *(const float4*)&g_z[p * HID + lane * 4];
    const float* w = sw + lane * 4 * NCLS;
    float acc[NCLS];
#pragma unroll
    for (int c = 0; c < NCLS; c++)
        acc[c] = z.x * w[c] + z.y * w[NCLS + c] + z.z * w[2 * NCLS + c] + z.w * w[3 * NCLS + c];
#pragma unroll
    for (int o = 16; o >= 1; o >>= 1)
#pragma unroll
        for (int c = 0; c < NCLS; c++) acc[c] += __shfl_xor_sync(0xffffffffu, acc[c], o);
    if (lane < NCLS) out[p * NCLS + lane] = acc[lane] + sb[lane];
}

// ---------------- launch ----------------
extern "C" void kernel_launch(void* const* d_in, const int* in_sizes, int n_in,
                              void* d_out, int out_size) {
    const float* x     = (const float*)d_in[0];
    const int*   ei    = (const int*)d_in[1];
    const int*   et    = (const int*)d_in[2];
    const int*   edges = (const int*)d_in[3];
    const float* w1 = (const float*)d_in[4];
    const float* q1 = (const float*)d_in[5];
    const float* k1 = (const float*)d_in[6];
    const float* b1 = (const float*)d_in[7];
    const float* w2 = (const float*)d_in[8];
    const float* q2 = (const float*)d_in[9];
    const float* k2 = (const float*)d_in[10];
    const float* b2 = (const float*)d_in[11];
    const float* ln1g = (const float*)d_in[12];
    const float* ln1b = (const float*)d_in[13];
    const float* ln2g = (const float*)d_in[14];
    const float* ln2b = (const float*)d_in[15];
    const float* mw1 = (const float*)d_in[16];
    const float* mb1 = (const float*)d_in[17];
    const float* mw2 = (const float*)d_in[18];
    const float* mb2 = (const float*)d_in[19];
    float* out = (float*)d_out;

    k_zero<<<(NN + 255) / 256, 256>>>();
    k_hist<<<(EE + 255) / 256, 256>>>(ei);
    k_scan<<<1, 1024>>>();
    k_fill<<<(EE + 255) / 256, 256>>>(ei, et);

    k_split_x<<<(NN * HID / 4 + 255) / 256, 256>>>(x);
    k_split_w<<<(RR * HID * HID + 255) / 256, 256>>>(w1);

    const dim3 gXW((NN + 127) / 128, RR);
    const int gAgg = (NN + 7) / 8;

    k_gemm_fused<<<gXW, 256>>>(q1, k1, 0);
    k_agg_ln<<<gAgg, 256>>>(b1, ln1g, ln1b, 1);

    k_split_w<<<(RR * HID * HID + 255) / 256, 256>>>(w2);
    k_gemm_fused<<<gXW, 256>>>(q2, k2, 1);
    k_agg_ln<<<gAgg, 256>>>(b2, ln2g, ln2b, 2);

    k_split_m1<<<(HID * 2 * HID + 255) / 256, 256>>>(mw1);
    k_decode1<<<(EE2 + 127) / 128, 256>>>(edges, mb1);
    k_decode2<<<EE2 / 8, 256>>>(mw2, mb2, out);
}

// round 6
// speedup vs baseline: 2.9069x; 1.0390x over previous
#include <cuda_runtime.h>
#include <cuda_bf16.h>
#include <math.h>
#include <stdint.h>

#define NN   50000
#define HID  128
#define RR   8
#define EE   640000
#define EE2  200000
#define NCLS 8

// ---------------- scratch (device globals; allocation-free) ----------------
__device__ float g_xw[NN * RR * HID];
__device__ float g_aq[NN * RR * 4];
__device__ float g_ak[NN * RR * 4];
__device__ float g_h1[NN * HID];
__device__ float g_z[EE2 * HID];
__device__ __nv_bfloat16 g_xhi[NN * HID],  g_xlo[NN * HID];
__device__ __nv_bfloat16 g_h1hi[NN * HID], g_h1lo[NN * HID];
__device__ __nv_bfloat16 g_hshi[NN * HID], g_hslo[NN * HID];
__device__ __nv_bfloat16 g_wthi[RR * HID * HID], g_wtlo[RR * HID * HID]; // [r][n][k]
__device__ __nv_bfloat16 g_m1thi[HID * 2 * HID], g_m1tlo[HID * 2 * HID]; // [n][k=256]
__device__ int g_deg[NN], g_rowptr[NN + 1], g_cursor[NN], g_csr[EE];

// ---------------- helpers ----------------
__device__ __forceinline__ void bsplit(float v, __nv_bfloat16& hi, __nv_bfloat16& lo) {
    hi = __float2bfloat16(v);
    lo = __float2bfloat16(v - __bfloat162float(hi));
}
__device__ __forceinline__ void mma_bf16(float4& d, const uint32_t* a, const uint32_t* b) {
    asm volatile(
        "mma.sync.aligned.m16n8k16.row.col.f32.bf16.bf16.f32 "
        "{%0,%1,%2,%3}, {%4,%5,%6,%7}, {%8,%9}, {%0,%1,%2,%3};"
        : "+f"(d.x), "+f"(d.y), "+f"(d.z), "+f"(d.w)
        : "r"(a[0]), "r"(a[1]), "r"(a[2]), "r"(a[3]), "r"(b[0]), "r"(b[1]));
}
__device__ __forceinline__ void ldm_x4(uint32_t* r, const void* p) {
    uint32_t addr = (uint32_t)__cvta_generic_to_shared(p);
    asm volatile("ldmatrix.sync.aligned.m8n8.x4.shared.b16 {%0,%1,%2,%3}, [%4];"
                 : "=r"(r[0]), "=r"(r[1]), "=r"(r[2]), "=r"(r[3]) : "r"(addr));
}

// ---------------- CSR build ----------------
__global__ void k_zero() {
    int i = blockIdx.x * blockDim.x + threadIdx.x;
    if (i < NN) g_deg[i] = 0;
}
__global__ void k_hist(const int* __restrict__ ei) {
    int e = blockIdx.x * blockDim.x + threadIdx.x;
    if (e < EE) atomicAdd(&g_deg[ei[EE + e]], 1);
}
__global__ void k_scan() {
    __shared__ int sp[1024];
    const int t = threadIdx.x;
    const int chunk = (NN + 1023) / 1024;
    int start = t * chunk, end = min(start + chunk, NN);
    int s = 0;
    for (int i = start; i < end; i++) s += g_deg[i];
    sp[t] = s;
    __syncthreads();
    for (int off = 1; off < 1024; off <<= 1) {
        int v = (t >= off) ? sp[t - off] : 0;
        __syncthreads();
        sp[t] += v;
        __syncthreads();
    }
    int run = (t == 0) ? 0 : sp[t - 1];
    for (int i = start; i < end; i++) {
        g_rowptr[i] = run;
        g_cursor[i] = run;
        run += g_deg[i];
    }
    if (t == 1023) g_rowptr[NN] = run;
}
__global__ void k_fill(const int* __restrict__ ei, const int* __restrict__ et) {
    int e = blockIdx.x * blockDim.x + threadIdx.x;
    if (e >= EE) return;
    int dst = ei[EE + e];
    int pos = atomicAdd(&g_cursor[dst], 1);
    g_csr[pos] = ei[e] * 8 + et[e];
}

// ---------------- split prep kernels ----------------
__global__ void k_split_x(const float* __restrict__ x) {
    int i = blockIdx.x * blockDim.x + threadIdx.x;
    if (i * 4 >= NN * HID) return;
    float4 v = *(const float4*)&x[i * 4];
    union { __nv_bfloat16 b[4]; uint2 u; } ph, pl;
    bsplit(v.x, ph.b[0], pl.b[0]); bsplit(v.y, ph.b[1], pl.b[1]);
    bsplit(v.z, ph.b[2], pl.b[2]); bsplit(v.w, ph.b[3], pl.b[3]);
    *(uint2*)&g_xhi[i * 4] = ph.u;
    *(uint2*)&g_xlo[i * 4] = pl.u;
}
__global__ void k_split_w(const float* __restrict__ W) {  // W[r][k][n] -> planes [r][n][k]
    int id = blockIdx.x * blockDim.x + threadIdx.x;
    if (id >= RR * HID * HID) return;
    int k = id & 127, n = (id >> 7) & 127, r = id >> 14;
    float v = W[r * 16384 + k * 128 + n];
    bsplit(v, g_wthi[id], g_wtlo[id]);
}
__global__ void k_split_m1(const float* __restrict__ mw1) {  // mw1[k=256][n=128] -> [n][k]
    int id = blockIdx.x * blockDim.x + threadIdx.x;
    if (id >= HID * 2 * HID) return;
    int k = id & 255, n = id >> 8;
    float v = mw1[k * 128 + n];
    bsplit(v, g_m1thi[id], g_m1tlo[id]);
}

// ---------------- fused bf16x3 GEMM (ldmatrix): xw = A @ W[r] + aq/ak epilogue ----------------
__global__ void __launch_bounds__(256)
k_gemm_fused(const float* __restrict__ qm, const float* __restrict__ km, int use_h1) {
    __shared__ __nv_bfloat16 Ah[128][40], Al[128][40], Bh[128][40], Bl[128][40];
    __shared__ float sq[128][4], sk[128][4], s_aq[128][4], s_ak[128][4];

    const int r = blockIdx.y;
    const int row0 = blockIdx.x * 128;
    const __nv_bfloat16* Ahi = use_h1 ? g_h1hi : g_xhi;
    const __nv_bfloat16* Alo = use_h1 ? g_h1lo : g_xlo;
    const __nv_bfloat16* Bhi = g_wthi + r * HID * HID;
    const __nv_bfloat16* Blo = g_wtlo + r * HID * HID;
    const int t = threadIdx.x;
    const int lane = t & 31, wid = t >> 5;
    const int wm = wid & 3, wn = wid >> 2;
    const int g = lane >> 2, tg = lane & 3;

    // ldmatrix per-lane offsets
    const int a_row = (lane & 15);
    const int a_col = ((lane >> 4) & 1) * 8;
    const int b_row = (lane & 7) + ((lane & 16) ? 8 : 0);
    const int b_col = (lane & 8) ? 8 : 0;

    if (t < 128) {
        *(float4*)sq[t] = *(const float4*)&qm[t * 4];
        *(float4*)sk[t] = *(const float4*)&km[t * 4];
        *(float4*)s_aq[t] = make_float4(0.f, 0.f, 0.f, 0.f);
        *(float4*)s_ak[t] = make_float4(0.f, 0.f, 0.f, 0.f);
    }

    float4 acc[2][8];
#pragma unroll
    for (int i = 0; i < 2; i++)
#pragma unroll
        for (int j = 0; j < 8; j++) acc[i][j] = make_float4(0.f, 0.f, 0.f, 0.f);

    const int lr = t >> 1;
    const int lc = (t & 1) * 16;
    const int garow = row0 + lr;
    const bool arow_ok = garow < NN;

    for (int k0 = 0; k0 < 128; k0 += 32) {
        uint4 ah0 = {0,0,0,0}, ah1 = {0,0,0,0}, al0 = {0,0,0,0}, al1 = {0,0,0,0};
        if (arow_ok) {
            ah0 = *(const uint4*)&Ahi[garow * 128 + k0 + lc];
            ah1 = *(const uint4*)&Ahi[garow * 128 + k0 + lc + 8];
            al0 = *(const uint4*)&Alo[garow * 128 + k0 + lc];
            al1 = *(const uint4*)&Alo[garow * 128 + k0 + lc + 8];
        }
        uint4 bh0 = *(const uint4*)&Bhi[lr * 128 + k0 + lc];
        uint4 bh1 = *(const uint4*)&Bhi[lr * 128 + k0 + lc + 8];
        uint4 bl0 = *(const uint4*)&Blo[lr * 128 + k0 + lc];
        uint4 bl1 = *(const uint4*)&Blo[lr * 128 + k0 + lc + 8];
        __syncthreads();
        *(uint4*)&Ah[lr][lc] = ah0; *(uint4*)&Ah[lr][lc + 8] = ah1;
        *(uint4*)&Al[lr][lc] = al0; *(uint4*)&Al[lr][lc + 8] = al1;
        *(uint4*)&Bh[lr][lc] = bh0; *(uint4*)&Bh[lr][lc + 8] = bh1;
        *(uint4*)&Bl[lr][lc] = bl0; *(uint4*)&Bl[lr][lc + 8] = bl1;
        __syncthreads();
#pragma unroll
        for (int ks = 0; ks < 32; ks += 16) {
            uint32_t ahh[2][4], all[2][4];
#pragma unroll
            for (int i = 0; i < 2; i++) {
                ldm_x4(ahh[i], &Ah[wm * 32 + i * 16 + a_row][ks + a_col]);
                ldm_x4(all[i], &Al[wm * 32 + i * 16 + a_row][ks + a_col]);
            }
            uint32_t bhh[8][2], bll[8][2];
#pragma unroll
            for (int jj = 0; jj < 4; jj++) {
                uint32_t rh[4], rl[4];
                ldm_x4(rh, &Bh[wn * 64 + jj * 16 + b_row][ks + b_col]);
                ldm_x4(rl, &Bl[wn * 64 + jj * 16 + b_row][ks + b_col]);
                bhh[2 * jj][0] = rh[0]; bhh[2 * jj][1] = rh[1];
                bhh[2 * jj + 1][0] = rh[2]; bhh[2 * jj + 1][1] = rh[3];
                bll[2 * jj][0] = rl[0]; bll[2 * jj][1] = rl[1];
                bll[2 * jj + 1][0] = rl[2]; bll[2 * jj + 1][1] = rl[3];
            }
#pragma unroll
            for (int i = 0; i < 2; i++)
#pragma unroll
                for (int j = 0; j < 8; j++) {
                    mma_bf16(acc[i][j], ahh[i], bll[j]);
                    mma_bf16(acc[i][j], all[i], bhh[j]);
                    mma_bf16(acc[i][j], ahh[i], bhh[j]);
                }
        }
    }

    // ---- store xw ----
#pragma unroll
    for (int i = 0; i < 2; i++)
#pragma unroll
        for (int half = 0; half < 2; half++) {
            int gr = row0 + wm * 32 + i * 16 + half * 8 + g;
            if (gr < NN) {
                float* dst = &g_xw[(gr * 8 + r) * 128 + wn * 64 + 2 * tg];
#pragma unroll
                for (int j = 0; j < 8; j++) {
                    float2 v = half ? make_float2(acc[i][j].z, acc[i][j].w)
                                    : make_float2(acc[i][j].x, acc[i][j].y);
                    *(float2*)(dst + j * 8) = v;
                }
            }
        }

    // ---- aq/ak epilogue ----
    float pq[4][4], pk[4][4];
#pragma unroll
    for (int rr = 0; rr < 4; rr++)
#pragma unroll
        for (int h = 0; h < 4; h++) { pq[rr][h] = 0.f; pk[rr][h] = 0.f; }
#pragma unroll
    for (int j = 0; j < 8; j++) {
        int col = wn * 64 + j * 8 + 2 * tg;
        float4 q0 = *(const float4*)sq[col];
        float4 q1 = *(const float4*)sq[col + 1];
        float4 s0 = *(const float4*)sk[col];
        float4 s1 = *(const float4*)sk[col + 1];
#pragma unroll
        for (int i = 0; i < 2; i++)
#pragma unroll
            for (int half = 0; half < 2; half++) {
                float cA = half ? acc[i][j].z : acc[i][j].x;
                float cB = half ? acc[i][j].w : acc[i][j].y;
                int rr = i * 2 + half;
                pq[rr][0] += cA * q0.x + cB * q1.x;
                pq[rr][1] += cA * q0.y + cB * q1.y;
                pq[rr][2] += cA * q0.z + cB * q1.z;
                pq[rr][3] += cA * q0.w + cB * q1.w;
                pk[rr][0] += cA * s0.x + cB * s1.x;
                pk[rr][1] += cA * s0.y + cB * s1.y;
                pk[rr][2] += cA * s0.z + cB * s1.z;
                pk[rr][3] += cA * s0.w + cB * s1.w;
            }
    }
#pragma unroll
    for (int off = 1; off < 4; off <<= 1)
#pragma unroll
        for (int rr = 0; rr < 4; rr++)
#pragma unroll
            for (int h = 0; h < 4; h++) {
                pq[rr][h] += __shfl_xor_sync(0xffffffffu, pq[rr][h], off);
                pk[rr][h] += __shfl_xor_sync(0xffffffffu, pk[rr][h], off);
            }
    if (tg == 0) {
#pragma unroll
        for (int rr = 0; rr < 4; rr++) {
            int row = wm * 32 + (rr >> 1) * 16 + (rr & 1) * 8 + g;
#pragma unroll
            for (int h = 0; h < 4; h++) {
                atomicAdd(&s_aq[row][h], pq[rr][h]);
                atomicAdd(&s_ak[row][h], pk[rr][h]);
            }
        }
    }
    __syncthreads();
    if (t < 128) {
        int gr = row0 + t;
        if (gr < NN) {
            *(float4*)&g_aq[(gr * 8 + t % 1 + r) * 4] = *(const float4*)s_aq[t];  // placeholder fixed below
        }
    }
    // (corrected write below)
    if (t < 128) {
        int gr = row0 + t;
        if (gr < NN) {
            *(float4*)&g_aq[(gr * 8 + r) * 4] = *(const float4*)s_aq[t];
            *(float4*)&g_ak[(gr * 8 + r) * 4] = *(const float4*)s_ak[t];
        }
    }
}

// ---------------- fused per-node softmax + aggregate + bias + relu + LN ----------------
__global__ void k_agg_ln(const float* __restrict__ bias, const float* __restrict__ gam,
                         const float* __restrict__ bet, int layer) {
    int nid = blockIdx.x * 8 + (threadIdx.x >> 5);
    if (nid >= NN) return;
    int lane = threadIdx.x & 31;
    int h = lane >> 3;
    int e8 = lane & 7;
    int j0 = g_rowptr[nid], j1 = g_rowptr[nid + 1];
    float4 num = make_float4(0.f, 0.f, 0.f, 0.f);
    float den = 0.f;
    for (int base = j0; base < j1; base += 8) {
        int idx = base + e8;
        int p = 0;
        float ex = 0.f;
        if (idx < j1) {
            p = g_csr[idx];
            int rr = p & 7;
            float a = g_aq[nid * 32 + rr * 4 + h] + g_ak[p * 4 + h];
            a = a > 0.f ? a : 0.2f * a;
            ex = __expf(a);
        }
        den += ex;
        int cnt = min(8, j1 - base);
        for (int e = 0; e < cnt; e++) {
            float exe = __shfl_sync(0xffffffffu, ex, (lane & 24) + e);
            int pe = __shfl_sync(0xffffffffu, p, e);
            float4 xj = *(const float4*)&g_xw[pe * 128 + lane * 4];
            num.x += exe * xj.x; num.y += exe * xj.y;
            num.z += exe * xj.z; num.w += exe * xj.w;
        }
    }
    den += __shfl_xor_sync(0xffffffffu, den, 1);
    den += __shfl_xor_sync(0xffffffffu, den, 2);
    den += __shfl_xor_sync(0xffffffffu, den, 4);
    float inv = 1.f / (den + 1e-16f);
    float4 bb = *(const float4*)&bias[lane * 4];
    float4 v;
    v.x = fmaxf(num.x * inv + bb.x, 0.f);
    v.y = fmaxf(num.y * inv + bb.y, 0.f);
    v.z = fmaxf(num.z * inv + bb.z, 0.f);
    v.w = fmaxf(num.w * inv + bb.w, 0.f);
    float s = v.x + v.y + v.z + v.w;
#pragma unroll
    for (int o = 16; o >= 1; o >>= 1) s += __shfl_xor_sync(0xffffffffu, s, o);
    float mean = s * (1.f / 128.f);
    float dx = v.x - mean, dy = v.y - mean, dz = v.z - mean, dw = v.w - mean;
    float ss = dx * dx + dy * dy + dz * dz + dw * dw;
#pragma unroll
    for (int o = 16; o >= 1; o >>= 1) ss += __shfl_xor_sync(0xffffffffu, ss, o);
    float rs = rsqrtf(ss * (1.f / 128.f) + 1e-5f);
    float4 g4 = *(const float4*)&gam[lane * 4];
    float4 b4 = *(const float4*)&bet[lane * 4];
    float4 y;
    y.x = dx * rs * g4.x + b4.x;
    y.y = dy * rs * g4.y + b4.y;
    y.z = dz * rs * g4.z + b4.z;
    y.w = dw * rs * g4.w + b4.w;
    union { __nv_bfloat16 b[4]; uint2 u; } ph, pl;
    if (layer == 1) {
        *(float4*)&g_h1[nid * HID + lane * 4] = y;
        bsplit(y.x, ph.b[0], pl.b[0]); bsplit(y.y, ph.b[1], pl.b[1]);
        bsplit(y.z, ph.b[2], pl.b[2]); bsplit(y.w, ph.b[3], pl.b[3]);
        *(uint2*)&g_h1hi[nid * HID + lane * 4] = ph.u;
        *(uint2*)&g_h1lo[nid * HID + lane * 4] = pl.u;
    } else {
        float4 h1 = *(const float4*)&g_h1[nid * HID + lane * 4];
        y.x += h1.x; y.y += h1.y; y.z += h1.z; y.w += h1.w;
        bsplit(y.x, ph.b[0], pl.b[0]); bsplit(y.y, ph.b[1], pl.b[1]);
        bsplit(y.z, ph.b[2], pl.b[2]); bsplit(y.w, ph.b[3], pl.b[3]);
        *(uint2*)&g_hshi[nid * HID + lane * 4] = ph.u;
        *(uint2*)&g_hslo[nid * HID + lane * 4] = pl.u;
    }
}

// ---------------- decode GEMM 1 (bf16x3 + ldmatrix): [E2,256] x [256,128] + GELU ----------------
__global__ void __launch_bounds__(256)
k_decode1(const int* __restrict__ edges, const float* __restrict__ mb1) {
    __shared__ __nv_bfloat16 Ah[128][40], Al[128][40], Bh[128][40], Bl[128][40];
    __shared__ int sidx[128][2];
    __shared__ float sb[128];

    const int t = threadIdx.x;
    const int row0 = blockIdx.x * 128;
    const int lane = t & 31, wid = t >> 5;
    const int wm = wid & 3, wn = wid >> 2;
    const int g = lane >> 2, tg = lane & 3;

    const int a_row = (lane & 15);
    const int a_col = ((lane >> 4) & 1) * 8;
    const int b_row = (lane & 7) + ((lane & 16) ? 8 : 0);
    const int b_col = (lane & 8) ? 8 : 0;

    if (t < 128) {
        int p = row0 + t;
        int2 pr = (p < EE2) ? ((const int2*)edges)[p] : make_int2(0, 0);
        sidx[t][0] = pr.x;
        sidx[t][1] = pr.y;
        sb[t] = mb1[t];
    }

    float4 acc[2][8];
#pragma unroll
    for (int i = 0; i < 2; i++)
#pragma unroll
        for (int j = 0; j < 8; j++) acc[i][j] = make_float4(0.f, 0.f, 0.f, 0.f);

    const int lr = t >> 1;
    const int lc = (t & 1) * 16;
    __syncthreads();
    const int node0 = sidx[lr][0];
    const int node1 = sidx[lr][1];

    for (int c = 0; c < 8; c++) {
        int node = (c < 4) ? node0 : node1;
        int colbase = (c & 3) * 32 + lc;
        uint4 ah0 = *(const uint4*)&g_hshi[node * 128 + colbase];
        uint4 ah1 = *(const uint4*)&g_hshi[node * 128 + colbase + 8];
        uint4 al0 = *(const uint4*)&g_hslo[node * 128 + colbase];
        uint4 al1 = *(const uint4*)&g_hslo[node * 128 + colbase + 8];
        uint4 bh0 = *(const uint4*)&g_m1thi[lr * 256 + c * 32 + lc];
        uint4 bh1 = *(const uint4*)&g_m1thi[lr * 256 + c * 32 + lc + 8];
        uint4 bl0 = *(const uint4*)&g_m1tlo[lr * 256 + c * 32 + lc];
        uint4 bl1 = *(const uint4*)&g_m1tlo[lr * 256 + c * 32 + lc + 8];
        __syncthreads();
        *(uint4*)&Ah[lr][lc] = ah0; *(uint4*)&Ah[lr][lc + 8] = ah1;
        *(uint4*)&Al[lr][lc] = al0; *(uint4*)&Al[lr][lc + 8] = al1;
        *(uint4*)&Bh[lr][lc] = bh0; *(uint4*)&Bh[lr][lc + 8] = bh1;
        *(uint4*)&Bl[lr][lc] = bl0; *(uint4*)&Bl[lr][lc + 8] = bl1;
        __syncthreads();
#pragma unroll
        for (int ks = 0; ks < 32; ks += 16) {
            uint32_t ahh[2][4], all[2][4];
#pragma unroll
            for (int i = 0; i < 2; i++) {
                ldm_x4(ahh[i], &Ah[wm * 32 + i * 16 + a_row][ks + a_col]);
                ldm_x4(all[i], &Al[wm * 32 + i * 16 + a_row][ks + a_col]);
            }
            uint32_t bhh[8][2], bll[8][2];
#pragma unroll
            for (int jj = 0; jj < 4; jj++) {
                uint32_t rh[4], rl[4];
                ldm_x4(rh, &Bh[wn * 64 + jj * 16 + b_row][ks + b_col]);
                ldm_x4(rl, &Bl[wn * 64 + jj * 16 + b_row][ks + b_col]);
                bhh[2 * jj][0] = rh[0]; bhh[2 * jj][1] = rh[1];
                bhh[2 * jj + 1][0] = rh[2]; bhh[2 * jj + 1][1] = rh[3];
                bll[2 * jj][0] = rl[0]; bll[2 * jj][1] = rl[1];
                bll[2 * jj + 1][0] = rl[2]; bll[2 * jj + 1][1] = rl[3];
            }
#pragma unroll
            for (int i = 0; i < 2; i++)
#pragma unroll
                for (int j = 0; j < 8; j++) {
                    mma_bf16(acc[i][j], ahh[i], bll[j]);
                    mma_bf16(acc[i][j], all[i], bhh[j]);
                    mma_bf16(acc[i][j], ahh[i], bhh[j]);
                }
        }
    }

#pragma unroll
    for (int i = 0; i < 2; i++)
#pragma unroll
        for (int half = 0; half < 2; half++) {
            int p = row0 + wm * 32 + i * 16 + half * 8 + g;
            if (p >= EE2) continue;
            float* dst = &g_z[p * 128 + wn * 64 + 2 * tg];
#pragma unroll
            for (int j = 0; j < 8; j++) {
                int col = wn * 64 + j * 8 + 2 * tg;
                float vA = (half ? acc[i][j].z : acc[i][j].x) + sb[col];
                float vB = (half ? acc[i][j].w : acc[i][j].y) + sb[col + 1];
                vA = 0.5f * vA * (1.f + erff(vA * 0.70710678118654752f));
                vB = 0.5f * vB * (1.f + erff(vB * 0.70710678118654752f));
                *(float2*)(dst + j * 8) = make_float2(vA, vB);
            }
        }
}

// ---------------- decode GEMM 2: [E2,128] x [128,8] (warp per pair) ----------------
__global__ void k_decode2(const float* __restrict__ mw2, const float* __restrict__ mb2,
                          float* __restrict__ out) {
    __shared__ float sw[HID * NCLS];
    __shared__ float sb[NCLS];
    const int t = threadIdx.x;
    for (int l = t; l < HID * NCLS; l += 256) sw[l] = mw2[l];
    if (t < NCLS) sb[t] = mb2[t];
    __syncthreads();
    int p = blockIdx.x * 8 + (t >> 5);
    int lane = t & 31;
    float4 z = *(const float4*)&g_z[p * HID + lane * 4];
    const float* w = sw + lane * 4 * NCLS;
    float acc[NCLS];
#pragma unroll
    for (int c = 0; c < NCLS; c++)
        acc[c] = z.x * w[c] + z.y * w[NCLS + c] + z.z * w[2 * NCLS + c] + z.w * w[3 * NCLS + c];
#pragma unroll
    for (int o = 16; o >= 1; o >>= 1)
#pragma unroll
        for (int c = 0; c < NCLS; c++) acc[c] += __shfl_xor_sync(0xffffffffu, acc[c], o);
    if (lane < NCLS) out[p * NCLS + lane] = acc[lane] + sb[lane];
}

// ---------------- launch ----------------
extern "C" void kernel_launch(void* const* d_in, const int* in_sizes, int n_in,
                              void* d_out, int out_size) {
    const float* x     = (const float*)d_in[0];
    const int*   ei    = (const int*)d_in[1];
    const int*   et    = (const int*)d_in[2];
    const int*   edges = (const int*)d_in[3];
    const float* w1 = (const float*)d_in[4];
    const float* q1 = (const float*)d_in[5];
    const float* k1 = (const float*)d_in[6];
    const float* b1 = (const float*)d_in[7];
    const float* w2 = (const float*)d_in[8];
    const float* q2 = (const float*)d_in[9];
    const float* k2 = (const float*)d_in[10];
    const float* b2 = (const float*)d_in[11];
    const float* ln1g = (const float*)d_in[12];
    const float* ln1b = (const float*)d_in[13];
    const float* ln2g = (const float*)d_in[14];
    const float* ln2b = (const float*)d_in[15];
    const float* mw1 = (const float*)d_in[16];
    const float* mb1 = (const float*)d_in[17];
    const float* mw2 = (const float*)d_in[18];
    const float* mb2 = (const float*)d_in[19];
    float* out = (float*)d_out;

    k_zero<<<(NN + 255) / 256, 256>>>();
    k_hist<<<(EE + 255) / 256, 256>>>(ei);
    k_scan<<<1, 1024>>>();
    k_fill<<<(EE + 255) / 256, 256>>>(ei, et);

    k_split_x<<<(NN * HID / 4 + 255) / 256, 256>>>(x);
    k_split_w<<<(RR * HID * HID + 255) / 256, 256>>>(w1);

    const dim3 gXW((NN + 127) / 128, RR);
    const int gAgg = (NN + 7) / 8;

    k_gemm_fused<<<gXW, 256>>>(q1, k1, 0);
    k_agg_ln<<<gAgg, 256>>>(b1, ln1g, ln1b, 1);

    k_split_w<<<(RR * HID * HID + 255) / 256, 256>>>(w2);
    k_gemm_fused<<<gXW, 256>>>(q2, k2, 1);
    k_agg_ln<<<gAgg, 256>>>(b2, ln2g, ln2b, 2);

    k_split_m1<<<(HID * 2 * HID + 255) / 256, 256>>>(mw1);
    k_decode1<<<(EE2 + 127) / 128, 256>>>(edges, mb1);
    k_decode2<<<EE2 / 8, 256>>>(mw2, mb2, out);
}

// round 7
// speedup vs baseline: 3.2453x; 1.1164x over previous
#include <cuda_runtime.h>
#include <cuda_bf16.h>
#include <math.h>
#include <stdint.h>

#define NN   50000
#define HID  128
#define RR   8
#define EE   640000
#define EE2  200000
#define NCLS 8

// ---------------- scratch (device globals; allocation-free) ----------------
__device__ float g_xw[NN * RR * HID];
__device__ float g_aq[NN * RR * 4];
__device__ float g_ak[NN * RR * 4];
__device__ float g_h1[NN * HID];
__device__ float g_z[EE2 * HID];
__device__ __nv_bfloat16 g_xhi[NN * HID],  g_xlo[NN * HID];
__device__ __nv_bfloat16 g_h1hi[NN * HID], g_h1lo[NN * HID];
__device__ __nv_bfloat16 g_hshi[NN * HID], g_hslo[NN * HID];
__device__ __nv_bfloat16 g_wthi[2 * RR * HID * HID], g_wtlo[2 * RR * HID * HID]; // [layer][r][k][n]
__device__ __nv_bfloat16 g_m1hi[2 * HID * HID], g_m1lo[2 * HID * HID];           // [k=256][n=128]
__device__ __nv_bfloat16 g_qkhi[2][64 * HID], g_qklo[2][64 * HID];               // [n=64][k=128]
__device__ int g_deg[NN], g_rowptr[NN + 1], g_cursor[NN], g_csr[EE];

// ---------------- helpers ----------------
__device__ __forceinline__ void bsplit(float v, __nv_bfloat16& hi, __nv_bfloat16& lo) {
    hi = __float2bfloat16(v);
    lo = __float2bfloat16(v - __bfloat162float(hi));
}
__device__ __forceinline__ void mma_bf16(float4& d, const uint32_t* a, const uint32_t* b) {
    asm volatile(
        "mma.sync.aligned.m16n8k16.row.col.f32.bf16.bf16.f32 "
        "{%0,%1,%2,%3}, {%4,%5,%6,%7}, {%8,%9}, {%0,%1,%2,%3};"
        : "+f"(d.x), "+f"(d.y), "+f"(d.z), "+f"(d.w)
        : "r"(a[0]), "r"(a[1]), "r"(a[2]), "r"(a[3]), "r"(b[0]), "r"(b[1]));
}
__device__ __forceinline__ void ldm_x4(uint32_t* r, const void* p) {
    uint32_t a = (uint32_t)__cvta_generic_to_shared(p);
    asm volatile("ldmatrix.sync.aligned.m8n8.x4.shared.b16 {%0,%1,%2,%3}, [%4];"
                 : "=r"(r[0]), "=r"(r[1]), "=r"(r[2]), "=r"(r[3]) : "r"(a));
}
__device__ __forceinline__ void ldm_x4_t(uint32_t* r, const void* p) {
    uint32_t a = (uint32_t)__cvta_generic_to_shared(p);
    asm volatile("ldmatrix.sync.aligned.m8n8.x4.trans.shared.b16 {%0,%1,%2,%3}, [%4];"
                 : "=r"(r[0]), "=r"(r[1]), "=r"(r[2]), "=r"(r[3]) : "r"(a));
}
__device__ __forceinline__ void cpa(uint32_t d, const void* s) {
    asm volatile("cp.async.cg.shared.global [%0], [%1], 16;" :: "r"(d), "l"(s));
}
__device__ __forceinline__ void cp_commit() { asm volatile("cp.async.commit_group;"); }
__device__ __forceinline__ void cp_wait0() { asm volatile("cp.async.wait_group 0;"); }
__device__ __forceinline__ void cp_wait1() { asm volatile("cp.async.wait_group 1;"); }

// stage layout (bytes): Ah 0, Al 10240, Bh 20480, Bl 29184; stage size 37888
#define STAGE_BYTES 37888

// ---------------- CSR build ----------------
__global__ void k_zero() {
    int i = blockIdx.x * blockDim.x + threadIdx.x;
    if (i < NN) g_deg[i] = 0;
}
__global__ void k_hist(const int* __restrict__ ei) {
    int e = blockIdx.x * blockDim.x + threadIdx.x;
    if (e < EE) atomicAdd(&g_deg[ei[EE + e]], 1);
}
__global__ void k_scan() {
    __shared__ int sp[1024];
    const int t = threadIdx.x;
    const int chunk = (NN + 1023) / 1024;
    int start = t * chunk, end = min(start + chunk, NN);
    int s = 0;
    for (int i = start; i < end; i++) s += g_deg[i];
    sp[t] = s;
    __syncthreads();
    for (int off = 1; off < 1024; off <<= 1) {
        int v = (t >= off) ? sp[t - off] : 0;
        __syncthreads();
        sp[t] += v;
        __syncthreads();
    }
    int run = (t == 0) ? 0 : sp[t - 1];
    for (int i = start; i < end; i++) {
        g_rowptr[i] = run;
        g_cursor[i] = run;
        run += g_deg[i];
    }
    if (t == 1023) g_rowptr[NN] = run;
}
__global__ void k_fill(const int* __restrict__ ei, const int* __restrict__ et) {
    int e = blockIdx.x * blockDim.x + threadIdx.x;
    if (e >= EE) return;
    int dst = ei[EE + e];
    int pos = atomicAdd(&g_cursor[dst], 1);
    g_csr[pos] = ei[e] * 8 + et[e];
}

// ---------------- fused prep: split x, w1, w2, mw1 into bf16 hi/lo planes ----------------
__global__ void k_prep(const float* __restrict__ x, const float* __restrict__ w1,
                       const float* __restrict__ w2, const float* __restrict__ mw1) {
    const int R0 = NN * HID / 4;          // 1,600,000
    const int R1 = RR * HID * HID / 4;    // 262,144
    const int R3 = 2 * HID * HID / 4;     // 8,192
    int id = blockIdx.x * blockDim.x + threadIdx.x;
    const float* src;
    __nv_bfloat16 *dhi, *dlo;
    int off;
    if (id < R0) { src = x; dhi = g_xhi; dlo = g_xlo; off = id; }
    else if (id < R0 + R1) { src = w1; dhi = g_wthi; dlo = g_wtlo; off = id - R0; }
    else if (id < R0 + 2 * R1) {
        src = w2; dhi = g_wthi + RR * HID * HID; dlo = g_wtlo + RR * HID * HID;
        off = id - R0 - R1;
    }
    else if (id < R0 + 2 * R1 + R3) { src = mw1; dhi = g_m1hi; dlo = g_m1lo; off = id - R0 - 2 * R1; }
    else return;
    float4 v = ((const float4*)src)[off];
    union { __nv_bfloat16 b[4]; uint2 u; } ph, pl;
    bsplit(v.x, ph.b[0], pl.b[0]); bsplit(v.y, ph.b[1], pl.b[1]);
    bsplit(v.z, ph.b[2], pl.b[2]); bsplit(v.w, ph.b[3], pl.b[3]);
    *(uint2*)&dhi[off * 4] = ph.u;
    *(uint2*)&dlo[off * 4] = pl.u;
}

// ---------------- Wqk planes: g_qk[layer][n=64][k=128] = sum_o W[r][k][o]*{q,k}[o][h] ----------------
__global__ void k_wqk(const float* __restrict__ W, const float* __restrict__ q,
                      const float* __restrict__ kk, int layer) {
    int id = blockIdx.x * blockDim.x + threadIdx.x;
    if (id >= 64 * HID) return;
    int i = id & 127, n = id >> 7;
    int h = n & 3, r = (n >> 2) & 7;
    const float* vq = (n < 32) ? q : kk;
    const float* wrow = W + r * HID * HID + i * HID;
    float s = 0.f;
#pragma unroll 4
    for (int o = 0; o < HID; o++) s += wrow[o] * vq[o * 4 + h];
    bsplit(s, g_qkhi[layer][n * HID + i], g_qklo[layer][n * HID + i]);
}

// ---------------- pure bf16x3 GEMM (cp.async pipelined): xw = A @ W[layer][r] ----------------
__global__ void __launch_bounds__(256, 2)
k_gemm_fused(int layer) {
    extern __shared__ char smem[];
    const int t = threadIdx.x, lane = t & 31, wid = t >> 5;
    const int wm = wid & 3, wn = wid >> 2, g = lane >> 2, tg = lane & 3;
    const int r = blockIdx.y, row0 = blockIdx.x * 128;
    const __nv_bfloat16* Ahi = layer ? g_h1hi : g_xhi;
    const __nv_bfloat16* Alo = layer ? g_h1lo : g_xlo;
    const __nv_bfloat16* Bhi = g_wthi + (layer * RR + r) * HID * HID;
    const __nv_bfloat16* Blo = g_wtlo + (layer * RR + r) * HID * HID;

    const int lr = t >> 1, lc = (t & 1) * 16;
    const int garow = row0 + lr;
    const __nv_bfloat16* asrc_hi = (garow < NN ? Ahi + garow * 128 : Ahi) + lc;
    const __nv_bfloat16* asrc_lo = (garow < NN ? Alo + garow * 128 : Alo) + lc;
    const int bk = t >> 3, bn = (t & 7) * 16;

    uint32_t sbase = (uint32_t)__cvta_generic_to_shared(smem);
    uint32_t ah_d[2], al_d[2], bh_d[2], bl_d[2];
#pragma unroll
    for (int s = 0; s < 2; s++) {
        uint32_t sb = sbase + s * STAGE_BYTES;
        ah_d[s] = sb + (lr * 40 + lc) * 2;
        al_d[s] = sb + 10240 + (lr * 40 + lc) * 2;
        bh_d[s] = sb + 20480 + (bk * 136 + bn) * 2;
        bl_d[s] = sb + 29184 + (bk * 136 + bn) * 2;
    }
    auto issue = [&](int k0, int s) {
        cpa(ah_d[s], asrc_hi + k0);       cpa(ah_d[s] + 16, asrc_hi + k0 + 8);
        cpa(al_d[s], asrc_lo + k0);       cpa(al_d[s] + 16, asrc_lo + k0 + 8);
        const __nv_bfloat16* bh = Bhi + (k0 + bk) * 128 + bn;
        const __nv_bfloat16* bl = Blo + (k0 + bk) * 128 + bn;
        cpa(bh_d[s], bh);                 cpa(bh_d[s] + 16, bh + 8);
        cpa(bl_d[s], bl);                 cpa(bl_d[s] + 16, bl + 8);
        cp_commit();
    };

    float4 acc[2][8];
#pragma unroll
    for (int i = 0; i < 2; i++)
#pragma unroll
        for (int j = 0; j < 8; j++) acc[i][j] = make_float4(0.f, 0.f, 0.f, 0.f);

    const int a_row = lane & 15, a_col = ((lane >> 4) & 1) * 8;
    const int b_k = (lane & 7) + ((lane & 8) ? 8 : 0);
    const int b_n8 = (lane & 16) ? 8 : 0;

    issue(0, 0);
    for (int it = 0; it < 4; it++) {
        if (it < 3) { issue((it + 1) * 32, (it + 1) & 1); cp_wait1(); }
        else cp_wait0();
        __syncthreads();
        char* st = smem + (it & 1) * STAGE_BYTES;
        __nv_bfloat16 (*Ah)[40]  = (__nv_bfloat16(*)[40])(st);
        __nv_bfloat16 (*Al)[40]  = (__nv_bfloat16(*)[40])(st + 10240);
        __nv_bfloat16 (*Bh)[136] = (__nv_bfloat16(*)[136])(st + 20480);
        __nv_bfloat16 (*Bl)[136] = (__nv_bfloat16(*)[136])(st + 29184);
#pragma unroll
        for (int ks = 0; ks < 32; ks += 16) {
            uint32_t ahh[2][4], all[2][4];
#pragma unroll
            for (int i = 0; i < 2; i++) {
                ldm_x4(ahh[i], &Ah[wm * 32 + i * 16 + a_row][ks + a_col]);
                ldm_x4(all[i], &Al[wm * 32 + i * 16 + a_row][ks + a_col]);
            }
            uint32_t bhh[8][2], bll[8][2];
#pragma unroll
            for (int jj = 0; jj < 4; jj++) {
                uint32_t rh[4], rl[4];
                ldm_x4_t(rh, &Bh[ks + b_k][wn * 64 + jj * 16 + b_n8]);
                ldm_x4_t(rl, &Bl[ks + b_k][wn * 64 + jj * 16 + b_n8]);
                bhh[2 * jj][0] = rh[0]; bhh[2 * jj][1] = rh[1];
                bhh[2 * jj + 1][0] = rh[2]; bhh[2 * jj + 1][1] = rh[3];
                bll[2 * jj][0] = rl[0]; bll[2 * jj][1] = rl[1];
                bll[2 * jj + 1][0] = rl[2]; bll[2 * jj + 1][1] = rl[3];
            }
#pragma unroll
            for (int i = 0; i < 2; i++)
#pragma unroll
                for (int j = 0; j < 8; j++) {
                    mma_bf16(acc[i][j], ahh[i], bll[j]);
                    mma_bf16(acc[i][j], all[i], bhh[j]);
                    mma_bf16(acc[i][j], ahh[i], bhh[j]);
                }
        }
        __syncthreads();
    }

#pragma unroll
    for (int i = 0; i < 2; i++)
#pragma unroll
        for (int half = 0; half < 2; half++) {
            int gr = row0 + wm * 32 + i * 16 + half * 8 + g;
            if (gr < NN) {
                float* dst = &g_xw[(gr * 8 + r) * 128 + wn * 64 + 2 * tg];
#pragma unroll
                for (int j = 0; j < 8; j++) {
                    float2 v = half ? make_float2(acc[i][j].z, acc[i][j].w)
                                    : make_float2(acc[i][j].x, acc[i][j].y);
                    *(float2*)(dst + j * 8) = v;
                }
            }
        }
}

// ---------------- aq/ak GEMM: [NN,128] @ qk-planes[64,128]^T ----------------
__global__ void __launch_bounds__(256)
k_aqk(int layer) {
    __shared__ __nv_bfloat16 Ah[128][40], Al[128][40], Bh[64][40], Bl[64][40];
    const int t = threadIdx.x, lane = t & 31, wid = t >> 5;
    const int wm = wid & 3, wn = wid >> 2, g = lane >> 2, tg = lane & 3;
    const int row0 = blockIdx.x * 128;
    const __nv_bfloat16* Ahi = layer ? g_h1hi : g_xhi;
    const __nv_bfloat16* Alo = layer ? g_h1lo : g_xlo;
    const __nv_bfloat16* Bhi = g_qkhi[layer];
    const __nv_bfloat16* Blo = g_qklo[layer];

    const int lr = t >> 1, lc = (t & 1) * 16;
    const int garow = row0 + lr;
    const __nv_bfloat16* ahp = (garow < NN ? Ahi + garow * 128 : Ahi) + lc;
    const __nv_bfloat16* alp = (garow < NN ? Alo + garow * 128 : Alo) + lc;
    const int br = t >> 2, bc = (t & 3) * 8;

    float4 acc[2][4];
#pragma unroll
    for (int i = 0; i < 2; i++)
#pragma unroll
        for (int j = 0; j < 4; j++) acc[i][j] = make_float4(0.f, 0.f, 0.f, 0.f);

    const int a_row = lane & 15, a_col = ((lane >> 4) & 1) * 8;
    const int b_row = (lane & 7) + ((lane & 16) ? 8 : 0);
    const int b_col = (lane & 8) ? 8 : 0;

    for (int k0 = 0; k0 < 128; k0 += 32) {
        uint4 a0 = *(const uint4*)(ahp + k0);
        uint4 a1 = *(const uint4*)(ahp + k0 + 8);
        uint4 a2 = *(const uint4*)(alp + k0);
        uint4 a3 = *(const uint4*)(alp + k0 + 8);
        uint4 b0 = *(const uint4*)&Bhi[br * 128 + k0 + bc];
        uint4 b1 = *(const uint4*)&Blo[br * 128 + k0 + bc];
        __syncthreads();
        *(uint4*)&Ah[lr][lc] = a0; *(uint4*)&Ah[lr][lc + 8] = a1;
        *(uint4*)&Al[lr][lc] = a2; *(uint4*)&Al[lr][lc + 8] = a3;
        *(uint4*)&Bh[br][bc] = b0;
        *(uint4*)&Bl[br][bc] = b1;
        __syncthreads();
#pragma unroll
        for (int ks = 0; ks < 32; ks += 16) {
            uint32_t ahh[2][4], all[2][4];
#pragma unroll
            for (int i = 0; i < 2; i++) {
                ldm_x4(ahh[i], &Ah[wm * 32 + i * 16 + a_row][ks + a_col]);
                ldm_x4(all[i], &Al[wm * 32 + i * 16 + a_row][ks + a_col]);
            }
            uint32_t bhh[4][2], bll[4][2];
#pragma unroll
            for (int jj = 0; jj < 2; jj++) {
                uint32_t rh[4], rl[4];
                ldm_x4(rh, &Bh[wn * 32 + jj * 16 + b_row][ks + b_col]);
                ldm_x4(rl, &Bl[wn * 32 + jj * 16 + b_row][ks + b_col]);
                bhh[2 * jj][0] = rh[0]; bhh[2 * jj][1] = rh[1];
                bhh[2 * jj + 1][0] = rh[2]; bhh[2 * jj + 1][1] = rh[3];
                bll[2 * jj][0] = rl[0]; bll[2 * jj][1] = rl[1];
                bll[2 * jj + 1][0] = rl[2]; bll[2 * jj + 1][1] = rl[3];
            }
#pragma unroll
            for (int i = 0; i < 2; i++)
#pragma unroll
                for (int j = 0; j < 4; j++) {
                    mma_bf16(acc[i][j], ahh[i], bll[j]);
                    mma_bf16(acc[i][j], all[i], bhh[j]);
                    mma_bf16(acc[i][j], ahh[i], bhh[j]);
                }
        }
    }

#pragma unroll
    for (int i = 0; i < 2; i++)
#pragma unroll
        for (int half = 0; half < 2; half++) {
            int gr = row0 + wm * 32 + i * 16 + half * 8 + g;
            if (gr >= NN) continue;
#pragma unroll
            for (int j = 0; j < 4; j++) {
                int col = wn * 32 + j * 8 + 2 * tg;
                float2 v = half ? make_float2(acc[i][j].z, acc[i][j].w)
                                : make_float2(acc[i][j].x, acc[i][j].y);
                if (col < 32) *(float2*)&g_aq[gr * 32 + col] = v;
                else          *(float2*)&g_ak[gr * 32 + col - 32] = v;
            }
        }
}

// ---------------- fused per-node softmax + aggregate + bias + relu + LN ----------------
__global__ void k_agg_ln(const float* __restrict__ bias, const float* __restrict__ gam,
                         const float* __restrict__ bet, int layer) {
    int nid = blockIdx.x * 8 + (threadIdx.x >> 5);
    if (nid >= NN) return;
    int lane = threadIdx.x & 31;
    int h = lane >> 3;
    int e8 = lane & 7;
    int j0 = g_rowptr[nid], j1 = g_rowptr[nid + 1];
    float4 num = make_float4(0.f, 0.f, 0.f, 0.f);
    float den = 0.f;
    for (int base = j0; base < j1; base += 8) {
        int idx = base + e8;
        int p = 0;
        float ex = 0.f;
        if (idx < j1) {
            p = g_csr[idx];
            int rr = p & 7;
            float a = g_aq[nid * 32 + rr * 4 + h] + g_ak[p * 4 + h];
            a = a > 0.f ? a : 0.2f * a;
            ex = __expf(a);
        }
        den += ex;
        int cnt = min(8, j1 - base);
        for (int e = 0; e < cnt; e++) {
            float exe = __shfl_sync(0xffffffffu, ex, (lane & 24) + e);
            int pe = __shfl_sync(0xffffffffu, p, e);
            float4 xj = *(const float4*)&g_xw[pe * 128 + lane * 4];
            num.x += exe * xj.x; num.y += exe * xj.y;
            num.z += exe * xj.z; num.w += exe * xj.w;
        }
    }
    den += __shfl_xor_sync(0xffffffffu, den, 1);
    den += __shfl_xor_sync(0xffffffffu, den, 2);
    den += __shfl_xor_sync(0xffffffffu, den, 4);
    float inv = 1.f / (den + 1e-16f);
    float4 bb = *(const float4*)&bias[lane * 4];
    float4 v;
    v.x = fmaxf(num.x * inv + bb.x, 0.f);
    v.y = fmaxf(num.y * inv + bb.y, 0.f);
    v.z = fmaxf(num.z * inv + bb.z, 0.f);
    v.w = fmaxf(num.w * inv + bb.w, 0.f);
    float s = v.x + v.y + v.z + v.w;
#pragma unroll
    for (int o = 16; o >= 1; o >>= 1) s += __shfl_xor_sync(0xffffffffu, s, o);
    float mean = s * (1.f / 128.f);
    float dx = v.x - mean, dy = v.y - mean, dz = v.z - mean, dw = v.w - mean;
    float ss = dx * dx + dy * dy + dz * dz + dw * dw;
#pragma unroll
    for (int o = 16; o >= 1; o >>= 1) ss += __shfl_xor_sync(0xffffffffu, ss, o);
    float rs = rsqrtf(ss * (1.f / 128.f) + 1e-5f);
    float4 g4 = *(const float4*)&gam[lane * 4];
    float4 b4 = *(const float4*)&bet[lane * 4];
    float4 y;
    y.x = dx * rs * g4.x + b4.x;
    y.y = dy * rs * g4.y + b4.y;
    y.z = dz * rs * g4.z + b4.z;
    y.w = dw * rs * g4.w + b4.w;
    union { __nv_bfloat16 b[4]; uint2 u; } ph, pl;
    if (layer == 1) {
        *(float4*)&g_h1[nid * HID + lane * 4] = y;
        bsplit(y.x, ph.b[0], pl.b[0]); bsplit(y.y, ph.b[1], pl.b[1]);
        bsplit(y.z, ph.b[2], pl.b[2]); bsplit(y.w, ph.b[3], pl.b[3]);
        *(uint2*)&g_h1hi[nid * HID + lane * 4] = ph.u;
        *(uint2*)&g_h1lo[nid * HID + lane * 4] = pl.u;
    } else {
        float4 h1 = *(const float4*)&g_h1[nid * HID + lane * 4];
        y.x += h1.x; y.y += h1.y; y.z += h1.z; y.w += h1.w;
        bsplit(y.x, ph.b[0], pl.b[0]); bsplit(y.y, ph.b[1], pl.b[1]);
        bsplit(y.z, ph.b[2], pl.b[2]); bsplit(y.w, ph.b[3], pl.b[3]);
        *(uint2*)&g_hshi[nid * HID + lane * 4] = ph.u;
        *(uint2*)&g_hslo[nid * HID + lane * 4] = pl.u;
    }
}

// ---------------- decode GEMM 1 (bf16x3 + cp.async pipeline): [E2,256] x [256,128] + GELU ----------------
__global__ void __launch_bounds__(256, 2)
k_decode1(const int* __restrict__ edges, const float* __restrict__ mb1) {
    extern __shared__ char smem[];
    __shared__ int sidx[128][2];
    __shared__ float sb[128];

    const int t = threadIdx.x, lane = t & 31, wid = t >> 5;
    const int wm = wid & 3, wn = wid >> 2, g = lane >> 2, tg = lane & 3;
    const int row0 = blockIdx.x * 128;

    if (t < 128) {
        int p = row0 + t;
        int2 pr = (p < EE2) ? ((const int2*)edges)[p] : make_int2(0, 0);
        sidx[t][0] = pr.x;
        sidx[t][1] = pr.y;
        sb[t] = mb1[t];
    }
    __syncthreads();

    const int lr = t >> 1, lc = (t & 1) * 16;
    const int node0 = sidx[lr][0];
    const int node1 = sidx[lr][1];
    const int bk = t >> 3, bn = (t & 7) * 16;

    uint32_t sbase = (uint32_t)__cvta_generic_to_shared(smem);
    uint32_t ah_d[2], al_d[2], bh_d[2], bl_d[2];
#pragma unroll
    for (int s = 0; s < 2; s++) {
        uint32_t sb2 = sbase + s * STAGE_BYTES;
        ah_d[s] = sb2 + (lr * 40 + lc) * 2;
        al_d[s] = sb2 + 10240 + (lr * 40 + lc) * 2;
        bh_d[s] = sb2 + 20480 + (bk * 136 + bn) * 2;
        bl_d[s] = sb2 + 29184 + (bk * 136 + bn) * 2;
    }
    auto issue = [&](int c, int s) {
        int node = (c < 4) ? node0 : node1;
        int colbase = (c & 3) * 32 + lc;
        const __nv_bfloat16* ah = &g_hshi[node * 128 + colbase];
        const __nv_bfloat16* al = &g_hslo[node * 128 + colbase];
        cpa(ah_d[s], ah);  cpa(ah_d[s] + 16, ah + 8);
        cpa(al_d[s], al);  cpa(al_d[s] + 16, al + 8);
        const __nv_bfloat16* bh = &g_m1hi[(c * 32 + bk) * 128 + bn];
        const __nv_bfloat16* bl = &g_m1lo[(c * 32 + bk) * 128 + bn];
        cpa(bh_d[s], bh);  cpa(bh_d[s] + 16, bh + 8);
        cpa(bl_d[s], bl);  cpa(bl_d[s] + 16, bl + 8);
        cp_commit();
    };

    float4 acc[2][8];
#pragma unroll
    for (int i = 0; i < 2; i++)
#pragma unroll
        for (int j = 0; j < 8; j++) acc[i][j] = make_float4(0.f, 0.f, 0.f, 0.f);

    const int a_row = lane & 15, a_col = ((lane >> 4) & 1) * 8;
    const int b_k = (lane & 7) + ((lane & 8) ? 8 : 0);
    const int b_n8 = (lane & 16) ? 8 : 0;

    issue(0, 0);
    for (int it = 0; it < 8; it++) {
        if (it < 7) { issue(it + 1, (it + 1) & 1); cp_wait1(); }
        else cp_wait0();
        __syncthreads();
        char* st = smem + (it & 1) * STAGE_BYTES;
        __nv_bfloat16 (*Ah)[40]  = (__nv_bfloat16(*)[40])(st);
        __nv_bfloat16 (*Al)[40]  = (__nv_bfloat16(*)[40])(st + 10240);
        __nv_bfloat16 (*Bh)[136] = (__nv_bfloat16(*)[136])(st + 20480);
        __nv_bfloat16 (*Bl)[136] = (__nv_bfloat16(*)[136])(st + 29184);
#pragma unroll
        for (int ks = 0; ks < 32; ks += 16) {
            uint32_t ahh[2][4], all[2][4];
#pragma unroll
            for (int i = 0; i < 2; i++) {
                ldm_x4(ahh[i], &Ah[wm * 32 + i * 16 + a_row][ks + a_col]);
                ldm_x4(all[i], &Al[wm * 32 + i * 16 + a_row][ks + a_col]);
            }
            uint32_t bhh[8][2], bll[8][2];
#pragma unroll
            for (int jj = 0; jj < 4; jj++) {
                uint32_t rh[4], rl[4];
                ldm_x4_t(rh, &Bh[ks + b_k][wn * 64 + jj * 16 + b_n8]);
                ldm_x4_t(rl, &Bl[ks + b_k][wn * 64 + jj * 16 + b_n8]);
                bhh[2 * jj][0] = rh[0]; bhh[2 * jj][1] = rh[1];
                bhh[2 * jj + 1][0] = rh[2]; bhh[2 * jj + 1][1] = rh[3];
                bll[2 * jj][0] = rl[0]; bll[2 * jj][1] = rl[1];
                bll[2 * jj + 1][0] = rl[2]; bll[2 * jj + 1][1] = rl[3];
            }
#pragma unroll
            for (int i = 0; i < 2; i++)
#pragma unroll
                for (int j = 0; j < 8; j++) {
                    mma_bf16(acc[i][j], ahh[i], bll[j]);
                    mma_bf16(acc[i][j], all[i], bhh[j]);
                    mma_bf16(acc[i][j], ahh[i], bhh[j]);
                }
        }
        __syncthreads();
    }

#pragma unroll
    for (int i = 0; i < 2; i++)
#pragma unroll
        for (int half = 0; half < 2; half++) {
            int p = row0 + wm * 32 + i * 16 + half * 8 + g;
            if (p >= EE2) continue;
            float* dst = &g_z[p * 128 + wn * 64 + 2 * tg];
#pragma unroll
            for (int j = 0; j < 8; j++) {
                int col = wn * 64 + j * 8 + 2 * tg;
                float vA = (half ? acc[i][j].z : acc[i][j].x) + sb[col];
                float vB = (half ? acc[i][j].w : acc[i][j].y) + sb[col + 1];
                vA = 0.5f * vA * (1.f + erff(vA * 0.70710678118654752f));
                vB = 0.5f * vB * (1.f + erff(vB * 0.70710678118654752f));
                *(float2*)(dst + j * 8) = make_float2(vA, vB);
            }
        }
}

// ---------------- decode GEMM 2: [E2,128] x [128,8] (warp per pair) ----------------
__global__ void k_decode2(const float* __restrict__ mw2, const float* __restrict__ mb2,
                          float* __restrict__ out) {
    __shared__ float sw[HID * NCLS];
    __shared__ float sb[NCLS];
    const int t = threadIdx.x;
    for (int l = t; l < HID * NCLS; l += 256) sw[l] = mw2[l];
    if (t < NCLS) sb[t] = mb2[t];
    __syncthreads();
    int p = blockIdx.x * 8 + (t >> 5);
    int lane = t & 31;
    float4 z = *(const float4*)&g_z[p * HID + lane * 4];
    const float* w = sw + lane * 4 * NCLS;
    float acc[NCLS];
#pragma unroll
    for (int c = 0; c < NCLS; c++)
        acc[c] = z.x * w[c] + z.y * w[NCLS + c] + z.z * w[2 * NCLS + c] + z.w * w[3 * NCLS + c];
#pragma unroll
    for (int o = 16; o >= 1; o >>= 1)
#pragma unroll
        for (int c = 0; c < NCLS; c++) acc[c] += __shfl_xor_sync(0xffffffffu, acc[c], o);
    if (lane < NCLS) out[p * NCLS + lane] = acc[lane] + sb[lane];
}

// ---------------- launch ----------------
extern "C" void kernel_launch(void* const* d_in, const int* in_sizes, int n_in,
                              void* d_out, int out_size) {
    const float* x     = (const float*)d_in[0];
    const int*   ei    = (const int*)d_in[1];
    const int*   et    = (const int*)d_in[2];
    const int*   edges = (const int*)d_in[3];
    const float* w1 = (const float*)d_in[4];
    const float* q1 = (const float*)d_in[5];
    const float* k1 = (const float*)d_in[6];
    const float* b1 = (const float*)d_in[7];
    const float* w2 = (const float*)d_in[8];
    const float* q2 = (const float*)d_in[9];
    const float* k2 = (const float*)d_in[10];
    const float* b2 = (const float*)d_in[11];
    const float* ln1g = (const float*)d_in[12];
    const float* ln1b = (const float*)d_in[13];
    const float* ln2g = (const float*)d_in[14];
    const float* ln2b = (const float*)d_in[15];
    const float* mw1 = (const float*)d_in[16];
    const float* mb1 = (const float*)d_in[17];
    const float* mw2 = (const float*)d_in[18];
    const float* mb2 = (const float*)d_in[19];
    float* out = (float*)d_out;

    cudaFuncSetAttribute(k_gemm_fused, cudaFuncAttributeMaxDynamicSharedMemorySize, 2 * STAGE_BYTES);
    cudaFuncSetAttribute(k_decode1,    cudaFuncAttributeMaxDynamicSharedMemorySize, 2 * STAGE_BYTES);

    const int prepTot = NN * HID / 4 + 2 * (RR * HID * HID / 4) + 2 * HID * HID / 4;
    const dim3 gXW((NN + 127) / 128, RR);

    k_prep<<<(prepTot + 255) / 256, 256>>>(x, w1, w2, mw1);          // 0
    k_wqk<<<(64 * HID + 255) / 256, 256>>>(w1, q1, k1, 0);           // 1
    k_zero<<<(NN + 255) / 256, 256>>>();                             // 2
    k_gemm_fused<<<gXW, 256, 2 * STAGE_BYTES>>>(0);                  // 3  <- profiler slot
    k_aqk<<<(NN + 127) / 128, 256>>>(0);                             // 4
    k_hist<<<(EE + 255) / 256, 256>>>(ei);                           // 5
    k_scan<<<1, 1024>>>();                                           // 6
    k_fill<<<(EE + 255) / 256, 256>>>(ei, et);                       // 7
    k_wqk<<<(64 * HID + 255) / 256, 256>>>(w2, q2, k2, 1);           // 8
    k_agg_ln<<<(NN + 7) / 8, 256>>>(b1, ln1g, ln1b, 1);              // 9
    k_gemm_fused<<<gXW, 256, 2 * STAGE_BYTES>>>(1);                  // 10
    k_aqk<<<(NN + 127) / 128, 256>>>(1);                             // 11
    k_agg_ln<<<(NN + 7) / 8, 256>>>(b2, ln2g, ln2b, 2);              // 12
    k_decode1<<<(EE2 + 127) / 128, 256, 2 * STAGE_BYTES>>>(edges, mb1); // 13
    k_decode2<<<EE2 / 8, 256>>>(mw2, mb2, out);                      // 14
}

// round 8
// speedup vs baseline: 4.2442x; 1.3078x over previous
#include <cuda_runtime.h>
#include <cuda_bf16.h>
#include <cuda_fp16.h>
#include <math.h>
#include <stdint.h>

#define NN   50000
#define HID  128
#define RR   8
#define EE   640000
#define EE2  200000
#define NCLS 8

// ---------------- scratch (device globals; allocation-free) ----------------
__device__ __half g_xw[NN * RR * HID];     // fp16: halves write + random-read traffic
__device__ float g_aq[NN * RR * 4];
__device__ float g_ak[NN * RR * 4];
__device__ float g_h1[NN * HID];
__device__ __nv_bfloat16 g_xhi[NN * HID],  g_xlo[NN * HID];
__device__ __nv_bfloat16 g_h1hi[NN * HID], g_h1lo[NN * HID];
__device__ __nv_bfloat16 g_hshi[NN * HID], g_hslo[NN * HID];
__device__ __nv_bfloat16 g_wthi[2 * RR * HID * HID], g_wtlo[2 * RR * HID * HID]; // [layer][r][k][n]
__device__ __nv_bfloat16 g_m1hi[2 * HID * HID], g_m1lo[2 * HID * HID];           // [k=256][n=128]
__device__ __nv_bfloat16 g_qkhi[2][64 * HID], g_qklo[2][64 * HID];               // [n=64][k=128]
__device__ int g_deg[NN], g_rowptr[NN + 1], g_cursor[NN], g_csr[EE];

// ---------------- helpers ----------------
__device__ __forceinline__ void bsplit(float v, __nv_bfloat16& hi, __nv_bfloat16& lo) {
    hi = __float2bfloat16(v);
    lo = __float2bfloat16(v - __bfloat162float(hi));
}
__device__ __forceinline__ void mma_bf16(float4& d, const uint32_t* a, const uint32_t* b) {
    asm volatile(
        "mma.sync.aligned.m16n8k16.row.col.f32.bf16.bf16.f32 "
        "{%0,%1,%2,%3}, {%4,%5,%6,%7}, {%8,%9}, {%0,%1,%2,%3};"
        : "+f"(d.x), "+f"(d.y), "+f"(d.z), "+f"(d.w)
        : "r"(a[0]), "r"(a[1]), "r"(a[2]), "r"(a[3]), "r"(b[0]), "r"(b[1]));
}
__device__ __forceinline__ void ldm_x4(uint32_t* r, const void* p) {
    uint32_t a = (uint32_t)__cvta_generic_to_shared(p);
    asm volatile("ldmatrix.sync.aligned.m8n8.x4.shared.b16 {%0,%1,%2,%3}, [%4];"
                 : "=r"(r[0]), "=r"(r[1]), "=r"(r[2]), "=r"(r[3]) : "r"(a));
}
__device__ __forceinline__ void ldm_x4_t(uint32_t* r, const void* p) {
    uint32_t a = (uint32_t)__cvta_generic_to_shared(p);
    asm volatile("ldmatrix.sync.aligned.m8n8.x4.trans.shared.b16 {%0,%1,%2,%3}, [%4];"
                 : "=r"(r[0]), "=r"(r[1]), "=r"(r[2]), "=r"(r[3]) : "r"(a));
}
__device__ __forceinline__ void cpa(uint32_t d, const void* s) {
    asm volatile("cp.async.cg.shared.global [%0], [%1], 16;" :: "r"(d), "l"(s));
}
__device__ __forceinline__ void cp_commit() { asm volatile("cp.async.commit_group;"); }
__device__ __forceinline__ void cp_wait0() { asm volatile("cp.async.wait_group 0;"); }
__device__ __forceinline__ void cp_wait1() { asm volatile("cp.async.wait_group 1;"); }

#define STAGE_BYTES 37888   // Ah 0, Al 10240, Bh 20480, Bl 29184

// ---------------- CSR build ----------------
__global__ void k_zero() {
    int i = blockIdx.x * blockDim.x + threadIdx.x;
    if (i < NN) g_deg[i] = 0;
}
__global__ void k_hist(const int* __restrict__ ei) {
    int e = blockIdx.x * blockDim.x + threadIdx.x;
    if (e < EE) atomicAdd(&g_deg[ei[EE + e]], 1);
}
__global__ void k_scan() {
    __shared__ int sp[1024];
    const int t = threadIdx.x;
    const int chunk = (NN + 1023) / 1024;
    int start = t * chunk, end = min(start + chunk, NN);
    int s = 0;
    for (int i = start; i < end; i++) s += g_deg[i];
    sp[t] = s;
    __syncthreads();
    for (int off = 1; off < 1024; off <<= 1) {
        int v = (t >= off) ? sp[t - off] : 0;
        __syncthreads();
        sp[t] += v;
        __syncthreads();
    }
    int run = (t == 0) ? 0 : sp[t - 1];
    for (int i = start; i < end; i++) {
        g_rowptr[i] = run;
        g_cursor[i] = run;
        run += g_deg[i];
    }
    if (t == 1023) g_rowptr[NN] = run;
}
__global__ void k_fill(const int* __restrict__ ei, const int* __restrict__ et) {
    int e = blockIdx.x * blockDim.x + threadIdx.x;
    if (e >= EE) return;
    int dst = ei[EE + e];
    int pos = atomicAdd(&g_cursor[dst], 1);
    g_csr[pos] = ei[e] * 8 + et[e];
}

// ---------------- fused prep: split x, w1, w2, mw1 into bf16 hi/lo planes ----------------
__global__ void k_prep(const float* __restrict__ x, const float* __restrict__ w1,
                       const float* __restrict__ w2, const float* __restrict__ mw1) {
    const int R0 = NN * HID / 4;
    const int R1 = RR * HID * HID / 4;
    const int R3 = 2 * HID * HID / 4;
    int id = blockIdx.x * blockDim.x + threadIdx.x;
    const float* src;
    __nv_bfloat16 *dhi, *dlo;
    int off;
    if (id < R0) { src = x; dhi = g_xhi; dlo = g_xlo; off = id; }
    else if (id < R0 + R1) { src = w1; dhi = g_wthi; dlo = g_wtlo; off = id - R0; }
    else if (id < R0 + 2 * R1) {
        src = w2; dhi = g_wthi + RR * HID * HID; dlo = g_wtlo + RR * HID * HID;
        off = id - R0 - R1;
    }
    else if (id < R0 + 2 * R1 + R3) { src = mw1; dhi = g_m1hi; dlo = g_m1lo; off = id - R0 - 2 * R1; }
    else return;
    float4 v = ((const float4*)src)[off];
    union { __nv_bfloat16 b[4]; uint2 u; } ph, pl;
    bsplit(v.x, ph.b[0], pl.b[0]); bsplit(v.y, ph.b[1], pl.b[1]);
    bsplit(v.z, ph.b[2], pl.b[2]); bsplit(v.w, ph.b[3], pl.b[3]);
    *(uint2*)&dhi[off * 4] = ph.u;
    *(uint2*)&dlo[off * 4] = pl.u;
}

// ---------------- Wqk planes ----------------
__global__ void k_wqk(const float* __restrict__ W, const float* __restrict__ q,
                      const float* __restrict__ kk, int layer) {
    int id = blockIdx.x * blockDim.x + threadIdx.x;
    if (id >= 64 * HID) return;
    int i = id & 127, n = id >> 7;
    int h = n & 3, r = (n >> 2) & 7;
    const float* vq = (n < 32) ? q : kk;
    const float* wrow = W + r * HID * HID + i * HID;
    float s = 0.f;
#pragma unroll 4
    for (int o = 0; o < HID; o++) s += wrow[o] * vq[o * 4 + h];
    bsplit(s, g_qkhi[layer][n * HID + i], g_qklo[layer][n * HID + i]);
}

// ---------------- pure bf16x3 GEMM (cp.async pipelined): xw = A @ W[layer][r] ----------------
__global__ void __launch_bounds__(256, 2)
k_gemm_fused(int layer) {
    extern __shared__ char smem[];
    const int t = threadIdx.x, lane = t & 31, wid = t >> 5;
    const int wm = wid & 3, wn = wid >> 2, g = lane >> 2, tg = lane & 3;
    const int r = blockIdx.y, row0 = blockIdx.x * 128;
    const __nv_bfloat16* Ahi = layer ? g_h1hi : g_xhi;
    const __nv_bfloat16* Alo = layer ? g_h1lo : g_xlo;
    const __nv_bfloat16* Bhi = g_wthi + (layer * RR + r) * HID * HID;
    const __nv_bfloat16* Blo = g_wtlo + (layer * RR + r) * HID * HID;

    const int lr = t >> 1, lc = (t & 1) * 16;
    const int garow = row0 + lr;
    const __nv_bfloat16* asrc_hi = (garow < NN ? Ahi + garow * 128 : Ahi) + lc;
    const __nv_bfloat16* asrc_lo = (garow < NN ? Alo + garow * 128 : Alo) + lc;
    const int bk = t >> 3, bn = (t & 7) * 16;

    uint32_t sbase = (uint32_t)__cvta_generic_to_shared(smem);
    uint32_t ah_d[2], al_d[2], bh_d[2], bl_d[2];
#pragma unroll
    for (int s = 0; s < 2; s++) {
        uint32_t sb = sbase + s * STAGE_BYTES;
        ah_d[s] = sb + (lr * 40 + lc) * 2;
        al_d[s] = sb + 10240 + (lr * 40 + lc) * 2;
        bh_d[s] = sb + 20480 + (bk * 136 + bn) * 2;
        bl_d[s] = sb + 29184 + (bk * 136 + bn) * 2;
    }
    auto issue = [&](int k0, int s) {
        cpa(ah_d[s], asrc_hi + k0);       cpa(ah_d[s] + 16, asrc_hi + k0 + 8);
        cpa(al_d[s], asrc_lo + k0);       cpa(al_d[s] + 16, asrc_lo + k0 + 8);
        const __nv_bfloat16* bh = Bhi + (k0 + bk) * 128 + bn;
        const __nv_bfloat16* bl = Blo + (k0 + bk) * 128 + bn;
        cpa(bh_d[s], bh);                 cpa(bh_d[s] + 16, bh + 8);
        cpa(bl_d[s], bl);                 cpa(bl_d[s] + 16, bl + 8);
        cp_commit();
    };

    float4 acc[2][8];
#pragma unroll
    for (int i = 0; i < 2; i++)
#pragma unroll
        for (int j = 0; j < 8; j++) acc[i][j] = make_float4(0.f, 0.f, 0.f, 0.f);

    const int a_row = lane & 15, a_col = ((lane >> 4) & 1) * 8;
    const int b_k = (lane & 7) + ((lane & 8) ? 8 : 0);
    const int b_n8 = (lane & 16) ? 8 : 0;

    issue(0, 0);
    for (int it = 0; it < 4; it++) {
        if (it < 3) { issue((it + 1) * 32, (it + 1) & 1); cp_wait1(); }
        else cp_wait0();
        __syncthreads();
        char* st = smem + (it & 1) * STAGE_BYTES;
        __nv_bfloat16 (*Ah)[40]  = (__nv_bfloat16(*)[40])(st);
        __nv_bfloat16 (*Al)[40]  = (__nv_bfloat16(*)[40])(st + 10240);
        __nv_bfloat16 (*Bh)[136] = (__nv_bfloat16(*)[136])(st + 20480);
        __nv_bfloat16 (*Bl)[136] = (__nv_bfloat16(*)[136])(st + 29184);
#pragma unroll
        for (int ks = 0; ks < 32; ks += 16) {
            uint32_t ahh[2][4], all[2][4];
#pragma unroll
            for (int i = 0; i < 2; i++) {
                ldm_x4(ahh[i], &Ah[wm * 32 + i * 16 + a_row][ks + a_col]);
                ldm_x4(all[i], &Al[wm * 32 + i * 16 + a_row][ks + a_col]);
            }
            uint32_t bhh[8][2], bll[8][2];
#pragma unroll
            for (int jj = 0; jj < 4; jj++) {
                uint32_t rh[4], rl[4];
                ldm_x4_t(rh, &Bh[ks + b_k][wn * 64 + jj * 16 + b_n8]);
                ldm_x4_t(rl, &Bl[ks + b_k][wn * 64 + jj * 16 + b_n8]);
                bhh[2 * jj][0] = rh[0]; bhh[2 * jj][1] = rh[1];
                bhh[2 * jj + 1][0] = rh[2]; bhh[2 * jj + 1][1] = rh[3];
                bll[2 * jj][0] = rl[0]; bll[2 * jj][1] = rl[1];
                bll[2 * jj + 1][0] = rl[2]; bll[2 * jj + 1][1] = rl[3];
            }
#pragma unroll
            for (int i = 0; i < 2; i++)
#pragma unroll
                for (int j = 0; j < 8; j++) {
                    mma_bf16(acc[i][j], ahh[i], bll[j]);
                    mma_bf16(acc[i][j], all[i], bhh[j]);
                    mma_bf16(acc[i][j], ahh[i], bhh[j]);
                }
        }
        __syncthreads();
    }

    // store xw as fp16
#pragma unroll
    for (int i = 0; i < 2; i++)
#pragma unroll
        for (int half = 0; half < 2; half++) {
            int gr = row0 + wm * 32 + i * 16 + half * 8 + g;
            if (gr < NN) {
                __half* dst = &g_xw[(gr * 8 + r) * 128 + wn * 64 + 2 * tg];
#pragma unroll
                for (int j = 0; j < 8; j++) {
                    float2 v = half ? make_float2(acc[i][j].z, acc[i][j].w)
                                    : make_float2(acc[i][j].x, acc[i][j].y);
                    *(__half2*)(dst + j * 8) = __floats2half2_rn(v.x, v.y);
                }
            }
        }
}

// ---------------- aq/ak GEMM: [NN,128] @ qk-planes[64,128]^T ----------------
__global__ void __launch_bounds__(256)
k_aqk(int layer) {
    __shared__ __nv_bfloat16 Ah[128][40], Al[128][40], Bh[64][40], Bl[64][40];
    const int t = threadIdx.x, lane = t & 31, wid = t >> 5;
    const int wm = wid & 3, wn = wid >> 2, g = lane >> 2, tg = lane & 3;
    const int row0 = blockIdx.x * 128;
    const __nv_bfloat16* Ahi = layer ? g_h1hi : g_xhi;
    const __nv_bfloat16* Alo = layer ? g_h1lo : g_xlo;
    const __nv_bfloat16* Bhi = g_qkhi[layer];
    const __nv_bfloat16* Blo = g_qklo[layer];

    const int lr = t >> 1, lc = (t & 1) * 16;
    const int garow = row0 + lr;
    const __nv_bfloat16* ahp = (garow < NN ? Ahi + garow * 128 : Ahi) + lc;
    const __nv_bfloat16* alp = (garow < NN ? Alo + garow * 128 : Alo) + lc;
    const int br = t >> 2, bc = (t & 3) * 8;

    float4 acc[2][4];
#pragma unroll
    for (int i = 0; i < 2; i++)
#pragma unroll
        for (int j = 0; j < 4; j++) acc[i][j] = make_float4(0.f, 0.f, 0.f, 0.f);

    const int a_row = lane & 15, a_col = ((lane >> 4) & 1) * 8;
    const int b_row = (lane & 7) + ((lane & 16) ? 8 : 0);
    const int b_col = (lane & 8) ? 8 : 0;

    for (int k0 = 0; k0 < 128; k0 += 32) {
        uint4 a0 = *(const uint4*)(ahp + k0);
        uint4 a1 = *(const uint4*)(ahp + k0 + 8);
        uint4 a2 = *(const uint4*)(alp + k0);
        uint4 a3 = *(const uint4*)(alp + k0 + 8);
        uint4 b0 = *(const uint4*)&Bhi[br * 128 + k0 + bc];
        uint4 b1 = *(const uint4*)&Blo[br * 128 + k0 + bc];
        __syncthreads();
        *(uint4*)&Ah[lr][lc] = a0; *(uint4*)&Ah[lr][lc + 8] = a1;
        *(uint4*)&Al[lr][lc] = a2; *(uint4*)&Al[lr][lc + 8] = a3;
        *(uint4*)&Bh[br][bc] = b0;
        *(uint4*)&Bl[br][bc] = b1;
        __syncthreads();
#pragma unroll
        for (int ks = 0; ks < 32; ks += 16) {
            uint32_t ahh[2][4], all[2][4];
#pragma unroll
            for (int i = 0; i < 2; i++) {
                ldm_x4(ahh[i], &Ah[wm * 32 + i * 16 + a_row][ks + a_col]);
                ldm_x4(all[i], &Al[wm * 32 + i * 16 + a_row][ks + a_col]);
            }
            uint32_t bhh[4][2], bll[4][2];
#pragma unroll
            for (int jj = 0; jj < 2; jj++) {
                uint32_t rh[4], rl[4];
                ldm_x4(rh, &Bh[wn * 32 + jj * 16 + b_row][ks + b_col]);
                ldm_x4(rl, &Bl[wn * 32 + jj * 16 + b_row][ks + b_col]);
                bhh[2 * jj][0] = rh[0]; bhh[2 * jj][1] = rh[1];
                bhh[2 * jj + 1][0] = rh[2]; bhh[2 * jj + 1][1] = rh[3];
                bll[2 * jj][0] = rl[0]; bll[2 * jj][1] = rl[1];
                bll[2 * jj + 1][0] = rl[2]; bll[2 * jj + 1][1] = rl[3];
            }
#pragma unroll
            for (int i = 0; i < 2; i++)
#pragma unroll
                for (int j = 0; j < 4; j++) {
                    mma_bf16(acc[i][j], ahh[i], bll[j]);
                    mma_bf16(acc[i][j], all[i], bhh[j]);
                    mma_bf16(acc[i][j], ahh[i], bhh[j]);
                }
        }
    }

#pragma unroll
    for (int i = 0; i < 2; i++)
#pragma unroll
        for (int half = 0; half < 2; half++) {
            int gr = row0 + wm * 32 + i * 16 + half * 8 + g;
            if (gr >= NN) continue;
#pragma unroll
            for (int j = 0; j < 4; j++) {
                int col = wn * 32 + j * 8 + 2 * tg;
                float2 v = half ? make_float2(acc[i][j].z, acc[i][j].w)
                                : make_float2(acc[i][j].x, acc[i][j].y);
                if (col < 32) *(float2*)&g_aq[gr * 32 + col] = v;
                else          *(float2*)&g_ak[gr * 32 + col - 32] = v;
            }
        }
}

// ---------------- fused per-node softmax + aggregate + bias + relu + LN ----------------
__global__ void k_agg_ln(const float* __restrict__ bias, const float* __restrict__ gam,
                         const float* __restrict__ bet, int layer) {
    int nid = blockIdx.x * 8 + (threadIdx.x >> 5);
    if (nid >= NN) return;
    int lane = threadIdx.x & 31;
    int h = lane >> 3;
    int e8 = lane & 7;
    int j0 = g_rowptr[nid], j1 = g_rowptr[nid + 1];
    float4 num = make_float4(0.f, 0.f, 0.f, 0.f);
    float den = 0.f;
    for (int base = j0; base < j1; base += 8) {
        int idx = base + e8;
        int p = 0;
        float ex = 0.f;
        if (idx < j1) {
            p = g_csr[idx];
            int rr = p & 7;
            float a = g_aq[nid * 32 + rr * 4 + h] + g_ak[p * 4 + h];
            a = a > 0.f ? a : 0.2f * a;
            ex = __expf(a);
        }
        den += ex;
        int cnt = min(8, j1 - base);
        for (int e = 0; e < cnt; e++) {
            float exe = __shfl_sync(0xffffffffu, ex, (lane & 24) + e);
            int pe = __shfl_sync(0xffffffffu, p, e);
            uint2 raw = *(const uint2*)&g_xw[pe * 128 + lane * 4];
            float2 f0 = __half22float2(*(__half2*)&raw.x);
            float2 f1 = __half22float2(*(__half2*)&raw.y);
            num.x += exe * f0.x; num.y += exe * f0.y;
            num.z += exe * f1.x; num.w += exe * f1.y;
        }
    }
    den += __shfl_xor_sync(0xffffffffu, den, 1);
    den += __shfl_xor_sync(0xffffffffu, den, 2);
    den += __shfl_xor_sync(0xffffffffu, den, 4);
    float inv = 1.f / (den + 1e-16f);
    float4 bb = *(const float4*)&bias[lane * 4];
    float4 v;
    v.x = fmaxf(num.x * inv + bb.x, 0.f);
    v.y = fmaxf(num.y * inv + bb.y, 0.f);
    v.z = fmaxf(num.z * inv + bb.z, 0.f);
    v.w = fmaxf(num.w * inv + bb.w, 0.f);
    float s = v.x + v.y + v.z + v.w;
#pragma unroll
    for (int o = 16; o >= 1; o >>= 1) s += __shfl_xor_sync(0xffffffffu, s, o);
    float mean = s * (1.f / 128.f);
    float dx = v.x - mean, dy = v.y - mean, dz = v.z - mean, dw = v.w - mean;
    float ss = dx * dx + dy * dy + dz * dz + dw * dw;
#pragma unroll
    for (int o = 16; o >= 1; o >>= 1) ss += __shfl_xor_sync(0xffffffffu, ss, o);
    float rs = rsqrtf(ss * (1.f / 128.f) + 1e-5f);
    float4 g4 = *(const float4*)&gam[lane * 4];
    float4 b4 = *(const float4*)&bet[lane * 4];
    float4 y;
    y.x = dx * rs * g4.x + b4.x;
    y.y = dy * rs * g4.y + b4.y;
    y.z = dz * rs * g4.z + b4.z;
    y.w = dw * rs * g4.w + b4.w;
    union { __nv_bfloat16 b[4]; uint2 u; } ph, pl;
    if (layer == 1) {
        *(float4*)&g_h1[nid * HID + lane * 4] = y;
        bsplit(y.x, ph.b[0], pl.b[0]); bsplit(y.y, ph.b[1], pl.b[1]);
        bsplit(y.z, ph.b[2], pl.b[2]); bsplit(y.w, ph.b[3], pl.b[3]);
        *(uint2*)&g_h1hi[nid * HID + lane * 4] = ph.u;
        *(uint2*)&g_h1lo[nid * HID + lane * 4] = pl.u;
    } else {
        float4 h1 = *(const float4*)&g_h1[nid * HID + lane * 4];
        y.x += h1.x; y.y += h1.y; y.z += h1.z; y.w += h1.w;
        bsplit(y.x, ph.b[0], pl.b[0]); bsplit(y.y, ph.b[1], pl.b[1]);
        bsplit(y.z, ph.b[2], pl.b[2]); bsplit(y.w, ph.b[3], pl.b[3]);
        *(uint2*)&g_hshi[nid * HID + lane * 4] = ph.u;
        *(uint2*)&g_hslo[nid * HID + lane * 4] = pl.u;
    }
}

// ---------------- decode (fused): gathered [E2,256]x[256,128] + GELU + [128,8] + bias ----------------
__global__ void __launch_bounds__(256, 2)
k_decode1(const int* __restrict__ edges, const float* __restrict__ mb1,
          const float* __restrict__ mw2, const float* __restrict__ mb2,
          float* __restrict__ out) {
    extern __shared__ char smem[];
    __shared__ int sidx[128][2];
    __shared__ float sb[128];
    __shared__ float sw2[128][NCLS];
    __shared__ float s_out[128][NCLS];

    const int t = threadIdx.x, lane = t & 31, wid = t >> 5;
    const int wm = wid & 3, wn = wid >> 2, g = lane >> 2, tg = lane & 3;
    const int row0 = blockIdx.x * 128;

    if (t < 128) {
        int p = row0 + t;
        int2 pr = (p < EE2) ? ((const int2*)edges)[p] : make_int2(0, 0);
        sidx[t][0] = pr.x;
        sidx[t][1] = pr.y;
        sb[t] = mb1[t];
        *(float4*)&sw2[t][0] = *(const float4*)&mw2[t * NCLS];
        *(float4*)&sw2[t][4] = *(const float4*)&mw2[t * NCLS + 4];
        *(float4*)&s_out[t][0] = make_float4(0.f, 0.f, 0.f, 0.f);
        *(float4*)&s_out[t][4] = make_float4(0.f, 0.f, 0.f, 0.f);
    }
    __syncthreads();

    const int lr = t >> 1, lc = (t & 1) * 16;
    const int node0 = sidx[lr][0];
    const int node1 = sidx[lr][1];
    const int bk = t >> 3, bn = (t & 7) * 16;

    uint32_t sbase = (uint32_t)__cvta_generic_to_shared(smem);
    uint32_t ah_d[2], al_d[2], bh_d[2], bl_d[2];
#pragma unroll
    for (int s = 0; s < 2; s++) {
        uint32_t sb2 = sbase + s * STAGE_BYTES;
        ah_d[s] = sb2 + (lr * 40 + lc) * 2;
        al_d[s] = sb2 + 10240 + (lr * 40 + lc) * 2;
        bh_d[s] = sb2 + 20480 + (bk * 136 + bn) * 2;
        bl_d[s] = sb2 + 29184 + (bk * 136 + bn) * 2;
    }
    auto issue = [&](int c, int s) {
        int node = (c < 4) ? node0 : node1;
        int colbase = (c & 3) * 32 + lc;
        const __nv_bfloat16* ah = &g_hshi[node * 128 + colbase];
        const __nv_bfloat16* al = &g_hslo[node * 128 + colbase];
        cpa(ah_d[s], ah);  cpa(ah_d[s] + 16, ah + 8);
        cpa(al_d[s], al);  cpa(al_d[s] + 16, al + 8);
        const __nv_bfloat16* bh = &g_m1hi[(c * 32 + bk) * 128 + bn];
        const __nv_bfloat16* bl = &g_m1lo[(c * 32 + bk) * 128 + bn];
        cpa(bh_d[s], bh);  cpa(bh_d[s] + 16, bh + 8);
        cpa(bl_d[s], bl);  cpa(bl_d[s] + 16, bl + 8);
        cp_commit();
    };

    float4 acc[2][8];
#pragma unroll
    for (int i = 0; i < 2; i++)
#pragma unroll
        for (int j = 0; j < 8; j++) acc[i][j] = make_float4(0.f, 0.f, 0.f, 0.f);

    const int a_row = lane & 15, a_col = ((lane >> 4) & 1) * 8;
    const int b_k = (lane & 7) + ((lane & 8) ? 8 : 0);
    const int b_n8 = (lane & 16) ? 8 : 0;

    issue(0, 0);
    for (int it = 0; it < 8; it++) {
        if (it < 7) { issue(it + 1, (it + 1) & 1); cp_wait1(); }
        else cp_wait0();
        __syncthreads();
        char* st = smem + (it & 1) * STAGE_BYTES;
        __nv_bfloat16 (*Ah)[40]  = (__nv_bfloat16(*)[40])(st);
        __nv_bfloat16 (*Al)[40]  = (__nv_bfloat16(*)[40])(st + 10240);
        __nv_bfloat16 (*Bh)[136] = (__nv_bfloat16(*)[136])(st + 20480);
        __nv_bfloat16 (*Bl)[136] = (__nv_bfloat16(*)[136])(st + 29184);
#pragma unroll
        for (int ks = 0; ks < 32; ks += 16) {
            uint32_t ahh[2][4], all[2][4];
#pragma unroll
            for (int i = 0; i < 2; i++) {
                ldm_x4(ahh[i], &Ah[wm * 32 + i * 16 + a_row][ks + a_col]);
                ldm_x4(all[i], &Al[wm * 32 + i * 16 + a_row][ks + a_col]);
            }
            uint32_t bhh[8][2], bll[8][2];
#pragma unroll
            for (int jj = 0; jj < 4; jj++) {
                uint32_t rh[4], rl[4];
                ldm_x4_t(rh, &Bh[ks + b_k][wn * 64 + jj * 16 + b_n8]);
                ldm_x4_t(rl, &Bl[ks + b_k][wn * 64 + jj * 16 + b_n8]);
                bhh[2 * jj][0] = rh[0]; bhh[2 * jj][1] = rh[1];
                bhh[2 * jj + 1][0] = rh[2]; bhh[2 * jj + 1][1] = rh[3];
                bll[2 * jj][0] = rl[0]; bll[2 * jj][1] = rl[1];
                bll[2 * jj + 1][0] = rl[2]; bll[2 * jj + 1][1] = rl[3];
            }
#pragma unroll
            for (int i = 0; i < 2; i++)
#pragma unroll
                for (int j = 0; j < 8; j++) {
                    mma_bf16(acc[i][j], ahh[i], bll[j]);
                    mma_bf16(acc[i][j], all[i], bhh[j]);
                    mma_bf16(acc[i][j], ahh[i], bhh[j]);
                }
        }
        __syncthreads();
    }

    // fused epilogue: bias + GELU + @mw2 partials, quad-reduce, smem accumulate
#pragma unroll
    for (int i = 0; i < 2; i++)
#pragma unroll
        for (int half = 0; half < 2; half++) {
            int row = wm * 32 + i * 16 + half * 8 + g;
            float pout[NCLS];
#pragma unroll
            for (int c = 0; c < NCLS; c++) pout[c] = 0.f;
#pragma unroll
            for (int j = 0; j < 8; j++) {
                int col = wn * 64 + j * 8 + 2 * tg;
                float vA = (half ? acc[i][j].z : acc[i][j].x) + sb[col];
                float vB = (half ? acc[i][j].w : acc[i][j].y) + sb[col + 1];
                vA = 0.5f * vA * (1.f + erff(vA * 0.70710678118654752f));
                vB = 0.5f * vB * (1.f + erff(vB * 0.70710678118654752f));
#pragma unroll
                for (int c = 0; c < NCLS; c++)
                    pout[c] += vA * sw2[col][c] + vB * sw2[col + 1][c];
            }
            // reduce over tg (lanes differing in bits 0-1)
#pragma unroll
            for (int c = 0; c < NCLS; c++) {
                pout[c] += __shfl_xor_sync(0xffffffffu, pout[c], 1);
                pout[c] += __shfl_xor_sync(0xffffffffu, pout[c], 2);
            }
            if (tg == 0) {
#pragma unroll
                for (int c = 0; c < NCLS; c++) atomicAdd(&s_out[row][c], pout[c]);
            }
        }
    __syncthreads();
    if (t < 128) {
        int p = row0 + t;
        if (p < EE2) {
            float4 o0, o1;
            o0.x = s_out[t][0] + mb2[0]; o0.y = s_out[t][1] + mb2[1];
            o0.z = s_out[t][2] + mb2[2]; o0.w = s_out[t][3] + mb2[3];
            o1.x = s_out[t][4] + mb2[4]; o1.y = s_out[t][5] + mb2[5];
            o1.z = s_out[t][6] + mb2[6]; o1.w = s_out[t][7] + mb2[7];
            *(float4*)&out[p * NCLS] = o0;
            *(float4*)&out[p * NCLS + 4] = o1;
        }
    }
}

// ---------------- launch ----------------
extern "C" void kernel_launch(void* const* d_in, const int* in_sizes, int n_in,
                              void* d_out, int out_size) {
    const float* x     = (const float*)d_in[0];
    const int*   ei    = (const int*)d_in[1];
    const int*   et    = (const int*)d_in[2];
    const int*   edges = (const int*)d_in[3];
    const float* w1 = (const float*)d_in[4];
    const float* q1 = (const float*)d_in[5];
    const float* k1 = (const float*)d_in[6];
    const float* b1 = (const float*)d_in[7];
    const float* w2 = (const float*)d_in[8];
    const float* q2 = (const float*)d_in[9];
    const float* k2 = (const float*)d_in[10];
    const float* b2 = (const float*)d_in[11];
    const float* ln1g = (const float*)d_in[12];
    const float* ln1b = (const float*)d_in[13];
    const float* ln2g = (const float*)d_in[14];
    const float* ln2b = (const float*)d_in[15];
    const float* mw1 = (const float*)d_in[16];
    const float* mb1 = (const float*)d_in[17];
    const float* mw2 = (const float*)d_in[18];
    const float* mb2 = (const float*)d_in[19];
    float* out = (float*)d_out;

    cudaFuncSetAttribute(k_gemm_fused, cudaFuncAttributeMaxDynamicSharedMemorySize, 2 * STAGE_BYTES);
    cudaFuncSetAttribute(k_decode1,    cudaFuncAttributeMaxDynamicSharedMemorySize, 2 * STAGE_BYTES);

    const int prepTot = NN * HID / 4 + 2 * (RR * HID * HID / 4) + 2 * HID * HID / 4;
    const dim3 gXW((NN + 127) / 128, RR);

    k_prep<<<(prepTot + 255) / 256, 256>>>(x, w1, w2, mw1);
    k_wqk<<<(64 * HID + 255) / 256, 256>>>(w1, q1, k1, 0);
    k_zero<<<(NN + 255) / 256, 256>>>();
    k_gemm_fused<<<gXW, 256, 2 * STAGE_BYTES>>>(0);
    k_aqk<<<(NN + 127) / 128, 256>>>(0);
    k_hist<<<(EE + 255) / 256, 256>>>(ei);
    k_scan<<<1, 1024>>>();
    k_fill<<<(EE + 255) / 256, 256>>>(ei, et);
    k_wqk<<<(64 * HID + 255) / 256, 256>>>(w2, q2, k2, 1);
    k_agg_ln<<<(NN + 7) / 8, 256>>>(b1, ln1g, ln1b, 1);
    k_gemm_fused<<<gXW, 256, 2 * STAGE_BYTES>>>(1);
    k_aqk<<<(NN + 127) / 128, 256>>>(1);
    k_agg_ln<<<(NN + 7) / 8, 256>>>(b2, ln2g, ln2b, 2);
    k_decode1<<<(EE2 + 127) / 128, 256, 2 * STAGE_BYTES>>>(edges, mb1, mw2, mb2, out);
}

// round 9
// speedup vs baseline: 4.3185x; 1.0175x over previous
#include <cuda_runtime.h>
#include <cuda_bf16.h>
#include <cuda_fp16.h>
#include <math.h>
#include <stdint.h>

#define NN   50000
#define HID  128
#define RR   8
#define EE   640000
#define EE2  200000
#define NCLS 8

// ---------------- scratch (device globals; allocation-free) ----------------
__device__ __half g_xw[NN * RR * HID];
__device__ float g_aq[NN * RR * 4];
__device__ float g_ak[NN * RR * 4];
__device__ __nv_bfloat16 g_xhi[NN * HID],  g_xlo[NN * HID];
__device__ __nv_bfloat16 g_h1hi[NN * HID], g_h1lo[NN * HID];
__device__ __nv_bfloat16 g_hshi[NN * HID], g_hslo[NN * HID];
__device__ __nv_bfloat16 g_wthi[2 * RR * HID * HID], g_wtlo[2 * RR * HID * HID];
__device__ __nv_bfloat16 g_m1hi[2 * HID * HID], g_m1lo[2 * HID * HID];
__device__ __nv_bfloat16 g_qkhi[2][64 * HID], g_qklo[2][64 * HID];
__device__ int g_deg[NN], g_rowptr[NN + 1], g_cursor[NN], g_csr[EE];

// ---------------- helpers ----------------
__device__ __forceinline__ void bsplit(float v, __nv_bfloat16& hi, __nv_bfloat16& lo) {
    hi = __float2bfloat16(v);
    lo = __float2bfloat16(v - __bfloat162float(hi));
}
__device__ __forceinline__ void mma_bf16(float4& d, const uint32_t* a, const uint32_t* b) {
    asm volatile(
        "mma.sync.aligned.m16n8k16.row.col.f32.bf16.bf16.f32 "
        "{%0,%1,%2,%3}, {%4,%5,%6,%7}, {%8,%9}, {%0,%1,%2,%3};"
        : "+f"(d.x), "+f"(d.y), "+f"(d.z), "+f"(d.w)
        : "r"(a[0]), "r"(a[1]), "r"(a[2]), "r"(a[3]), "r"(b[0]), "r"(b[1]));
}
__device__ __forceinline__ void ldm_x4(uint32_t* r, const void* p) {
    uint32_t a = (uint32_t)__cvta_generic_to_shared(p);
    asm volatile("ldmatrix.sync.aligned.m8n8.x4.shared.b16 {%0,%1,%2,%3}, [%4];"
                 : "=r"(r[0]), "=r"(r[1]), "=r"(r[2]), "=r"(r[3]) : "r"(a));
}
__device__ __forceinline__ void ldm_x4_t(uint32_t* r, const void* p) {
    uint32_t a = (uint32_t)__cvta_generic_to_shared(p);
    asm volatile("ldmatrix.sync.aligned.m8n8.x4.trans.shared.b16 {%0,%1,%2,%3}, [%4];"
                 : "=r"(r[0]), "=r"(r[1]), "=r"(r[2]), "=r"(r[3]) : "r"(a));
}
__device__ __forceinline__ void cpa(uint32_t d, const void* s) {
    asm volatile("cp.async.cg.shared.global [%0], [%1], 16;" :: "r"(d), "l"(s));
}
__device__ __forceinline__ void cp_commit() { asm volatile("cp.async.commit_group;"); }
__device__ __forceinline__ void cp_wait0() { asm volatile("cp.async.wait_group 0;"); }
__device__ __forceinline__ void cp_wait1() { asm volatile("cp.async.wait_group 1;"); }

#define STAGE_BYTES 37888   // Ah 0, Al 10240, Bh 20480, Bl 29184

// ---------------- CSR build ----------------
__global__ void k_zero() {
    int i = blockIdx.x * blockDim.x + threadIdx.x;
    if (i < NN) g_deg[i] = 0;
}
__global__ void k_hist(const int* __restrict__ ei) {
    int e = blockIdx.x * blockDim.x + threadIdx.x;
    if (e < EE) atomicAdd(&g_deg[ei[EE + e]], 1);
}
__global__ void k_scan() {
    __shared__ int sp[1024];
    const int t = threadIdx.x;
    const int chunk = (NN + 1023) / 1024;
    int start = t * chunk, end = min(start + chunk, NN);
    int s = 0;
    for (int i = start; i < end; i++) s += g_deg[i];
    sp[t] = s;
    __syncthreads();
    for (int off = 1; off < 1024; off <<= 1) {
        int v = (t >= off) ? sp[t - off] : 0;
        __syncthreads();
        sp[t] += v;
        __syncthreads();
    }
    int run = (t == 0) ? 0 : sp[t - 1];
    for (int i = start; i < end; i++) {
        g_rowptr[i] = run;
        g_cursor[i] = run;
        run += g_deg[i];
    }
    if (t == 1023) g_rowptr[NN] = run;
}
__global__ void k_fill(const int* __restrict__ ei, const int* __restrict__ et) {
    int e = blockIdx.x * blockDim.x + threadIdx.x;
    if (e >= EE) return;
    int dst = ei[EE + e];
    int pos = atomicAdd(&g_cursor[dst], 1);
    g_csr[pos] = ei[e] * 8 + et[e];
}

// ---------------- fused prep ----------------
__global__ void k_prep(const float* __restrict__ x, const float* __restrict__ w1,
                       const float* __restrict__ w2, const float* __restrict__ mw1) {
    const int R0 = NN * HID / 4;
    const int R1 = RR * HID * HID / 4;
    const int R3 = 2 * HID * HID / 4;
    int id = blockIdx.x * blockDim.x + threadIdx.x;
    const float* src;
    __nv_bfloat16 *dhi, *dlo;
    int off;
    if (id < R0) { src = x; dhi = g_xhi; dlo = g_xlo; off = id; }
    else if (id < R0 + R1) { src = w1; dhi = g_wthi; dlo = g_wtlo; off = id - R0; }
    else if (id < R0 + 2 * R1) {
        src = w2; dhi = g_wthi + RR * HID * HID; dlo = g_wtlo + RR * HID * HID;
        off = id - R0 - R1;
    }
    else if (id < R0 + 2 * R1 + R3) { src = mw1; dhi = g_m1hi; dlo = g_m1lo; off = id - R0 - 2 * R1; }
    else return;
    float4 v = ((const float4*)src)[off];
    union { __nv_bfloat16 b[4]; uint2 u; } ph, pl;
    bsplit(v.x, ph.b[0], pl.b[0]); bsplit(v.y, ph.b[1], pl.b[1]);
    bsplit(v.z, ph.b[2], pl.b[2]); bsplit(v.w, ph.b[3], pl.b[3]);
    *(uint2*)&dhi[off * 4] = ph.u;
    *(uint2*)&dlo[off * 4] = pl.u;
}

// ---------------- Wqk planes ----------------
__global__ void k_wqk(const float* __restrict__ W, const float* __restrict__ q,
                      const float* __restrict__ kk, int layer) {
    int id = blockIdx.x * blockDim.x + threadIdx.x;
    if (id >= 64 * HID) return;
    int i = id & 127, n = id >> 7;
    int h = n & 3, r = (n >> 2) & 7;
    const float* vq = (n < 32) ? q : kk;
    const float* wrow = W + r * HID * HID + i * HID;
    float s = 0.f;
#pragma unroll 4
    for (int o = 0; o < HID; o++) s += wrow[o] * vq[o * 4 + h];
    bsplit(s, g_qkhi[layer][n * HID + i], g_qklo[layer][n * HID + i]);
}

// ---------------- pure bf16x3 GEMM (cp.async pipelined) ----------------
__global__ void __launch_bounds__(256, 2)
k_gemm_fused(int layer) {
    extern __shared__ char smem[];
    const int t = threadIdx.x, lane = t & 31, wid = t >> 5;
    const int wm = wid & 3, wn = wid >> 2, g = lane >> 2, tg = lane & 3;
    const int r = blockIdx.y, row0 = blockIdx.x * 128;
    const __nv_bfloat16* Ahi = layer ? g_h1hi : g_xhi;
    const __nv_bfloat16* Alo = layer ? g_h1lo : g_xlo;
    const __nv_bfloat16* Bhi = g_wthi + (layer * RR + r) * HID * HID;
    const __nv_bfloat16* Blo = g_wtlo + (layer * RR + r) * HID * HID;

    const int lr = t >> 1, lc = (t & 1) * 16;
    const int garow = row0 + lr;
    const __nv_bfloat16* asrc_hi = (garow < NN ? Ahi + garow * 128 : Ahi) + lc;
    const __nv_bfloat16* asrc_lo = (garow < NN ? Alo + garow * 128 : Alo) + lc;
    const int bk = t >> 3, bn = (t & 7) * 16;

    uint32_t sbase = (uint32_t)__cvta_generic_to_shared(smem);
    uint32_t ah_d[2], al_d[2], bh_d[2], bl_d[2];
#pragma unroll
    for (int s = 0; s < 2; s++) {
        uint32_t sb = sbase + s * STAGE_BYTES;
        ah_d[s] = sb + (lr * 40 + lc) * 2;
        al_d[s] = sb + 10240 + (lr * 40 + lc) * 2;
        bh_d[s] = sb + 20480 + (bk * 136 + bn) * 2;
        bl_d[s] = sb + 29184 + (bk * 136 + bn) * 2;
    }
    auto issue = [&](int k0, int s) {
        cpa(ah_d[s], asrc_hi + k0);       cpa(ah_d[s] + 16, asrc_hi + k0 + 8);
        cpa(al_d[s], asrc_lo + k0);       cpa(al_d[s] + 16, asrc_lo + k0 + 8);
        const __nv_bfloat16* bh = Bhi + (k0 + bk) * 128 + bn;
        const __nv_bfloat16* bl = Blo + (k0 + bk) * 128 + bn;
        cpa(bh_d[s], bh);                 cpa(bh_d[s] + 16, bh + 8);
        cpa(bl_d[s], bl);                 cpa(bl_d[s] + 16, bl + 8);
        cp_commit();
    };

    float4 acc[2][8];
#pragma unroll
    for (int i = 0; i < 2; i++)
#pragma unroll
        for (int j = 0; j < 8; j++) acc[i][j] = make_float4(0.f, 0.f, 0.f, 0.f);

    const int a_row = lane & 15, a_col = ((lane >> 4) & 1) * 8;
    const int b_k = (lane & 7) + ((lane & 8) ? 8 : 0);
    const int b_n8 = (lane & 16) ? 8 : 0;

    issue(0, 0);
    for (int it = 0; it < 4; it++) {
        if (it < 3) { issue((it + 1) * 32, (it + 1) & 1); cp_wait1(); }
        else cp_wait0();
        __syncthreads();
        char* st = smem + (it & 1) * STAGE_BYTES;
        __nv_bfloat16 (*Ah)[40]  = (__nv_bfloat16(*)[40])(st);
        __nv_bfloat16 (*Al)[40]  = (__nv_bfloat16(*)[40])(st + 10240);
        __nv_bfloat16 (*Bh)[136] = (__nv_bfloat16(*)[136])(st + 20480);
        __nv_bfloat16 (*Bl)[136] = (__nv_bfloat16(*)[136])(st + 29184);
#pragma unroll
        for (int ks = 0; ks < 32; ks += 16) {
            uint32_t ahh[2][4], all[2][4];
#pragma unroll
            for (int i = 0; i < 2; i++) {
                ldm_x4(ahh[i], &Ah[wm * 32 + i * 16 + a_row][ks + a_col]);
                ldm_x4(all[i], &Al[wm * 32 + i * 16 + a_row][ks + a_col]);
            }
            uint32_t bhh[8][2], bll[8][2];
#pragma unroll
            for (int jj = 0; jj < 4; jj++) {
                uint32_t rh[4], rl[4];
                ldm_x4_t(rh, &Bh[ks + b_k][wn * 64 + jj * 16 + b_n8]);
                ldm_x4_t(rl, &Bl[ks + b_k][wn * 64 + jj * 16 + b_n8]);
                bhh[2 * jj][0] = rh[0]; bhh[2 * jj][1] = rh[1];
                bhh[2 * jj + 1][0] = rh[2]; bhh[2 * jj + 1][1] = rh[3];
                bll[2 * jj][0] = rl[0]; bll[2 * jj][1] = rl[1];
                bll[2 * jj + 1][0] = rl[2]; bll[2 * jj + 1][1] = rl[3];
            }
#pragma unroll
            for (int i = 0; i < 2; i++)
#pragma unroll
                for (int j = 0; j < 8; j++) {
                    mma_bf16(acc[i][j], ahh[i], bll[j]);
                    mma_bf16(acc[i][j], all[i], bhh[j]);
                    mma_bf16(acc[i][j], ahh[i], bhh[j]);
                }
        }
        __syncthreads();
    }

#pragma unroll
    for (int i = 0; i < 2; i++)
#pragma unroll
        for (int half = 0; half < 2; half++) {
            int gr = row0 + wm * 32 + i * 16 + half * 8 + g;
            if (gr < NN) {
                __half* dst = &g_xw[(gr * 8 + r) * 128 + wn * 64 + 2 * tg];
#pragma unroll
                for (int j = 0; j < 8; j++) {
                    float2 v = half ? make_float2(acc[i][j].z, acc[i][j].w)
                                    : make_float2(acc[i][j].x, acc[i][j].y);
                    *(__half2*)(dst + j * 8) = __floats2half2_rn(v.x, v.y);
                }
            }
        }
}

// ---------------- aq/ak GEMM ----------------
__global__ void __launch_bounds__(256)
k_aqk(int layer) {
    __shared__ __nv_bfloat16 Ah[128][40], Al[128][40], Bh[64][40], Bl[64][40];
    const int t = threadIdx.x, lane = t & 31, wid = t >> 5;
    const int wm = wid & 3, wn = wid >> 2, g = lane >> 2, tg = lane & 3;
    const int row0 = blockIdx.x * 128;
    const __nv_bfloat16* Ahi = layer ? g_h1hi : g_xhi;
    const __nv_bfloat16* Alo = layer ? g_h1lo : g_xlo;
    const __nv_bfloat16* Bhi = g_qkhi[layer];
    const __nv_bfloat16* Blo = g_qklo[layer];

    const int lr = t >> 1, lc = (t & 1) * 16;
    const int garow = row0 + lr;
    const __nv_bfloat16* ahp = (garow < NN ? Ahi + garow * 128 : Ahi) + lc;
    const __nv_bfloat16* alp = (garow < NN ? Alo + garow * 128 : Alo) + lc;
    const int br = t >> 2, bc = (t & 3) * 8;

    float4 acc[2][4];
#pragma unroll
    for (int i = 0; i < 2; i++)
#pragma unroll
        for (int j = 0; j < 4; j++) acc[i][j] = make_float4(0.f, 0.f, 0.f, 0.f);

    const int a_row = lane & 15, a_col = ((lane >> 4) & 1) * 8;
    const int b_row = (lane & 7) + ((lane & 16) ? 8 : 0);
    const int b_col = (lane & 8) ? 8 : 0;

    for (int k0 = 0; k0 < 128; k0 += 32) {
        uint4 a0 = *(const uint4*)(ahp + k0);
        uint4 a1 = *(const uint4*)(ahp + k0 + 8);
        uint4 a2 = *(const uint4*)(alp + k0);
        uint4 a3 = *(const uint4*)(alp + k0 + 8);
        uint4 b0 = *(const uint4*)&Bhi[br * 128 + k0 + bc];
        uint4 b1 = *(const uint4*)&Blo[br * 128 + k0 + bc];
        __syncthreads();
        *(uint4*)&Ah[lr][lc] = a0; *(uint4*)&Ah[lr][lc + 8] = a1;
        *(uint4*)&Al[lr][lc] = a2; *(uint4*)&Al[lr][lc + 8] = a3;
        *(uint4*)&Bh[br][bc] = b0;
        *(uint4*)&Bl[br][bc] = b1;
        __syncthreads();
#pragma unroll
        for (int ks = 0; ks < 32; ks += 16) {
            uint32_t ahh[2][4], all[2][4];
#pragma unroll
            for (int i = 0; i < 2; i++) {
                ldm_x4(ahh[i], &Ah[wm * 32 + i * 16 + a_row][ks + a_col]);
                ldm_x4(all[i], &Al[wm * 32 + i * 16 + a_row][ks + a_col]);
            }
            uint32_t bhh[4][2], bll[4][2];
#pragma unroll
            for (int jj = 0; jj < 2; jj++) {
                uint32_t rh[4], rl[4];
                ldm_x4(rh, &Bh[wn * 32 + jj * 16 + b_row][ks + b_col]);
                ldm_x4(rl, &Bl[wn * 32 + jj * 16 + b_row][ks + b_col]);
                bhh[2 * jj][0] = rh[0]; bhh[2 * jj][1] = rh[1];
                bhh[2 * jj + 1][0] = rh[2]; bhh[2 * jj + 1][1] = rh[3];
                bll[2 * jj][0] = rl[0]; bll[2 * jj][1] = rl[1];
                bll[2 * jj + 1][0] = rl[2]; bll[2 * jj + 1][1] = rl[3];
            }
#pragma unroll
            for (int i = 0; i < 2; i++)
#pragma unroll
                for (int j = 0; j < 4; j++) {
                    mma_bf16(acc[i][j], ahh[i], bll[j]);
                    mma_bf16(acc[i][j], all[i], bhh[j]);
                    mma_bf16(acc[i][j], ahh[i], bhh[j]);
                }
        }
    }

#pragma unroll
    for (int i = 0; i < 2; i++)
#pragma unroll
        for (int half = 0; half < 2; half++) {
            int gr = row0 + wm * 32 + i * 16 + half * 8 + g;
            if (gr >= NN) continue;
#pragma unroll
            for (int j = 0; j < 4; j++) {
                int col = wn * 32 + j * 8 + 2 * tg;
                float2 v = half ? make_float2(acc[i][j].z, acc[i][j].w)
                                : make_float2(acc[i][j].x, acc[i][j].y);
                if (col < 32) *(float2*)&g_aq[gr * 32 + col] = v;
                else          *(float2*)&g_ak[gr * 32 + col - 32] = v;
            }
        }
}

// ---------------- fused per-node softmax + aggregate + bias + relu + LN ----------------
__global__ void k_agg_ln(const float* __restrict__ bias, const float* __restrict__ gam,
                         const float* __restrict__ bet, int layer) {
    int nid = blockIdx.x * 8 + (threadIdx.x >> 5);
    if (nid >= NN) return;
    int lane = threadIdx.x & 31;
    int h = lane >> 3;
    int e8 = lane & 7;
    int j0 = g_rowptr[nid], j1 = g_rowptr[nid + 1];
    float4 num = make_float4(0.f, 0.f, 0.f, 0.f);
    float den = 0.f;
    for (int base = j0; base < j1; base += 8) {
        int idx = base + e8;
        int p = 0;
        float ex = 0.f;
        if (idx < j1) {
            p = g_csr[idx];
            int rr = p & 7;
            float a = g_aq[nid * 32 + rr * 4 + h] + g_ak[p * 4 + h];
            a = a > 0.f ? a : 0.2f * a;
            ex = __expf(a);
        }
        den += ex;
        int cnt = min(8, j1 - base);
        for (int e = 0; e < cnt; e++) {
            float exe = __shfl_sync(0xffffffffu, ex, (lane & 24) + e);
            int pe = __shfl_sync(0xffffffffu, p, e);
            uint2 raw = *(const uint2*)&g_xw[pe * 128 + lane * 4];
            float2 f0 = __half22float2(*(__half2*)&raw.x);
            float2 f1 = __half22float2(*(__half2*)&raw.y);
            num.x += exe * f0.x; num.y += exe * f0.y;
            num.z += exe * f1.x; num.w += exe * f1.y;
        }
    }
    den += __shfl_xor_sync(0xffffffffu, den, 1);
    den += __shfl_xor_sync(0xffffffffu, den, 2);
    den += __shfl_xor_sync(0xffffffffu, den, 4);
    float inv = 1.f / (den + 1e-16f);
    float4 bb = *(const float4*)&bias[lane * 4];
    float4 v;
    v.x = fmaxf(num.x * inv + bb.x, 0.f);
    v.y = fmaxf(num.y * inv + bb.y, 0.f);
    v.z = fmaxf(num.z * inv + bb.z, 0.f);
    v.w = fmaxf(num.w * inv + bb.w, 0.f);
    float s = v.x + v.y + v.z + v.w;
#pragma unroll
    for (int o = 16; o >= 1; o >>= 1) s += __shfl_xor_sync(0xffffffffu, s, o);
    float mean = s * (1.f / 128.f);
    float dx = v.x - mean, dy = v.y - mean, dz = v.z - mean, dw = v.w - mean;
    float ss = dx * dx + dy * dy + dz * dz + dw * dw;
#pragma unroll
    for (int o = 16; o >= 1; o >>= 1) ss += __shfl_xor_sync(0xffffffffu, ss, o);
    float rs = rsqrtf(ss * (1.f / 128.f) + 1e-5f);
    float4 g4 = *(const float4*)&gam[lane * 4];
    float4 b4 = *(const float4*)&bet[lane * 4];
    float4 y;
    y.x = dx * rs * g4.x + b4.x;
    y.y = dy * rs * g4.y + b4.y;
    y.z = dz * rs * g4.z + b4.z;
    y.w = dw * rs * g4.w + b4.w;
    union { __nv_bfloat16 b[4]; uint2 u; } ph, pl;
    if (layer == 1) {
        bsplit(y.x, ph.b[0], pl.b[0]); bsplit(y.y, ph.b[1], pl.b[1]);
        bsplit(y.z, ph.b[2], pl.b[2]); bsplit(y.w, ph.b[3], pl.b[3]);
        *(uint2*)&g_h1hi[nid * HID + lane * 4] = ph.u;
        *(uint2*)&g_h1lo[nid * HID + lane * 4] = pl.u;
    } else {
        // residual h1 reconstructed from split planes (hi+lo), avoiding a fp32 array
        uint2 rh = *(const uint2*)&g_h1hi[nid * HID + lane * 4];
        uint2 rl = *(const uint2*)&g_h1lo[nid * HID + lane * 4];
        const __nv_bfloat16* hb = (const __nv_bfloat16*)&rh;
        const __nv_bfloat16* lb = (const __nv_bfloat16*)&rl;
        y.x += __bfloat162float(hb[0]) + __bfloat162float(lb[0]);
        y.y += __bfloat162float(hb[1]) + __bfloat162float(lb[1]);
        y.z += __bfloat162float(hb[2]) + __bfloat162float(lb[2]);
        y.w += __bfloat162float(hb[3]) + __bfloat162float(lb[3]);
        bsplit(y.x, ph.b[0], pl.b[0]); bsplit(y.y, ph.b[1], pl.b[1]);
        bsplit(y.z, ph.b[2], pl.b[2]); bsplit(y.w, ph.b[3], pl.b[3]);
        *(uint2*)&g_hshi[nid * HID + lane * 4] = ph.u;
        *(uint2*)&g_hslo[nid * HID + lane * 4] = pl.u;
    }
}

// ---------------- decode (fused): [E2,256]x[256,128] + GELU + [128,8] + bias ----------------
__global__ void __launch_bounds__(256, 2)
k_decode1(const int* __restrict__ edges, const float* __restrict__ mb1,
          const float* __restrict__ mw2, const float* __restrict__ mb2,
          float* __restrict__ out) {
    extern __shared__ char smem[];
    __shared__ int sidx[128][2];
    __shared__ float sb[128];
    __shared__ float sw2[128][NCLS];
    __shared__ float s_out[128][NCLS];

    const int t = threadIdx.x, lane = t & 31, wid = t >> 5;
    const int wm = wid & 3, wn = wid >> 2, g = lane >> 2, tg = lane & 3;
    const int row0 = blockIdx.x * 128;

    if (t < 128) {
        int p = row0 + t;
        int2 pr = (p < EE2) ? ((const int2*)edges)[p] : make_int2(0, 0);
        sidx[t][0] = pr.x;
        sidx[t][1] = pr.y;
        sb[t] = mb1[t];
        *(float4*)&sw2[t][0] = *(const float4*)&mw2[t * NCLS];
        *(float4*)&sw2[t][4] = *(const float4*)&mw2[t * NCLS + 4];
        *(float4*)&s_out[t][0] = make_float4(0.f, 0.f, 0.f, 0.f);
        *(float4*)&s_out[t][4] = make_float4(0.f, 0.f, 0.f, 0.f);
    }
    __syncthreads();

    const int lr = t >> 1, lc = (t & 1) * 16;
    const int node0 = sidx[lr][0];
    const int node1 = sidx[lr][1];
    const int bk = t >> 3, bn = (t & 7) * 16;

    uint32_t sbase = (uint32_t)__cvta_generic_to_shared(smem);
    uint32_t ah_d[2], al_d[2], bh_d[2], bl_d[2];
#pragma unroll
    for (int s = 0; s < 2; s++) {
        uint32_t sb2 = sbase + s * STAGE_BYTES;
        ah_d[s] = sb2 + (lr * 40 + lc) * 2;
        al_d[s] = sb2 + 10240 + (lr * 40 + lc) * 2;
        bh_d[s] = sb2 + 20480 + (bk * 136 + bn) * 2;
        bl_d[s] = sb2 + 29184 + (bk * 136 + bn) * 2;
    }
    auto issue = [&](int c, int s) {
        int node = (c < 4) ? node0 : node1;
        int colbase = (c & 3) * 32 + lc;
        const __nv_bfloat16* ah = &g_hshi[node * 128 + colbase];
        const __nv_bfloat16* al = &g_hslo[node * 128 + colbase];
        cpa(ah_d[s], ah);  cpa(ah_d[s] + 16, ah + 8);
        cpa(al_d[s], al);  cpa(al_d[s] + 16, al + 8);
        const __nv_bfloat16* bh = &g_m1hi[(c * 32 + bk) * 128 + bn];
        const __nv_bfloat16* bl = &g_m1lo[(c * 32 + bk) * 128 + bn];
        cpa(bh_d[s], bh);  cpa(bh_d[s] + 16, bh + 8);
        cpa(bl_d[s], bl);  cpa(bl_d[s] + 16, bl + 8);
        cp_commit();
    };

    float4 acc[2][8];
#pragma unroll
    for (int i = 0; i < 2; i++)
#pragma unroll
        for (int j = 0; j < 8; j++) acc[i][j] = make_float4(0.f, 0.f, 0.f, 0.f);

    const int a_row = lane & 15, a_col = ((lane >> 4) & 1) * 8;
    const int b_k = (lane & 7) + ((lane & 8) ? 8 : 0);
    const int b_n8 = (lane & 16) ? 8 : 0;

    issue(0, 0);
    for (int it = 0; it < 8; it++) {
        if (it < 7) { issue(it + 1, (it + 1) & 1); cp_wait1(); }
        else cp_wait0();
        __syncthreads();
        char* st = smem + (it & 1) * STAGE_BYTES;
        __nv_bfloat16 (*Ah)[40]  = (__nv_bfloat16(*)[40])(st);
        __nv_bfloat16 (*Al)[40]  = (__nv_bfloat16(*)[40])(st + 10240);
        __nv_bfloat16 (*Bh)[136] = (__nv_bfloat16(*)[136])(st + 20480);
        __nv_bfloat16 (*Bl)[136] = (__nv_bfloat16(*)[136])(st + 29184);
#pragma unroll
        for (int ks = 0; ks < 32; ks += 16) {
            uint32_t ahh[2][4], all[2][4];
#pragma unroll
            for (int i = 0; i < 2; i++) {
                ldm_x4(ahh[i], &Ah[wm * 32 + i * 16 + a_row][ks + a_col]);
                ldm_x4(all[i], &Al[wm * 32 + i * 16 + a_row][ks + a_col]);
            }
            uint32_t bhh[8][2], bll[8][2];
#pragma unroll
            for (int jj = 0; jj < 4; jj++) {
                uint32_t rh[4], rl[4];
                ldm_x4_t(rh, &Bh[ks + b_k][wn * 64 + jj * 16 + b_n8]);
                ldm_x4_t(rl, &Bl[ks + b_k][wn * 64 + jj * 16 + b_n8]);
                bhh[2 * jj][0] = rh[0]; bhh[2 * jj][1] = rh[1];
                bhh[2 * jj + 1][0] = rh[2]; bhh[2 * jj + 1][1] = rh[3];
                bll[2 * jj][0] = rl[0]; bll[2 * jj][1] = rl[1];
                bll[2 * jj + 1][0] = rl[2]; bll[2 * jj + 1][1] = rl[3];
            }
#pragma unroll
            for (int i = 0; i < 2; i++)
#pragma unroll
                for (int j = 0; j < 8; j++) {
                    mma_bf16(acc[i][j], ahh[i], bll[j]);
                    mma_bf16(acc[i][j], all[i], bhh[j]);
                    mma_bf16(acc[i][j], ahh[i], bhh[j]);
                }
        }
        __syncthreads();
    }

#pragma unroll
    for (int i = 0; i < 2; i++)
#pragma unroll
        for (int half = 0; half < 2; half++) {
            int row = wm * 32 + i * 16 + half * 8 + g;
            float pout[NCLS];
#pragma unroll
            for (int c = 0; c < NCLS; c++) pout[c] = 0.f;
#pragma unroll
            for (int j = 0; j < 8; j++) {
                int col = wn * 64 + j * 8 + 2 * tg;
                float vA = (half ? acc[i][j].z : acc[i][j].x) + sb[col];
                float vB = (half ? acc[i][j].w : acc[i][j].y) + sb[col + 1];
                vA = 0.5f * vA * (1.f + erff(vA * 0.70710678118654752f));
                vB = 0.5f * vB * (1.f + erff(vB * 0.70710678118654752f));
#pragma unroll
                for (int c = 0; c < NCLS; c++)
                    pout[c] += vA * sw2[col][c] + vB * sw2[col + 1][c];
            }
#pragma unroll
            for (int c = 0; c < NCLS; c++) {
                pout[c] += __shfl_xor_sync(0xffffffffu, pout[c], 1);
                pout[c] += __shfl_xor_sync(0xffffffffu, pout[c], 2);
            }
            if (tg == 0) {
#pragma unroll
                for (int c = 0; c < NCLS; c++) atomicAdd(&s_out[row][c], pout[c]);
            }
        }
    __syncthreads();
    if (t < 128) {
        int p = row0 + t;
        if (p < EE2) {
            float4 o0, o1;
            o0.x = s_out[t][0] + mb2[0]; o0.y = s_out[t][1] + mb2[1];
            o0.z = s_out[t][2] + mb2[2]; o0.w = s_out[t][3] + mb2[3];
            o1.x = s_out[t][4] + mb2[4]; o1.y = s_out[t][5] + mb2[5];
            o1.z = s_out[t][6] + mb2[6]; o1.w = s_out[t][7] + mb2[7];
            *(float4*)&out[p * NCLS] = o0;
            *(float4*)&out[p * NCLS + 4] = o1;
        }
    }
}

// ---------------- launch (multi-stream fork/join, graph-capturable) ----------------
extern "C" void kernel_launch(void* const* d_in, const int* in_sizes, int n_in,
                              void* d_out, int out_size) {
    const float* x     = (const float*)d_in[0];
    const int*   ei    = (const int*)d_in[1];
    const int*   et    = (const int*)d_in[2];
    const int*   edges = (const int*)d_in[3];
    const float* w1 = (const float*)d_in[4];
    const float* q1 = (const float*)d_in[5];
    const float* k1 = (const float*)d_in[6];
    const float* b1 = (const float*)d_in[7];
    const float* w2 = (const float*)d_in[8];
    const float* q2 = (const float*)d_in[9];
    const float* k2 = (const float*)d_in[10];
    const float* b2 = (const float*)d_in[11];
    const float* ln1g = (const float*)d_in[12];
    const float* ln1b = (const float*)d_in[13];
    const float* ln2g = (const float*)d_in[14];
    const float* ln2b = (const float*)d_in[15];
    const float* mw1 = (const float*)d_in[16];
    const float* mb1 = (const float*)d_in[17];
    const float* mw2 = (const float*)d_in[18];
    const float* mb2 = (const float*)d_in[19];
    float* out = (float*)d_out;

    static cudaStream_t s1 = nullptr, s2 = nullptr;
    static cudaEvent_t evStart, evPrep, evW0, evFill, evA0, evH1, evA1;
    if (!s1) {
        cudaStreamCreateWithFlags(&s1, cudaStreamNonBlocking);
        cudaStreamCreateWithFlags(&s2, cudaStreamNonBlocking);
        cudaEventCreateWithFlags(&evStart, cudaEventDisableTiming);
        cudaEventCreateWithFlags(&evPrep,  cudaEventDisableTiming);
        cudaEventCreateWithFlags(&evW0,    cudaEventDisableTiming);
        cudaEventCreateWithFlags(&evFill,  cudaEventDisableTiming);
        cudaEventCreateWithFlags(&evA0,    cudaEventDisableTiming);
        cudaEventCreateWithFlags(&evH1,    cudaEventDisableTiming);
        cudaEventCreateWithFlags(&evA1,    cudaEventDisableTiming);
        cudaFuncSetAttribute(k_gemm_fused, cudaFuncAttributeMaxDynamicSharedMemorySize, 2 * STAGE_BYTES);
        cudaFuncSetAttribute(k_decode1,    cudaFuncAttributeMaxDynamicSharedMemorySize, 2 * STAGE_BYTES);
    }

    const int prepTot = NN * HID / 4 + 2 * (RR * HID * HID / 4) + 2 * HID * HID / 4;
    const dim3 gXW((NN + 127) / 128, RR);

    // fork side streams off the capture stream
    cudaEventRecord(evStart, 0);
    cudaStreamWaitEvent(s1, evStart, 0);

    // side stream 1: wqk planes + CSR build (independent of main chain)
    k_wqk<<<(64 * HID + 255) / 256, 256, 0, s1>>>(w1, q1, k1, 0);
    cudaEventRecord(evW0, s1);
    k_wqk<<<(64 * HID + 255) / 256, 256, 0, s1>>>(w2, q2, k2, 1);
    k_zero<<<(NN + 255) / 256, 256, 0, s1>>>();
    k_hist<<<(EE + 255) / 256, 256, 0, s1>>>(ei);
    k_scan<<<1, 1024, 0, s1>>>();
    k_fill<<<(EE + 255) / 256, 256, 0, s1>>>(ei, et);
    cudaEventRecord(evFill, s1);

    // main stream: prep -> gemm(0)
    k_prep<<<(prepTot + 255) / 256, 256>>>(x, w1, w2, mw1);
    cudaEventRecord(evPrep, 0);

    // side stream 2: aqk(0) concurrent with gemm(0)
    cudaStreamWaitEvent(s2, evStart, 0);
    cudaStreamWaitEvent(s2, evPrep, 0);
    cudaStreamWaitEvent(s2, evW0, 0);
    k_aqk<<<(NN + 127) / 128, 256, 0, s2>>>(0);
    cudaEventRecord(evA0, s2);

    k_gemm_fused<<<gXW, 256, 2 * STAGE_BYTES>>>(0);
    cudaStreamWaitEvent(0, evA0, 0);
    cudaStreamWaitEvent(0, evFill, 0);
    k_agg_ln<<<(NN + 7) / 8, 256>>>(b1, ln1g, ln1b, 1);
    cudaEventRecord(evH1, 0);

    // side stream 2: aqk(1) concurrent with gemm(1)
    cudaStreamWaitEvent(s2, evH1, 0);
    k_aqk<<<(NN + 127) / 128, 256, 0, s2>>>(1);
    cudaEventRecord(evA1, s2);

    k_gemm_fused<<<gXW, 256, 2 * STAGE_BYTES>>>(1);
    cudaStreamWaitEvent(0, evA1, 0);
    k_agg_ln<<<(NN + 7) / 8, 256>>>(b2, ln2g, ln2b, 2);

    k_decode1<<<(EE2 + 127) / 128, 256, 2 * STAGE_BYTES>>>(edges, mb1, mw2, mb2, out);
}

// round 11
// speedup vs baseline: 5.0463x; 1.1685x over previous
#include <cuda_runtime.h>
#include <cuda_bf16.h>
#include <cuda_fp16.h>
#include <math.h>
#include <stdint.h>

#define NN   50000
#define HID  128
#define RR   8
#define EE   640000
#define EE2  200000
#define NCLS 8

// ---------------- scratch (device globals; allocation-free) ----------------
__device__ __half g_xw[NN * RR * HID];
__device__ float g_aq[NN * RR * 4];
__device__ float g_ak[NN * RR * 4];
__device__ __half g_x16[NN * HID], g_h116[NN * HID];             // fp16 single-plane A for xw GEMM
__device__ __nv_bfloat16 g_xhi[NN * HID],  g_xlo[NN * HID];      // bf16 splits for aqk
__device__ __nv_bfloat16 g_h1hi[NN * HID], g_h1lo[NN * HID];
__device__ __nv_bfloat16 g_hshi[NN * HID], g_hslo[NN * HID];
__device__ __half g_w16[2 * RR * HID * HID];                     // [layer][r][k][n] fp16
__device__ __nv_bfloat16 g_m1hi[2 * HID * HID], g_m1lo[2 * HID * HID]; // [k=256][n=128]
__device__ __nv_bfloat16 g_qkhi[2][64 * HID], g_qklo[2][64 * HID];     // [n=64][k=128]
__device__ int g_deg[NN], g_rowptr[NN + 1], g_cursor[NN], g_csr[EE];

// ---------------- helpers ----------------
__device__ __forceinline__ void bsplit(float v, __nv_bfloat16& hi, __nv_bfloat16& lo) {
    hi = __float2bfloat16(v);
    lo = __float2bfloat16(v - __bfloat162float(hi));
}
__device__ __forceinline__ void mma_bf16(float4& d, const uint32_t* a, const uint32_t* b) {
    asm volatile(
        "mma.sync.aligned.m16n8k16.row.col.f32.bf16.bf16.f32 "
        "{%0,%1,%2,%3}, {%4,%5,%6,%7}, {%8,%9}, {%0,%1,%2,%3};"
        : "+f"(d.x), "+f"(d.y), "+f"(d.z), "+f"(d.w)
        : "r"(a[0]), "r"(a[1]), "r"(a[2]), "r"(a[3]), "r"(b[0]), "r"(b[1]));
}
__device__ __forceinline__ void mma_f16(float4& d, const uint32_t* a, const uint32_t* b) {
    asm volatile(
        "mma.sync.aligned.m16n8k16.row.col.f32.f16.f16.f32 "
        "{%0,%1,%2,%3}, {%4,%5,%6,%7}, {%8,%9}, {%0,%1,%2,%3};"
        : "+f"(d.x), "+f"(d.y), "+f"(d.z), "+f"(d.w)
        : "r"(a[0]), "r"(a[1]), "r"(a[2]), "r"(a[3]), "r"(b[0]), "r"(b[1]));
}
__device__ __forceinline__ void ldm_x4(uint32_t* r, const void* p) {
    uint32_t a = (uint32_t)__cvta_generic_to_shared(p);
    asm volatile("ldmatrix.sync.aligned.m8n8.x4.shared.b16 {%0,%1,%2,%3}, [%4];"
                 : "=r"(r[0]), "=r"(r[1]), "=r"(r[2]), "=r"(r[3]) : "r"(a));
}
__device__ __forceinline__ void ldm_x4_t(uint32_t* r, const void* p) {
    uint32_t a = (uint32_t)__cvta_generic_to_shared(p);
    asm volatile("ldmatrix.sync.aligned.m8n8.x4.trans.shared.b16 {%0,%1,%2,%3}, [%4];"
                 : "=r"(r[0]), "=r"(r[1]), "=r"(r[2]), "=r"(r[3]) : "r"(a));
}
__device__ __forceinline__ void cpa(uint32_t d, const void* s) {
    asm volatile("cp.async.cg.shared.global [%0], [%1], 16;" :: "r"(d), "l"(s));
}
__device__ __forceinline__ void cp_commit() { asm volatile("cp.async.commit_group;"); }
__device__ __forceinline__ void cp_wait0() { asm volatile("cp.async.wait_group 0;"); }
__device__ __forceinline__ void cp_wait1() { asm volatile("cp.async.wait_group 1;"); }

#define STAGE_BYTES 37888   // decode stage: Ah 0, Al 10240, Bh 20480, Bl 29184
#define G_STAGE 18944       // fp16 gemm stage: A 0 (10240), B 10240 (8704)

// ---------------- CSR build ----------------
__global__ void k_zero() {
    int i = blockIdx.x * blockDim.x + threadIdx.x;
    if (i < NN) g_deg[i] = 0;
}
__global__ void k_hist(const int* __restrict__ ei) {
    int e = blockIdx.x * blockDim.x + threadIdx.x;
    if (e < EE) atomicAdd(&g_deg[ei[EE + e]], 1);
}
__global__ void k_scan() {
    __shared__ int sp[1024];
    const int t = threadIdx.x;
    const int chunk = (NN + 1023) / 1024;
    int start = t * chunk, end = min(start + chunk, NN);
    int s = 0;
    for (int i = start; i < end; i++) s += g_deg[i];
    sp[t] = s;
    __syncthreads();
    for (int off = 1; off < 1024; off <<= 1) {
        int v = (t >= off) ? sp[t - off] : 0;
        __syncthreads();
        sp[t] += v;
        __syncthreads();
    }
    int run = (t == 0) ? 0 : sp[t - 1];
    for (int i = start; i < end; i++) {
        g_rowptr[i] = run;
        g_cursor[i] = run;
        run += g_deg[i];
    }
    if (t == 1023) g_rowptr[NN] = run;
}
__global__ void k_fill(const int* __restrict__ ei, const int* __restrict__ et) {
    int e = blockIdx.x * blockDim.x + threadIdx.x;
    if (e >= EE) return;
    int dst = ei[EE + e];
    int pos = atomicAdd(&g_cursor[dst], 1);
    g_csr[pos] = ei[e] * 8 + et[e];
}

// ---------------- fused prep: x -> {fp16, bf16 hi/lo}; W -> fp16; mw1 -> bf16 hi/lo ----------------
__global__ void k_prep(const float* __restrict__ x, const float* __restrict__ w1,
                       const float* __restrict__ w2, const float* __restrict__ mw1) {
    const int R0 = NN * HID / 4;
    const int R1 = RR * HID * HID / 4;
    const int R3 = 2 * HID * HID / 4;
    int id = blockIdx.x * blockDim.x + threadIdx.x;
    if (id < R0) {
        float4 v = ((const float4*)x)[id];
        union { __nv_bfloat16 b[4]; uint2 u; } ph, pl;
        bsplit(v.x, ph.b[0], pl.b[0]); bsplit(v.y, ph.b[1], pl.b[1]);
        bsplit(v.z, ph.b[2], pl.b[2]); bsplit(v.w, ph.b[3], pl.b[3]);
        *(uint2*)&g_xhi[id * 4] = ph.u;
        *(uint2*)&g_xlo[id * 4] = pl.u;
        __half2 h0 = __floats2half2_rn(v.x, v.y);
        __half2 h1 = __floats2half2_rn(v.z, v.w);
        uint2 u16;
        u16.x = *(uint32_t*)&h0; u16.y = *(uint32_t*)&h1;
        *(uint2*)&g_x16[id * 4] = u16;
    } else if (id < R0 + 2 * R1) {
        int layer = (id - R0) >= R1;
        int off = id - R0 - layer * R1;
        const float* src = layer ? w2 : w1;
        float4 v = ((const float4*)src)[off];
        __half2 h0 = __floats2half2_rn(v.x, v.y);
        __half2 h1 = __floats2half2_rn(v.z, v.w);
        uint2 u16;
        u16.x = *(uint32_t*)&h0; u16.y = *(uint32_t*)&h1;
        *(uint2*)&g_w16[layer * RR * HID * HID + off * 4] = u16;
    } else if (id < R0 + 2 * R1 + R3) {
        int off = id - R0 - 2 * R1;
        float4 v = ((const float4*)mw1)[off];
        union { __nv_bfloat16 b[4]; uint2 u; } ph, pl;
        bsplit(v.x, ph.b[0], pl.b[0]); bsplit(v.y, ph.b[1], pl.b[1]);
        bsplit(v.z, ph.b[2], pl.b[2]); bsplit(v.w, ph.b[3], pl.b[3]);
        *(uint2*)&g_m1hi[off * 4] = ph.u;
        *(uint2*)&g_m1lo[off * 4] = pl.u;
    }
}

// ---------------- Wqk planes ----------------
__global__ void k_wqk(const float* __restrict__ W, const float* __restrict__ q,
                      const float* __restrict__ kk, int layer) {
    int id = blockIdx.x * blockDim.x + threadIdx.x;
    if (id >= 64 * HID) return;
    int i = id & 127, n = id >> 7;
    int h = n & 3, r = (n >> 2) & 7;
    const float* vq = (n < 32) ? q : kk;
    const float* wrow = W + r * HID * HID + i * HID;
    float s = 0.f;
#pragma unroll 4
    for (int o = 0; o < HID; o++) s += wrow[o] * vq[o * 4 + h];
    bsplit(s, g_qkhi[layer][n * HID + i], g_qklo[layer][n * HID + i]);
}

// ---------------- fp16 single-plane GEMM (cp.async pipelined): xw = A @ W[layer][r] ----------------
__global__ void __launch_bounds__(256, 2)
k_gemm16(int layer) {
    extern __shared__ char smem[];
    const int t = threadIdx.x, lane = t & 31, wid = t >> 5;
    const int wm = wid & 3, wn = wid >> 2, g = lane >> 2, tg = lane & 3;
    const int r = blockIdx.y, row0 = blockIdx.x * 128;
    const __half* A = layer ? g_h116 : g_x16;
    const __half* B = g_w16 + (layer * RR + r) * HID * HID;   // [k][n]

    const int lr = t >> 1, lc = (t & 1) * 16;
    const int garow = row0 + lr;
    const __half* asrc = (garow < NN ? A + garow * 128 : A) + lc;
    const int bk = t >> 3, bn = (t & 7) * 16;

    uint32_t sbase = (uint32_t)__cvta_generic_to_shared(smem);
    uint32_t a_d[2], b_d[2];
#pragma unroll
    for (int s = 0; s < 2; s++) {
        uint32_t sb = sbase + s * G_STAGE;
        a_d[s] = sb + (lr * 40 + lc) * 2;
        b_d[s] = sb + 10240 + (bk * 136 + bn) * 2;
    }
    auto issue = [&](int k0, int s) {
        cpa(a_d[s], asrc + k0);  cpa(a_d[s] + 16, asrc + k0 + 8);
        const __half* bp = B + (k0 + bk) * 128 + bn;
        cpa(b_d[s], bp);         cpa(b_d[s] + 16, bp + 8);
        cp_commit();
    };

    float4 acc[2][8];
#pragma unroll
    for (int i = 0; i < 2; i++)
#pragma unroll
        for (int j = 0; j < 8; j++) acc[i][j] = make_float4(0.f, 0.f, 0.f, 0.f);

    const int a_row = lane & 15, a_col = ((lane >> 4) & 1) * 8;
    const int b_k = (lane & 7) + ((lane & 8) ? 8 : 0);
    const int b_n8 = (lane & 16) ? 8 : 0;

    issue(0, 0);
    for (int it = 0; it < 4; it++) {
        if (it < 3) { issue((it + 1) * 32, (it + 1) & 1); cp_wait1(); }
        else cp_wait0();
        __syncthreads();
        char* st = smem + (it & 1) * G_STAGE;
        __half (*Ah)[40]  = (__half(*)[40])(st);
        __half (*Bh)[136] = (__half(*)[136])(st + 10240);
#pragma unroll
        for (int ks = 0; ks < 32; ks += 16) {
            uint32_t af[2][4];
#pragma unroll
            for (int i = 0; i < 2; i++)
                ldm_x4(af[i], &Ah[wm * 32 + i * 16 + a_row][ks + a_col]);
            uint32_t bf[8][2];
#pragma unroll
            for (int jj = 0; jj < 4; jj++) {
                uint32_t rh[4];
                ldm_x4_t(rh, &Bh[ks + b_k][wn * 64 + jj * 16 + b_n8]);
                bf[2 * jj][0] = rh[0]; bf[2 * jj][1] = rh[1];
                bf[2 * jj + 1][0] = rh[2]; bf[2 * jj + 1][1] = rh[3];
            }
#pragma unroll
            for (int i = 0; i < 2; i++)
#pragma unroll
                for (int j = 0; j < 8; j++)
                    mma_f16(acc[i][j], af[i], bf[j]);
        }
        __syncthreads();
    }

    // store xw fp16
#pragma unroll
    for (int i = 0; i < 2; i++)
#pragma unroll
        for (int half = 0; half < 2; half++) {
            int gr = row0 + wm * 32 + i * 16 + half * 8 + g;
            if (gr < NN) {
                __half* dst = &g_xw[(gr * 8 + r) * 128 + wn * 64 + 2 * tg];
#pragma unroll
                for (int j = 0; j < 8; j++) {
                    float2 v = half ? make_float2(acc[i][j].z, acc[i][j].w)
                                    : make_float2(acc[i][j].x, acc[i][j].y);
                    *(__half2*)(dst + j * 8) = __floats2half2_rn(v.x, v.y);
                }
            }
        }
}

// ---------------- aq/ak GEMM (bf16x3; unchanged) ----------------
__global__ void __launch_bounds__(256)
k_aqk(int layer) {
    __shared__ __nv_bfloat16 Ah[128][40], Al[128][40], Bh[64][40], Bl[64][40];
    const int t = threadIdx.x, lane = t & 31, wid = t >> 5;
    const int wm = wid & 3, wn = wid >> 2, g = lane >> 2, tg = lane & 3;
    const int row0 = blockIdx.x * 128;
    const __nv_bfloat16* Ahi = layer ? g_h1hi : g_xhi;
    const __nv_bfloat16* Alo = layer ? g_h1lo : g_xlo;
    const __nv_bfloat16* Bhi = g_qkhi[layer];
    const __nv_bfloat16* Blo = g_qklo[layer];

    const int lr = t >> 1, lc = (t & 1) * 16;
    const int garow = row0 + lr;
    const __nv_bfloat16* ahp = (garow < NN ? Ahi + garow * 128 : Ahi) + lc;
    const __nv_bfloat16* alp = (garow < NN ? Alo + garow * 128 : Alo) + lc;
    const int br = t >> 2, bc = (t & 3) * 8;

    float4 acc[2][4];
#pragma unroll
    for (int i = 0; i < 2; i++)
#pragma unroll
        for (int j = 0; j < 4; j++) acc[i][j] = make_float4(0.f, 0.f, 0.f, 0.f);

    const int a_row = lane & 15, a_col = ((lane >> 4) & 1) * 8;
    const int b_row = (lane & 7) + ((lane & 16) ? 8 : 0);
    const int b_col = (lane & 8) ? 8 : 0;

    for (int k0 = 0; k0 < 128; k0 += 32) {
        uint4 a0 = *(const uint4*)(ahp + k0);
        uint4 a1 = *(const uint4*)(ahp + k0 + 8);
        uint4 a2 = *(const uint4*)(alp + k0);
        uint4 a3 = *(const uint4*)(alp + k0 + 8);
        uint4 b0 = *(const uint4*)&Bhi[br * 128 + k0 + bc];
        uint4 b1 = *(const uint4*)&Blo[br * 128 + k0 + bc];
        __syncthreads();
        *(uint4*)&Ah[lr][lc] = a0; *(uint4*)&Ah[lr][lc + 8] = a1;
        *(uint4*)&Al[lr][lc] = a2; *(uint4*)&Al[lr][lc + 8] = a3;
        *(uint4*)&Bh[br][bc] = b0;
        *(uint4*)&Bl[br][bc] = b1;
        __syncthreads();
#pragma unroll
        for (int ks = 0; ks < 32; ks += 16) {
            uint32_t ahh[2][4], all[2][4];
#pragma unroll
            for (int i = 0; i < 2; i++) {
                ldm_x4(ahh[i], &Ah[wm * 32 + i * 16 + a_row][ks + a_col]);
                ldm_x4(all[i], &Al[wm * 32 + i * 16 + a_row][ks + a_col]);
            }
            uint32_t bhh[4][2], bll[4][2];
#pragma unroll
            for (int jj = 0; jj < 2; jj++) {
                uint32_t rh[4], rl[4];
                ldm_x4(rh, &Bh[wn * 32 + jj * 16 + b_row][ks + b_col]);
                ldm_x4(rl, &Bl[wn * 32 + jj * 16 + b_row][ks + b_col]);
                bhh[2 * jj][0] = rh[0]; bhh[2 * jj][1] = rh[1];
                bhh[2 * jj + 1][0] = rh[2]; bhh[2 * jj + 1][1] = rh[3];
                bll[2 * jj][0] = rl[0]; bll[2 * jj][1] = rl[1];
                bll[2 * jj + 1][0] = rl[2]; bll[2 * jj + 1][1] = rl[3];
            }
#pragma unroll
            for (int i = 0; i < 2; i++)
#pragma unroll
                for (int j = 0; j < 4; j++) {
                    mma_bf16(acc[i][j], ahh[i], bll[j]);
                    mma_bf16(acc[i][j], all[i], bhh[j]);
                    mma_bf16(acc[i][j], ahh[i], bhh[j]);
                }
        }
    }

#pragma unroll
    for (int i = 0; i < 2; i++)
#pragma unroll
        for (int half = 0; half < 2; half++) {
            int gr = row0 + wm * 32 + i * 16 + half * 8 + g;
            if (gr >= NN) continue;
#pragma unroll
            for (int j = 0; j < 4; j++) {
                int col = wn * 32 + j * 8 + 2 * tg;
                float2 v = half ? make_float2(acc[i][j].z, acc[i][j].w)
                                : make_float2(acc[i][j].x, acc[i][j].y);
                if (col < 32) *(float2*)&g_aq[gr * 32 + col] = v;
                else          *(float2*)&g_ak[gr * 32 + col - 32] = v;
            }
        }
}

// ---------------- fused per-node softmax + aggregate + bias + relu + LN ----------------
__global__ void k_agg_ln(const float* __restrict__ bias, const float* __restrict__ gam,
                         const float* __restrict__ bet, int layer) {
    int nid = blockIdx.x * 8 + (threadIdx.x >> 5);
    if (nid >= NN) return;
    int lane = threadIdx.x & 31;
    int h = lane >> 3;
    int e8 = lane & 7;
    int j0 = g_rowptr[nid], j1 = g_rowptr[nid + 1];
    float4 num = make_float4(0.f, 0.f, 0.f, 0.f);
    float den = 0.f;
    for (int base = j0; base < j1; base += 8) {
        int idx = base + e8;
        int p = 0;
        float ex = 0.f;
        if (idx < j1) {
            p = g_csr[idx];
            int rr = p & 7;
            float a = g_aq[nid * 32 + rr * 4 + h] + g_ak[p * 4 + h];
            a = a > 0.f ? a : 0.2f * a;
            ex = __expf(a);
        }
        den += ex;
        int cnt = min(8, j1 - base);
        for (int e = 0; e < cnt; e++) {
            float exe = __shfl_sync(0xffffffffu, ex, (lane & 24) + e);
            int pe = __shfl_sync(0xffffffffu, p, e);
            uint2 raw = *(const uint2*)&g_xw[pe * 128 + lane * 4];
            float2 f0 = __half22float2(*(__half2*)&raw.x);
            float2 f1 = __half22float2(*(__half2*)&raw.y);
            num.x += exe * f0.x; num.y += exe * f0.y;
            num.z += exe * f1.x; num.w += exe * f1.y;
        }
    }
    den += __shfl_xor_sync(0xffffffffu, den, 1);
    den += __shfl_xor_sync(0xffffffffu, den, 2);
    den += __shfl_xor_sync(0xffffffffu, den, 4);
    float inv = 1.f / (den + 1e-16f);
    float4 bb = *(const float4*)&bias[lane * 4];
    float4 v;
    v.x = fmaxf(num.x * inv + bb.x, 0.f);
    v.y = fmaxf(num.y * inv + bb.y, 0.f);
    v.z = fmaxf(num.z * inv + bb.z, 0.f);
    v.w = fmaxf(num.w * inv + bb.w, 0.f);
    float s = v.x + v.y + v.z + v.w;
#pragma unroll
    for (int o = 16; o >= 1; o >>= 1) s += __shfl_xor_sync(0xffffffffu, s, o);
    float mean = s * (1.f / 128.f);
    float dx = v.x - mean, dy = v.y - mean, dz = v.z - mean, dw = v.w - mean;
    float ss = dx * dx + dy * dy + dz * dz + dw * dw;
#pragma unroll
    for (int o = 16; o >= 1; o >>= 1) ss += __shfl_xor_sync(0xffffffffu, ss, o);
    float rs = rsqrtf(ss * (1.f / 128.f) + 1e-5f);
    float4 g4 = *(const float4*)&gam[lane * 4];
    float4 b4 = *(const float4*)&bet[lane * 4];
    float4 y;
    y.x = dx * rs * g4.x + b4.x;
    y.y = dy * rs * g4.y + b4.y;
    y.z = dz * rs * g4.z + b4.z;
    y.w = dw * rs * g4.w + b4.w;
    union { __nv_bfloat16 b[4]; uint2 u; } ph, pl;
    if (layer == 1) {
        bsplit(y.x, ph.b[0], pl.b[0]); bsplit(y.y, ph.b[1], pl.b[1]);
        bsplit(y.z, ph.b[2], pl.b[2]); bsplit(y.w, ph.b[3], pl.b[3]);
        *(uint2*)&g_h1hi[nid * HID + lane * 4] = ph.u;
        *(uint2*)&g_h1lo[nid * HID + lane * 4] = pl.u;
        __half2 h0 = __floats2half2_rn(y.x, y.y);
        __half2 h1 = __floats2half2_rn(y.z, y.w);
        uint2 u16;
        u16.x = *(uint32_t*)&h0; u16.y = *(uint32_t*)&h1;
        *(uint2*)&g_h116[nid * HID + lane * 4] = u16;
    } else {
        uint2 rh = *(const uint2*)&g_h1hi[nid * HID + lane * 4];
        uint2 rl = *(const uint2*)&g_h1lo[nid * HID + lane * 4];
        const __nv_bfloat16* hb = (const __nv_bfloat16*)&rh;
        const __nv_bfloat16* lb = (const __nv_bfloat16*)&rl;
        y.x += __bfloat162float(hb[0]) + __bfloat162float(lb[0]);
        y.y += __bfloat162float(hb[1]) + __bfloat162float(lb[1]);
        y.z += __bfloat162float(hb[2]) + __bfloat162float(lb[2]);
        y.w += __bfloat162float(hb[3]) + __bfloat162float(lb[3]);
        bsplit(y.x, ph.b[0], pl.b[0]); bsplit(y.y, ph.b[1], pl.b[1]);
        bsplit(y.z, ph.b[2], pl.b[2]); bsplit(y.w, ph.b[3], pl.b[3]);
        *(uint2*)&g_hshi[nid * HID + lane * 4] = ph.u;
        *(uint2*)&g_hslo[nid * HID + lane * 4] = pl.u;
    }
}

// ---------------- decode (bf16x3 fused; unchanged) ----------------
__global__ void __launch_bounds__(256, 2)
k_decode1(const int* __restrict__ edges, const float* __restrict__ mb1,
          const float* __restrict__ mw2, const float* __restrict__ mb2,
          float* __restrict__ out) {
    extern __shared__ char smem[];
    __shared__ int sidx[128][2];
    __shared__ float sb[128];
    __shared__ float sw2[128][NCLS];
    __shared__ float s_out[128][NCLS];

    const int t = threadIdx.x, lane = t & 31, wid = t >> 5;
    const int wm = wid & 3, wn = wid >> 2, g = lane >> 2, tg = lane & 3;
    const int row0 = blockIdx.x * 128;

    if (t < 128) {
        int p = row0 + t;
        int2 pr = (p < EE2) ? ((const int2*)edges)[p] : make_int2(0, 0);
        sidx[t][0] = pr.x;
        sidx[t][1] = pr.y;
        sb[t] = mb1[t];
        *(float4*)&sw2[t][0] = *(const float4*)&mw2[t * NCLS];
        *(float4*)&sw2[t][4] = *(const float4*)&mw2[t * NCLS + 4];
        *(float4*)&s_out[t][0] = make_float4(0.f, 0.f, 0.f, 0.f);
        *(float4*)&s_out[t][4] = make_float4(0.f, 0.f, 0.f, 0.f);
    }
    __syncthreads();

    const int lr = t >> 1, lc = (t & 1) * 16;
    const int node0 = sidx[lr][0];
    const int node1 = sidx[lr][1];
    const int bk = t >> 3, bn = (t & 7) * 16;

    uint32_t sbase = (uint32_t)__cvta_generic_to_shared(smem);
    uint32_t ah_d[2], al_d[2], bh_d[2], bl_d[2];
#pragma unroll
    for (int s = 0; s < 2; s++) {
        uint32_t sb2 = sbase + s * STAGE_BYTES;
        ah_d[s] = sb2 + (lr * 40 + lc) * 2;
        al_d[s] = sb2 + 10240 + (lr * 40 + lc) * 2;
        bh_d[s] = sb2 + 20480 + (bk * 136 + bn) * 2;
        bl_d[s] = sb2 + 29184 + (bk * 136 + bn) * 2;
    }
    auto issue = [&](int c, int s) {
        int node = (c < 4) ? node0 : node1;
        int colbase = (c & 3) * 32 + lc;
        const __nv_bfloat16* ah = &g_hshi[node * 128 + colbase];
        const __nv_bfloat16* al = &g_hslo[node * 128 + colbase];
        cpa(ah_d[s], ah);  cpa(ah_d[s] + 16, ah + 8);
        cpa(al_d[s], al);  cpa(al_d[s] + 16, al + 8);
        const __nv_bfloat16* bh = &g_m1hi[(c * 32 + bk) * 128 + bn];
        const __nv_bfloat16* bl = &g_m1lo[(c * 32 + bk) * 128 + bn];
        cpa(bh_d[s], bh);  cpa(bh_d[s] + 16, bh + 8);
        cpa(bl_d[s], bl);  cpa(bl_d[s] + 16, bl + 8);
        cp_commit();
    };

    float4 acc[2][8];
#pragma unroll
    for (int i = 0; i < 2; i++)
#pragma unroll
        for (int j = 0; j < 8; j++) acc[i][j] = make_float4(0.f, 0.f, 0.f, 0.f);

    const int a_row = lane & 15, a_col = ((lane >> 4) & 1) * 8;
    const int b_k = (lane & 7) + ((lane & 8) ? 8 : 0);
    const int b_n8 = (lane & 16) ? 8 : 0;

    issue(0, 0);
    for (int it = 0; it < 8; it++) {
        if (it < 7) { issue(it + 1, (it + 1) & 1); cp_wait1(); }
        else cp_wait0();
        __syncthreads();
        char* st = smem + (it & 1) * STAGE_BYTES;
        __nv_bfloat16 (*Ah)[40]  = (__nv_bfloat16(*)[40])(st);
        __nv_bfloat16 (*Al)[40]  = (__nv_bfloat16(*)[40])(st + 10240);
        __nv_bfloat16 (*Bh)[136] = (__nv_bfloat16(*)[136])(st + 20480);
        __nv_bfloat16 (*Bl)[136] = (__nv_bfloat16(*)[136])(st + 29184);
#pragma unroll
        for (int ks = 0; ks < 32; ks += 16) {
            uint32_t ahh[2][4], all[2][4];
#pragma unroll
            for (int i = 0; i < 2; i++) {
                ldm_x4(ahh[i], &Ah[wm * 32 + i * 16 + a_row][ks + a_col]);
                ldm_x4(all[i], &Al[wm * 32 + i * 16 + a_row][ks + a_col]);
            }
            uint32_t bhh[8][2], bll[8][2];
#pragma unroll
            for (int jj = 0; jj < 4; jj++) {
                uint32_t rh[4], rl[4];
                ldm_x4_t(rh, &Bh[ks + b_k][wn * 64 + jj * 16 + b_n8]);
                ldm_x4_t(rl, &Bl[ks + b_k][wn * 64 + jj * 16 + b_n8]);
                bhh[2 * jj][0] = rh[0]; bhh[2 * jj][1] = rh[1];
                bhh[2 * jj + 1][0] = rh[2]; bhh[2 * jj + 1][1] = rh[3];
                bll[2 * jj][0] = rl[0]; bll[2 * jj][1] = rl[1];
                bll[2 * jj + 1][0] = rl[2]; bll[2 * jj + 1][1] = rl[3];
            }
#pragma unroll
            for (int i = 0; i < 2; i++)
#pragma unroll
                for (int j = 0; j < 8; j++) {
                    mma_bf16(acc[i][j], ahh[i], bll[j]);
                    mma_bf16(acc[i][j], all[i], bhh[j]);
                    mma_bf16(acc[i][j], ahh[i], bhh[j]);
                }
        }
        __syncthreads();
    }

#pragma unroll
    for (int i = 0; i < 2; i++)
#pragma unroll
        for (int half = 0; half < 2; half++) {
            int row = wm * 32 + i * 16 + half * 8 + g;
            float pout[NCLS];
#pragma unroll
            for (int c = 0; c < NCLS; c++) pout[c] = 0.f;
#pragma unroll
            for (int j = 0; j < 8; j++) {
                int col = wn * 64 + j * 8 + 2 * tg;
                float vA = (half ? acc[i][j].z : acc[i][j].x) + sb[col];
                float vB = (half ? acc[i][j].w : acc[i][j].y) + sb[col + 1];
                vA = 0.5f * vA * (1.f + erff(vA * 0.70710678118654752f));
                vB = 0.5f * vB * (1.f + erff(vB * 0.70710678118654752f));
#pragma unroll
                for (int c = 0; c < NCLS; c++)
                    pout[c] += vA * sw2[col][c] + vB * sw2[col + 1][c];
            }
#pragma unroll
            for (int c = 0; c < NCLS; c++) {
                pout[c] += __shfl_xor_sync(0xffffffffu, pout[c], 1);
                pout[c] += __shfl_xor_sync(0xffffffffu, pout[c], 2);
            }
            if (tg == 0) {
#pragma unroll
                for (int c = 0; c < NCLS; c++) atomicAdd(&s_out[row][c], pout[c]);
            }
        }
    __syncthreads();
    if (t < 128) {
        int p = row0 + t;
        if (p < EE2) {
            float4 o0, o1;
            o0.x = s_out[t][0] + mb2[0]; o0.y = s_out[t][1] + mb2[1];
            o0.z = s_out[t][2] + mb2[2]; o0.w = s_out[t][3] + mb2[3];
            o1.x = s_out[t][4] + mb2[4]; o1.y = s_out[t][5] + mb2[5];
            o1.z = s_out[t][6] + mb2[6]; o1.w = s_out[t][7] + mb2[7];
            *(float4*)&out[p * NCLS] = o0;
            *(float4*)&out[p * NCLS + 4] = o1;
        }
    }
}

// ---------------- launch (multi-stream fork/join, graph-capturable) ----------------
extern "C" void kernel_launch(void* const* d_in, const int* in_sizes, int n_in,
                              void* d_out, int out_size) {
    const float* x     = (const float*)d_in[0];
    const int*   ei    = (const int*)d_in[1];
    const int*   et    = (const int*)d_in[2];
    const int*   edges = (const int*)d_in[3];
    const float* w1 = (const float*)d_in[4];
    const float* q1 = (const float*)d_in[5];
    const float* k1 = (const float*)d_in[6];
    const float* b1 = (const float*)d_in[7];
    const float* w2 = (const float*)d_in[8];
    const float* q2 = (const float*)d_in[9];
    const float* k2 = (const float*)d_in[10];
    const float* b2 = (const float*)d_in[11];
    const float* ln1g = (const float*)d_in[12];
    const float* ln1b = (const float*)d_in[13];
    const float* ln2g = (const float*)d_in[14];
    const float* ln2b = (const float*)d_in[15];
    const float* mw1 = (const float*)d_in[16];
    const float* mb1 = (const float*)d_in[17];
    const float* mw2 = (const float*)d_in[18];
    const float* mb2 = (const float*)d_in[19];
    float* out = (float*)d_out;

    static cudaStream_t s1 = nullptr, s2 = nullptr;
    static cudaEvent_t evStart, evPrep, evW0, evFill, evA0, evH1, evA1;
    if (!s1) {
        cudaStreamCreateWithFlags(&s1, cudaStreamNonBlocking);
        cudaStreamCreateWithFlags(&s2, cudaStreamNonBlocking);
        cudaEventCreateWithFlags(&evStart, cudaEventDisableTiming);
        cudaEventCreateWithFlags(&evPrep,  cudaEventDisableTiming);
        cudaEventCreateWithFlags(&evW0,    cudaEventDisableTiming);
        cudaEventCreateWithFlags(&evFill,  cudaEventDisableTiming);
        cudaEventCreateWithFlags(&evA0,    cudaEventDisableTiming);
        cudaEventCreateWithFlags(&evH1,    cudaEventDisableTiming);
        cudaEventCreateWithFlags(&evA1,    cudaEventDisableTiming);
        cudaFuncSetAttribute(k_gemm16,  cudaFuncAttributeMaxDynamicSharedMemorySize, 2 * G_STAGE);
        cudaFuncSetAttribute(k_decode1, cudaFuncAttributeMaxDynamicSharedMemorySize, 2 * STAGE_BYTES);
    }

    const int prepTot = NN * HID / 4 + 2 * (RR * HID * HID / 4) + 2 * HID * HID / 4;
    const dim3 gXW((NN + 127) / 128, RR);

    cudaEventRecord(evStart, 0);
    cudaStreamWaitEvent(s1, evStart, 0);

    // side stream 1: wqk planes + CSR build
    k_wqk<<<(64 * HID + 255) / 256, 256, 0, s1>>>(w1, q1, k1, 0);
    cudaEventRecord(evW0, s1);
    k_wqk<<<(64 * HID + 255) / 256, 256, 0, s1>>>(w2, q2, k2, 1);
    k_zero<<<(NN + 255) / 256, 256, 0, s1>>>();
    k_hist<<<(EE + 255) / 256, 256, 0, s1>>>(ei);
    k_scan<<<1, 1024, 0, s1>>>();
    k_fill<<<(EE + 255) / 256, 256, 0, s1>>>(ei, et);
    cudaEventRecord(evFill, s1);

    // main: prep -> gemm(0)
    k_prep<<<(prepTot + 255) / 256, 256>>>(x, w1, w2, mw1);
    cudaEventRecord(evPrep, 0);

    cudaStreamWaitEvent(s2, evStart, 0);
    cudaStreamWaitEvent(s2, evPrep, 0);
    cudaStreamWaitEvent(s2, evW0, 0);
    k_aqk<<<(NN + 127) / 128, 256, 0, s2>>>(0);
    cudaEventRecord(evA0, s2);

    k_gemm16<<<gXW, 256, 2 * G_STAGE>>>(0);
    cudaStreamWaitEvent(0, evA0, 0);
    cudaStreamWaitEvent(0, evFill, 0);
    k_agg_ln<<<(NN + 7) / 8, 256>>>(b1, ln1g, ln1b, 1);
    cudaEventRecord(evH1, 0);

    cudaStreamWaitEvent(s2, evH1, 0);
    k_aqk<<<(NN + 127) / 128, 256, 0, s2>>>(1);
    cudaEventRecord(evA1, s2);

    k_gemm16<<<gXW, 256, 2 * G_STAGE>>>(1);
    cudaStreamWaitEvent(0, evA1, 0);
    k_agg_ln<<<(NN + 7) / 8, 256>>>(b2, ln2g, ln2b, 2);

    k_decode1<<<(EE2 + 127) / 128, 256, 2 * STAGE_BYTES>>>(edges, mb1, mw2, mb2, out);
}

// round 13
// speedup vs baseline: 5.5680x; 1.1034x over previous
#include <cuda_runtime.h>
#include <cuda_bf16.h>
#include <cuda_fp16.h>
#include <math.h>
#include <stdint.h>

#define NN   50000
#define HID  128
#define RR   8
#define EE   640000
#define EE2  200000
#define NCLS 8

// ---------------- scratch (device globals; allocation-free) ----------------
__device__ __half g_xw[NN * RR * HID];
__device__ float g_aq[NN * RR * 4];
__device__ float g_ak[NN * RR * 4];
__device__ __half g_x16[NN * HID], g_h116[NN * HID];             // fp16 single-plane A for xw GEMM
__device__ __nv_bfloat16 g_xhi[NN * HID],  g_xlo[NN * HID];      // bf16 splits for aqk
__device__ __nv_bfloat16 g_h1hi[NN * HID], g_h1lo[NN * HID];
__device__ __nv_bfloat16 g_hshi[NN * HID], g_hslo[NN * HID];
__device__ __half g_w16[2 * RR * HID * HID];                     // [layer][r][k][n] fp16
__device__ __nv_bfloat16 g_m1hi[2 * HID * HID], g_m1lo[2 * HID * HID]; // [k=256][n=128]
__device__ __nv_bfloat16 g_qkhi[2][64 * HID], g_qklo[2][64 * HID];     // [n=64][k=128]
__device__ int g_deg[NN], g_rowptr[NN + 1], g_cursor[NN], g_csr[EE];

// ---------------- helpers ----------------
__device__ __forceinline__ void bsplit(float v, __nv_bfloat16& hi, __nv_bfloat16& lo) {
    hi = __float2bfloat16(v);
    lo = __float2bfloat16(v - __bfloat162float(hi));
}
__device__ __forceinline__ void mma_bf16(float4& d, const uint32_t* a, const uint32_t* b) {
    asm volatile(
        "mma.sync.aligned.m16n8k16.row.col.f32.bf16.bf16.f32 "
        "{%0,%1,%2,%3}, {%4,%5,%6,%7}, {%8,%9}, {%0,%1,%2,%3};"
        : "+f"(d.x), "+f"(d.y), "+f"(d.z), "+f"(d.w)
        : "r"(a[0]), "r"(a[1]), "r"(a[2]), "r"(a[3]), "r"(b[0]), "r"(b[1]));
}
__device__ __forceinline__ void mma_f16(float4& d, const uint32_t* a, const uint32_t* b) {
    asm volatile(
        "mma.sync.aligned.m16n8k16.row.col.f32.f16.f16.f32 "
        "{%0,%1,%2,%3}, {%4,%5,%6,%7}, {%8,%9}, {%0,%1,%2,%3};"
        : "+f"(d.x), "+f"(d.y), "+f"(d.z), "+f"(d.w)
        : "r"(a[0]), "r"(a[1]), "r"(a[2]), "r"(a[3]), "r"(b[0]), "r"(b[1]));
}
__device__ __forceinline__ void ldm_x4(uint32_t* r, const void* p) {
    uint32_t a = (uint32_t)__cvta_generic_to_shared(p);
    asm volatile("ldmatrix.sync.aligned.m8n8.x4.shared.b16 {%0,%1,%2,%3}, [%4];"
                 : "=r"(r[0]), "=r"(r[1]), "=r"(r[2]), "=r"(r[3]) : "r"(a));
}
__device__ __forceinline__ void ldm_x4_t(uint32_t* r, const void* p) {
    uint32_t a = (uint32_t)__cvta_generic_to_shared(p);
    asm volatile("ldmatrix.sync.aligned.m8n8.x4.trans.shared.b16 {%0,%1,%2,%3}, [%4];"
                 : "=r"(r[0]), "=r"(r[1]), "=r"(r[2]), "=r"(r[3]) : "r"(a));
}
__device__ __forceinline__ void cpa(uint32_t d, const void* s) {
    asm volatile("cp.async.cg.shared.global [%0], [%1], 16;" :: "r"(d), "l"(s));
}
__device__ __forceinline__ void cp_commit() { asm volatile("cp.async.commit_group;"); }
__device__ __forceinline__ void cp_wait0() { asm volatile("cp.async.wait_group 0;"); }
__device__ __forceinline__ void cp_wait1() { asm volatile("cp.async.wait_group 1;"); }

#define STAGE_BYTES 37888   // decode stage: Ah 0, Al 10240, Bh 20480, Bl 29184
#define G_STAGE 18944       // fp16 gemm stage: A 0 (10240), B 10240 (8704)

// ---------------- CSR build ----------------
__global__ void k_zero() {
    int i = blockIdx.x * blockDim.x + threadIdx.x;
    if (i < NN) g_deg[i] = 0;
}
__global__ void k_hist(const int* __restrict__ ei) {
    int e = blockIdx.x * blockDim.x + threadIdx.x;
    if (e < EE) atomicAdd(&g_deg[ei[EE + e]], 1);
}
__global__ void k_scan() {
    __shared__ int sp[1024];
    const int t = threadIdx.x;
    const int chunk = (NN + 1023) / 1024;
    int start = t * chunk, end = min(start + chunk, NN);
    int s = 0;
    for (int i = start; i < end; i++) s += g_deg[i];
    sp[t] = s;
    __syncthreads();
    for (int off = 1; off < 1024; off <<= 1) {
        int v = (t >= off) ? sp[t - off] : 0;
        __syncthreads();
        sp[t] += v;
        __syncthreads();
    }
    int run = (t == 0) ? 0 : sp[t - 1];
    for (int i = start; i < end; i++) {
        g_rowptr[i] = run;
        g_cursor[i] = run;
        run += g_deg[i];
    }
    if (t == 1023) g_rowptr[NN] = run;
}
__global__ void k_fill(const int* __restrict__ ei, const int* __restrict__ et) {
    int e = blockIdx.x * blockDim.x + threadIdx.x;
    if (e >= EE) return;
    int dst = ei[EE + e];
    int pos = atomicAdd(&g_cursor[dst], 1);
    g_csr[pos] = ei[e] * 8 + et[e];
}

// ---------------- fused prep: x -> {fp16, bf16 hi/lo}; W -> fp16; mw1 -> bf16 hi/lo ----------------
__global__ void k_prep(const float* __restrict__ x, const float* __restrict__ w1,
                       const float* __restrict__ w2, const float* __restrict__ mw1) {
    const int R0 = NN * HID / 4;
    const int R1 = RR * HID * HID / 4;
    const int R3 = 2 * HID * HID / 4;
    int id = blockIdx.x * blockDim.x + threadIdx.x;
    if (id < R0) {
        float4 v = ((const float4*)x)[id];
        union { __nv_bfloat16 b[4]; uint2 u; } ph, pl;
        bsplit(v.x, ph.b[0], pl.b[0]); bsplit(v.y, ph.b[1], pl.b[1]);
        bsplit(v.z, ph.b[2], pl.b[2]); bsplit(v.w, ph.b[3], pl.b[3]);
        *(uint2*)&g_xhi[id * 4] = ph.u;
        *(uint2*)&g_xlo[id * 4] = pl.u;
        __half2 h0 = __floats2half2_rn(v.x, v.y);
        __half2 h1 = __floats2half2_rn(v.z, v.w);
        uint2 u16;
        u16.x = *(uint32_t*)&h0; u16.y = *(uint32_t*)&h1;
        *(uint2*)&g_x16[id * 4] = u16;
    } else if (id < R0 + 2 * R1) {
        int layer = (id - R0) >= R1;
        int off = id - R0 - layer * R1;
        const float* src = layer ? w2 : w1;
        float4 v = ((const float4*)src)[off];
        __half2 h0 = __floats2half2_rn(v.x, v.y);
        __half2 h1 = __floats2half2_rn(v.z, v.w);
        uint2 u16;
        u16.x = *(uint32_t*)&h0; u16.y = *(uint32_t*)&h1;
        *(uint2*)&g_w16[layer * RR * HID * HID + off * 4] = u16;
    } else if (id < R0 + 2 * R1 + R3) {
        int off = id - R0 - 2 * R1;
        float4 v = ((const float4*)mw1)[off];
        union { __nv_bfloat16 b[4]; uint2 u; } ph, pl;
        bsplit(v.x, ph.b[0], pl.b[0]); bsplit(v.y, ph.b[1], pl.b[1]);
        bsplit(v.z, ph.b[2], pl.b[2]); bsplit(v.w, ph.b[3], pl.b[3]);
        *(uint2*)&g_m1hi[off * 4] = ph.u;
        *(uint2*)&g_m1lo[off * 4] = pl.u;
    }
}

// ---------------- Wqk planes ----------------
__global__ void k_wqk(const float* __restrict__ W, const float* __restrict__ q,
                      const float* __restrict__ kk, int layer) {
    int id = blockIdx.x * blockDim.x + threadIdx.x;
    if (id >= 64 * HID) return;
    int i = id & 127, n = id >> 7;
    int h = n & 3, r = (n >> 2) & 7;
    const float* vq = (n < 32) ? q : kk;
    const float* wrow = W + r * HID * HID + i * HID;
    float s = 0.f;
#pragma unroll 4
    for (int o = 0; o < HID; o++) s += wrow[o] * vq[o * 4 + h];
    bsplit(s, g_qkhi[layer][n * HID + i], g_qklo[layer][n * HID + i]);
}

// ---------------- fp16 single-plane GEMM (cp.async pipelined): xw = A @ W[layer][r] ----------------
__global__ void __launch_bounds__(256, 2)
k_gemm16(int layer) {
    extern __shared__ char smem[];
    const int t = threadIdx.x, lane = t & 31, wid = t >> 5;
    const int wm = wid & 3, wn = wid >> 2, g = lane >> 2, tg = lane & 3;
    const int r = blockIdx.y, row0 = blockIdx.x * 128;
    const __half* A = layer ? g_h116 : g_x16;
    const __half* B = g_w16 + (layer * RR + r) * HID * HID;   // [k][n]

    const int lr = t >> 1, lc = (t & 1) * 16;
    const int garow = row0 + lr;
    const __half* asrc = (garow < NN ? A + garow * 128 : A) + lc;
    const int bk = t >> 3, bn = (t & 7) * 16;

    uint32_t sbase = (uint32_t)__cvta_generic_to_shared(smem);
    uint32_t a_d[2], b_d[2];
#pragma unroll
    for (int s = 0; s < 2; s++) {
        uint32_t sb = sbase + s * G_STAGE;
        a_d[s] = sb + (lr * 40 + lc) * 2;
        b_d[s] = sb + 10240 + (bk * 136 + bn) * 2;
    }
    auto issue = [&](int k0, int s) {
        cpa(a_d[s], asrc + k0);  cpa(a_d[s] + 16, asrc + k0 + 8);
        const __half* bp = B + (k0 + bk) * 128 + bn;
        cpa(b_d[s], bp);         cpa(b_d[s] + 16, bp + 8);
        cp_commit();
    };

    float4 acc[2][8];
#pragma unroll
    for (int i = 0; i < 2; i++)
#pragma unroll
        for (int j = 0; j < 8; j++) acc[i][j] = make_float4(0.f, 0.f, 0.f, 0.f);

    const int a_row = lane & 15, a_col = ((lane >> 4) & 1) * 8;
    const int b_k = (lane & 7) + ((lane & 8) ? 8 : 0);
    const int b_n8 = (lane & 16) ? 8 : 0;

    issue(0, 0);
    for (int it = 0; it < 4; it++) {
        if (it < 3) { issue((it + 1) * 32, (it + 1) & 1); cp_wait1(); }
        else cp_wait0();
        __syncthreads();
        char* st = smem + (it & 1) * G_STAGE;
        __half (*Ah)[40]  = (__half(*)[40])(st);
        __half (*Bh)[136] = (__half(*)[136])(st + 10240);
#pragma unroll
        for (int ks = 0; ks < 32; ks += 16) {
            uint32_t af[2][4];
#pragma unroll
            for (int i = 0; i < 2; i++)
                ldm_x4(af[i], &Ah[wm * 32 + i * 16 + a_row][ks + a_col]);
            uint32_t bf[8][2];
#pragma unroll
            for (int jj = 0; jj < 4; jj++) {
                uint32_t rh[4];
                ldm_x4_t(rh, &Bh[ks + b_k][wn * 64 + jj * 16 + b_n8]);
                bf[2 * jj][0] = rh[0]; bf[2 * jj][1] = rh[1];
                bf[2 * jj + 1][0] = rh[2]; bf[2 * jj + 1][1] = rh[3];
            }
#pragma unroll
            for (int i = 0; i < 2; i++)
#pragma unroll
                for (int j = 0; j < 8; j++)
                    mma_f16(acc[i][j], af[i], bf[j]);
        }
        __syncthreads();
    }

    // store xw fp16
#pragma unroll
    for (int i = 0; i < 2; i++)
#pragma unroll
        for (int half = 0; half < 2; half++) {
            int gr = row0 + wm * 32 + i * 16 + half * 8 + g;
            if (gr < NN) {
                __half* dst = &g_xw[(gr * 8 + r) * 128 + wn * 64 + 2 * tg];
#pragma unroll
                for (int j = 0; j < 8; j++) {
                    float2 v = half ? make_float2(acc[i][j].z, acc[i][j].w)
                                    : make_float2(acc[i][j].x, acc[i][j].y);
                    *(__half2*)(dst + j * 8) = __floats2half2_rn(v.x, v.y);
                }
            }
        }
}

// ---------------- aq/ak GEMM (bf16x3; unchanged) ----------------
__global__ void __launch_bounds__(256)
k_aqk(int layer) {
    __shared__ __nv_bfloat16 Ah[128][40], Al[128][40], Bh[64][40], Bl[64][40];
    const int t = threadIdx.x, lane = t & 31, wid = t >> 5;
    const int wm = wid & 3, wn = wid >> 2, g = lane >> 2, tg = lane & 3;
    const int row0 = blockIdx.x * 128;
    const __nv_bfloat16* Ahi = layer ? g_h1hi : g_xhi;
    const __nv_bfloat16* Alo = layer ? g_h1lo : g_xlo;
    const __nv_bfloat16* Bhi = g_qkhi[layer];
    const __nv_bfloat16* Blo = g_qklo[layer];

    const int lr = t >> 1, lc = (t & 1) * 16;
    const int garow = row0 + lr;
    const __nv_bfloat16* ahp = (garow < NN ? Ahi + garow * 128 : Ahi) + lc;
    const __nv_bfloat16* alp = (garow < NN ? Alo + garow * 128 : Alo) + lc;
    const int br = t >> 2, bc = (t & 3) * 8;

    float4 acc[2][4];
#pragma unroll
    for (int i = 0; i < 2; i++)
#pragma unroll
        for (int j = 0; j < 4; j++) acc[i][j] = make_float4(0.f, 0.f, 0.f, 0.f);

    const int a_row = lane & 15, a_col = ((lane >> 4) & 1) * 8;
    const int b_row = (lane & 7) + ((lane & 16) ? 8 : 0);
    const int b_col = (lane & 8) ? 8 : 0;

    for (int k0 = 0; k0 < 128; k0 += 32) {
        uint4 a0 = *(const uint4*)(ahp + k0);
        uint4 a1 = *(const uint4*)(ahp + k0 + 8);
        uint4 a2 = *(const uint4*)(alp + k0);
        uint4 a3 = *(const uint4*)(alp + k0 + 8);
        uint4 b0 = *(const uint4*)&Bhi[br * 128 + k0 + bc];
        uint4 b1 = *(const uint4*)&Blo[br * 128 + k0 + bc];
        __syncthreads();
        *(uint4*)&Ah[lr][lc] = a0; *(uint4*)&Ah[lr][lc + 8] = a1;
        *(uint4*)&Al[lr][lc] = a2; *(uint4*)&Al[lr][lc + 8] = a3;
        *(uint4*)&Bh[br][bc] = b0;
        *(uint4*)&Bl[br][bc] = b1;
        __syncthreads();
#pragma unroll
        for (int ks = 0; ks < 32; ks += 16) {
            uint32_t ahh[2][4], all[2][4];
#pragma unroll
            for (int i = 0; i < 2; i++) {
                ldm_x4(ahh[i], &Ah[wm * 32 + i * 16 + a_row][ks + a_col]);
                ldm_x4(all[i], &Al[wm * 32 + i * 16 + a_row][ks + a_col]);
            }
            uint32_t bhh[4][2], bll[4][2];
#pragma unroll
            for (int jj = 0; jj < 2; jj++) {
                uint32_t rh[4], rl[4];
                ldm_x4(rh, &Bh[wn * 32 + jj * 16 + b_row][ks + b_col]);
                ldm_x4(rl, &Bl[wn * 32 + jj * 16 + b_row][ks + b_col]);
                bhh[2 * jj][0] = rh[0]; bhh[2 * jj][1] = rh[1];
                bhh[2 * jj + 1][0] = rh[2]; bhh[2 * jj + 1][1] = rh[3];
                bll[2 * jj][0] = rl[0]; bll[2 * jj][1] = rl[1];
                bll[2 * jj + 1][0] = rl[2]; bll[2 * jj + 1][1] = rl[3];
            }
#pragma unroll
            for (int i = 0; i < 2; i++)
#pragma unroll
                for (int j = 0; j < 4; j++) {
                    mma_bf16(acc[i][j], ahh[i], bll[j]);
                    mma_bf16(acc[i][j], all[i], bhh[j]);
                    mma_bf16(acc[i][j], ahh[i], bhh[j]);
                }
        }
    }

#pragma unroll
    for (int i = 0; i < 2; i++)
#pragma unroll
        for (int half = 0; half < 2; half++) {
            int gr = row0 + wm * 32 + i * 16 + half * 8 + g;
            if (gr >= NN) continue;
#pragma unroll
            for (int j = 0; j < 4; j++) {
                int col = wn * 32 + j * 8 + 2 * tg;
                float2 v = half ? make_float2(acc[i][j].z, acc[i][j].w)
                                : make_float2(acc[i][j].x, acc[i][j].y);
                if (col < 32) *(float2*)&g_aq[gr * 32 + col] = v;
                else          *(float2*)&g_ak[gr * 32 + col - 32] = v;
            }
        }
}

// ---------------- fused per-node softmax + aggregate + bias + relu + LN ----------------
// MLP-batched; ALL shfl_sync ops kept in convergent code (the round-12 crash was a
// full-mask shfl inside the divergent remainder guard).
__global__ void k_agg_ln(const float* __restrict__ bias, const float* __restrict__ gam,
                         const float* __restrict__ bet, int layer) {
    int nid = blockIdx.x * 8 + (threadIdx.x >> 5);
    if (nid >= NN) return;
    int lane = threadIdx.x & 31;
    int h = lane >> 3;
    int e8 = lane & 7;
    int j0 = g_rowptr[nid], j1 = g_rowptr[nid + 1];
    float aqr = g_aq[nid * 32 + lane];      // lane = rr*4 + h layout
    float4 num = make_float4(0.f, 0.f, 0.f, 0.f);
    float den = 0.f;

    int base = j0;
    // full 8-edge chunks: batch loads for MLP=8 (warp-convergent: j0/j1 uniform per warp)
    for (; base + 8 <= j1; base += 8) {
        int p = g_csr[base + e8];
        int rr = p & 7;
        float aqv = __shfl_sync(0xffffffffu, aqr, rr * 4 + h);
        float a = aqv + g_ak[p * 4 + h];
        a = a > 0.f ? a : 0.2f * a;
        float ex = __expf(a);
        den += ex;
        uint2 rbuf[8];
#pragma unroll
        for (int e = 0; e < 8; e++) {
            int pe = __shfl_sync(0xffffffffu, p, e);
            rbuf[e] = *(const uint2*)&g_xw[pe * 128 + lane * 4];
        }
#pragma unroll
        for (int e = 0; e < 8; e++) {
            float exe = __shfl_sync(0xffffffffu, ex, (lane & 24) + e);
            float2 f0 = __half22float2(*(__half2*)&rbuf[e].x);
            float2 f1 = __half22float2(*(__half2*)&rbuf[e].y);
            num.x += exe * f0.x; num.y += exe * f0.y;
            num.z += exe * f1.x; num.w += exe * f1.y;
        }
    }
    // remainder (< 8 edges) — shfls hoisted OUT of divergent guards
    if (base < j1) {                        // warp-uniform condition
        int idx = base + e8;
        bool ok = idx < j1;                 // per-lane
        int p = ok ? g_csr[idx] : 0;        // safe default keeps indices in-bounds
        int rr = p & 7;
        float aqv = __shfl_sync(0xffffffffu, aqr, rr * 4 + h);   // convergent
        float ex = 0.f;
        if (ok) {
            float a = aqv + g_ak[p * 4 + h];
            a = a > 0.f ? a : 0.2f * a;
            ex = __expf(a);
        }
        den += ex;
        int cnt = j1 - base;                // warp-uniform
        for (int e = 0; e < cnt; e++) {
            float exe = __shfl_sync(0xffffffffu, ex, (lane & 24) + e);
            int pe = __shfl_sync(0xffffffffu, p, e);
            uint2 raw = *(const uint2*)&g_xw[pe * 128 + lane * 4];
            float2 f0 = __half22float2(*(__half2*)&raw.x);
            float2 f1 = __half22float2(*(__half2*)&raw.y);
            num.x += exe * f0.x; num.y += exe * f0.y;
            num.z += exe * f1.x; num.w += exe * f1.y;
        }
    }

    den += __shfl_xor_sync(0xffffffffu, den, 1);
    den += __shfl_xor_sync(0xffffffffu, den, 2);
    den += __shfl_xor_sync(0xffffffffu, den, 4);
    float inv = 1.f / (den + 1e-16f);
    float4 bb = *(const float4*)&bias[lane * 4];
    float4 v;
    v.x = fmaxf(num.x * inv + bb.x, 0.f);
    v.y = fmaxf(num.y * inv + bb.y, 0.f);
    v.z = fmaxf(num.z * inv + bb.z, 0.f);
    v.w = fmaxf(num.w * inv + bb.w, 0.f);
    float s = v.x + v.y + v.z + v.w;
#pragma unroll
    for (int o = 16; o >= 1; o >>= 1) s += __shfl_xor_sync(0xffffffffu, s, o);
    float mean = s * (1.f / 128.f);
    float dx = v.x - mean, dy = v.y - mean, dz = v.z - mean, dw = v.w - mean;
    float ss = dx * dx + dy * dy + dz * dz + dw * dw;
#pragma unroll
    for (int o = 16; o >= 1; o >>= 1) ss += __shfl_xor_sync(0xffffffffu, ss, o);
    float rs = rsqrtf(ss * (1.f / 128.f) + 1e-5f);
    float4 g4 = *(const float4*)&gam[lane * 4];
    float4 b4 = *(const float4*)&bet[lane * 4];
    float4 y;
    y.x = dx * rs * g4.x + b4.x;
    y.y = dy * rs * g4.y + b4.y;
    y.z = dz * rs * g4.z + b4.z;
    y.w = dw * rs * g4.w + b4.w;
    union { __nv_bfloat16 b[4]; uint2 u; } ph, pl;
    if (layer == 1) {
        bsplit(y.x, ph.b[0], pl.b[0]); bsplit(y.y, ph.b[1], pl.b[1]);
        bsplit(y.z, ph.b[2], pl.b[2]); bsplit(y.w, ph.b[3], pl.b[3]);
        *(uint2*)&g_h1hi[nid * HID + lane * 4] = ph.u;
        *(uint2*)&g_h1lo[nid * HID + lane * 4] = pl.u;
        __half2 h0 = __floats2half2_rn(y.x, y.y);
        __half2 h1 = __floats2half2_rn(y.z, y.w);
        uint2 u16;
        u16.x = *(uint32_t*)&h0; u16.y = *(uint32_t*)&h1;
        *(uint2*)&g_h116[nid * HID + lane * 4] = u16;
    } else {
        uint2 rh = *(const uint2*)&g_h1hi[nid * HID + lane * 4];
        uint2 rl = *(const uint2*)&g_h1lo[nid * HID + lane * 4];
        const __nv_bfloat16* hb = (const __nv_bfloat16*)&rh;
        const __nv_bfloat16* lb = (const __nv_bfloat16*)&rl;
        y.x += __bfloat162float(hb[0]) + __bfloat162float(lb[0]);
        y.y += __bfloat162float(hb[1]) + __bfloat162float(lb[1]);
        y.z += __bfloat162float(hb[2]) + __bfloat162float(lb[2]);
        y.w += __bfloat162float(hb[3]) + __bfloat162float(lb[3]);
        bsplit(y.x, ph.b[0], pl.b[0]); bsplit(y.y, ph.b[1], pl.b[1]);
        bsplit(y.z, ph.b[2], pl.b[2]); bsplit(y.w, ph.b[3], pl.b[3]);
        *(uint2*)&g_hshi[nid * HID + lane * 4] = ph.u;
        *(uint2*)&g_hslo[nid * HID + lane * 4] = pl.u;
    }
}

// ---------------- decode (bf16x3 fused; unchanged) ----------------
__global__ void __launch_bounds__(256, 2)
k_decode1(const int* __restrict__ edges, const float* __restrict__ mb1,
          const float* __restrict__ mw2, const float* __restrict__ mb2,
          float* __restrict__ out) {
    extern __shared__ char smem[];
    __shared__ int sidx[128][2];
    __shared__ float sb[128];
    __shared__ float sw2[128][NCLS];
    __shared__ float s_out[128][NCLS];

    const int t = threadIdx.x, lane = t & 31, wid = t >> 5;
    const int wm = wid & 3, wn = wid >> 2, g = lane >> 2, tg = lane & 3;
    const int row0 = blockIdx.x * 128;

    if (t < 128) {
        int p = row0 + t;
        int2 pr = (p < EE2) ? ((const int2*)edges)[p] : make_int2(0, 0);
        sidx[t][0] = pr.x;
        sidx[t][1] = pr.y;
        sb[t] = mb1[t];
        *(float4*)&sw2[t][0] = *(const float4*)&mw2[t * NCLS];
        *(float4*)&sw2[t][4] = *(const float4*)&mw2[t * NCLS + 4];
        *(float4*)&s_out[t][0] = make_float4(0.f, 0.f, 0.f, 0.f);
        *(float4*)&s_out[t][4] = make_float4(0.f, 0.f, 0.f, 0.f);
    }
    __syncthreads();

    const int lr = t >> 1, lc = (t & 1) * 16;
    const int node0 = sidx[lr][0];
    const int node1 = sidx[lr][1];
    const int bk = t >> 3, bn = (t & 7) * 16;

    uint32_t sbase = (uint32_t)__cvta_generic_to_shared(smem);
    uint32_t ah_d[2], al_d[2], bh_d[2], bl_d[2];
#pragma unroll
    for (int s = 0; s < 2; s++) {
        uint32_t sb2 = sbase + s * STAGE_BYTES;
        ah_d[s] = sb2 + (lr * 40 + lc) * 2;
        al_d[s] = sb2 + 10240 + (lr * 40 + lc) * 2;
        bh_d[s] = sb2 + 20480 + (bk * 136 + bn) * 2;
        bl_d[s] = sb2 + 29184 + (bk * 136 + bn) * 2;
    }
    auto issue = [&](int c, int s) {
        int node = (c < 4) ? node0 : node1;
        int colbase = (c & 3) * 32 + lc;
        const __nv_bfloat16* ah = &g_hshi[node * 128 + colbase];
        const __nv_bfloat16* al = &g_hslo[node * 128 + colbase];
        cpa(ah_d[s], ah);  cpa(ah_d[s] + 16, ah + 8);
        cpa(al_d[s], al);  cpa(al_d[s] + 16, al + 8);
        const __nv_bfloat16* bh = &g_m1hi[(c * 32 + bk) * 128 + bn];
        const __nv_bfloat16* bl = &g_m1lo[(c * 32 + bk) * 128 + bn];
        cpa(bh_d[s], bh);  cpa(bh_d[s] + 16, bh + 8);
        cpa(bl_d[s], bl);  cpa(bl_d[s] + 16, bl + 8);
        cp_commit();
    };

    float4 acc[2][8];
#pragma unroll
    for (int i = 0; i < 2; i++)
#pragma unroll
        for (int j = 0; j < 8; j++) acc[i][j] = make_float4(0.f, 0.f, 0.f, 0.f);

    const int a_row = lane & 15, a_col = ((lane >> 4) & 1) * 8;
    const int b_k = (lane & 7) + ((lane & 8) ? 8 : 0);
    const int b_n8 = (lane & 16) ? 8 : 0;

    issue(0, 0);
    for (int it = 0; it < 8; it++) {
        if (it < 7) { issue(it + 1, (it + 1) & 1); cp_wait1(); }
        else cp_wait0();
        __syncthreads();
        char* st = smem + (it & 1) * STAGE_BYTES;
        __nv_bfloat16 (*Ah)[40]  = (__nv_bfloat16(*)[40])(st);
        __nv_bfloat16 (*Al)[40]  = (__nv_bfloat16(*)[40])(st + 10240);
        __nv_bfloat16 (*Bh)[136] = (__nv_bfloat16(*)[136])(st + 20480);
        __nv_bfloat16 (*Bl)[136] = (__nv_bfloat16(*)[136])(st + 29184);
#pragma unroll
        for (int ks = 0; ks < 32; ks += 16) {
            uint32_t ahh[2][4], all[2][4];
#pragma unroll
            for (int i = 0; i < 2; i++) {
                ldm_x4(ahh[i], &Ah[wm * 32 + i * 16 + a_row][ks + a_col]);
                ldm_x4(all[i], &Al[wm * 32 + i * 16 + a_row][ks + a_col]);
            }
            uint32_t bhh[8][2], bll[8][2];
#pragma unroll
            for (int jj = 0; jj < 4; jj++) {
                uint32_t rh[4], rl[4];
                ldm_x4_t(rh, &Bh[ks + b_k][wn * 64 + jj * 16 + b_n8]);
                ldm_x4_t(rl, &Bl[ks + b_k][wn * 64 + jj * 16 + b_n8]);
                bhh[2 * jj][0] = rh[0]; bhh[2 * jj][1] = rh[1];
                bhh[2 * jj + 1][0] = rh[2]; bhh[2 * jj + 1][1] = rh[3];
                bll[2 * jj][0] = rl[0]; bll[2 * jj][1] = rl[1];
                bll[2 * jj + 1][0] = rl[2]; bll[2 * jj + 1][1] = rl[3];
            }
#pragma unroll
            for (int i = 0; i < 2; i++)
#pragma unroll
                for (int j = 0; j < 8; j++) {
                    mma_bf16(acc[i][j], ahh[i], bll[j]);
                    mma_bf16(acc[i][j], all[i], bhh[j]);
                    mma_bf16(acc[i][j], ahh[i], bhh[j]);
                }
        }
        __syncthreads();
    }

#pragma unroll
    for (int i = 0; i < 2; i++)
#pragma unroll
        for (int half = 0; half < 2; half++) {
            int row = wm * 32 + i * 16 + half * 8 + g;
            float pout[NCLS];
#pragma unroll
            for (int c = 0; c < NCLS; c++) pout[c] = 0.f;
#pragma unroll
            for (int j = 0; j < 8; j++) {
                int col = wn * 64 + j * 8 + 2 * tg;
                float vA = (half ? acc[i][j].z : acc[i][j].x) + sb[col];
                float vB = (half ? acc[i][j].w : acc[i][j].y) + sb[col + 1];
                vA = 0.5f * vA * (1.f + erff(vA * 0.70710678118654752f));
                vB = 0.5f * vB * (1.f + erff(vB * 0.70710678118654752f));
#pragma unroll
                for (int c = 0; c < NCLS; c++)
                    pout[c] += vA * sw2[col][c] + vB * sw2[col + 1][c];
            }
#pragma unroll
            for (int c = 0; c < NCLS; c++) {
                pout[c] += __shfl_xor_sync(0xffffffffu, pout[c], 1);
                pout[c] += __shfl_xor_sync(0xffffffffu, pout[c], 2);
            }
            if (tg == 0) {
#pragma unroll
                for (int c = 0; c < NCLS; c++) atomicAdd(&s_out[row][c], pout[c]);
            }
        }
    __syncthreads();
    if (t < 128) {
        int p = row0 + t;
        if (p < EE2) {
            float4 o0, o1;
            o0.x = s_out[t][0] + mb2[0]; o0.y = s_out[t][1] + mb2[1];
            o0.z = s_out[t][2] + mb2[2]; o0.w = s_out[t][3] + mb2[3];
            o1.x = s_out[t][4] + mb2[4]; o1.y = s_out[t][5] + mb2[5];
            o1.z = s_out[t][6] + mb2[6]; o1.w = s_out[t][7] + mb2[7];
            *(float4*)&out[p * NCLS] = o0;
            *(float4*)&out[p * NCLS + 4] = o1;
        }
    }
}

// ---------------- launch (multi-stream fork/join, graph-capturable) ----------------
extern "C" void kernel_launch(void* const* d_in, const int* in_sizes, int n_in,
                              void* d_out, int out_size) {
    const float* x     = (const float*)d_in[0];
    const int*   ei    = (const int*)d_in[1];
    const int*   et    = (const int*)d_in[2];
    const int*   edges = (const int*)d_in[3];
    const float* w1 = (const float*)d_in[4];
    const float* q1 = (const float*)d_in[5];
    const float* k1 = (const float*)d_in[6];
    const float* b1 = (const float*)d_in[7];
    const float* w2 = (const float*)d_in[8];
    const float* q2 = (const float*)d_in[9];
    const float* k2 = (const float*)d_in[10];
    const float* b2 = (const float*)d_in[11];
    const float* ln1g = (const float*)d_in[12];
    const float* ln1b = (const float*)d_in[13];
    const float* ln2g = (const float*)d_in[14];
    const float* ln2b = (const float*)d_in[15];
    const float* mw1 = (const float*)d_in[16];
    const float* mb1 = (const float*)d_in[17];
    const float* mw2 = (const float*)d_in[18];
    const float* mb2 = (const float*)d_in[19];
    float* out = (float*)d_out;

    static cudaStream_t s1 = nullptr, s2 = nullptr;
    static cudaEvent_t evStart, evPrep, evW0, evFill, evA0, evH1, evA1;
    if (!s1) {
        cudaStreamCreateWithFlags(&s1, cudaStreamNonBlocking);
        cudaStreamCreateWithFlags(&s2, cudaStreamNonBlocking);
        cudaEventCreateWithFlags(&evStart, cudaEventDisableTiming);
        cudaEventCreateWithFlags(&evPrep,  cudaEventDisableTiming);
        cudaEventCreateWithFlags(&evW0,    cudaEventDisableTiming);
        cudaEventCreateWithFlags(&evFill,  cudaEventDisableTiming);
        cudaEventCreateWithFlags(&evA0,    cudaEventDisableTiming);
        cudaEventCreateWithFlags(&evH1,    cudaEventDisableTiming);
        cudaEventCreateWithFlags(&evA1,    cudaEventDisableTiming);
        cudaFuncSetAttribute(k_gemm16,  cudaFuncAttributeMaxDynamicSharedMemorySize, 2 * G_STAGE);
        cudaFuncSetAttribute(k_decode1, cudaFuncAttributeMaxDynamicSharedMemorySize, 2 * STAGE_BYTES);
    }

    const int prepTot = NN * HID / 4 + 2 * (RR * HID * HID / 4) + 2 * HID * HID / 4;
    const dim3 gXW((NN + 127) / 128, RR);

    cudaEventRecord(evStart, 0);
    cudaStreamWaitEvent(s1, evStart, 0);

    // side stream 1: wqk planes + CSR build
    k_wqk<<<(64 * HID + 255) / 256, 256, 0, s1>>>(w1, q1, k1, 0);
    cudaEventRecord(evW0, s1);
    k_wqk<<<(64 * HID + 255) / 256, 256, 0, s1>>>(w2, q2, k2, 1);
    k_zero<<<(NN + 255) / 256, 256, 0, s1>>>();
    k_hist<<<(EE + 255) / 256, 256, 0, s1>>>(ei);
    k_scan<<<1, 1024, 0, s1>>>();
    k_fill<<<(EE + 255) / 256, 256, 0, s1>>>(ei, et);
    cudaEventRecord(evFill, s1);

    // main: prep -> gemm(0)
    k_prep<<<(prepTot + 255) / 256, 256>>>(x, w1, w2, mw1);
    cudaEventRecord(evPrep, 0);

    cudaStreamWaitEvent(s2, evStart, 0);
    cudaStreamWaitEvent(s2, evPrep, 0);
    cudaStreamWaitEvent(s2, evW0, 0);
    k_aqk<<<(NN + 127) / 128, 256, 0, s2>>>(0);
    cudaEventRecord(evA0, s2);

    k_gemm16<<<gXW, 256, 2 * G_STAGE>>>(0);
    cudaStreamWaitEvent(0, evA0, 0);
    cudaStreamWaitEvent(0, evFill, 0);
    k_agg_ln<<<(NN + 7) / 8, 256>>>(b1, ln1g, ln1b, 1);
    cudaEventRecord(evH1, 0);

    cudaStreamWaitEvent(s2, evH1, 0);
    k_aqk<<<(NN + 127) / 128, 256, 0, s2>>>(1);
    cudaEventRecord(evA1, s2);

    k_gemm16<<<gXW, 256, 2 * G_STAGE>>>(1);
    cudaStreamWaitEvent(0, evA1, 0);
    k_agg_ln<<<(NN + 7) / 8, 256>>>(b2, ln2g, ln2b, 2);

    k_decode1<<<(EE2 + 127) / 128, 256, 2 * STAGE_BYTES>>>(edges, mb1, mw2, mb2, out);
}